// round 2
// baseline (speedup 1.0000x reference)
#include <cuda_runtime.h>

#define D_   768
#define NH_  12
#define P_   5
#define NL_  54
#define NS_  256
#define B_   128
#define NTL_ 49           // NL_ - P_
#define ML_  (B_*NL_)     // 6912
#define MS_  (B_*NS_)     // 32768

// ---------------- scratch (device globals; no allocation in kernel_launch) ----------------
__device__ float g_local[(size_t)ML_*D_];
__device__ float g_scene[(size_t)MS_*D_];
__device__ float g_q    [(size_t)MS_*D_];
__device__ float g_k    [(size_t)MS_*D_];
__device__ float g_v    [(size_t)MS_*D_];
__device__ float g_ao   [(size_t)MS_*D_];
__device__ float g_h    [(size_t)ML_*D_];
__device__ float g_qkv  [(size_t)ML_*3*D_];
__device__ float g_mlp  [(size_t)ML_*4*D_];
__device__ float g_lsin [B_*NTL_*32];
__device__ float g_lcos [B_*NTL_*32];
__device__ float g_ssin [NS_*32];
__device__ float g_scos [NS_*32];

__device__ __forceinline__ float gelu_f(float x){
    float t = tanhf(0.7978845608028654f*(x + 0.044715f*x*x*x));
    return 0.5f*x*(1.0f+t);
}

// ---------------- SGEMM: C(MxN) = A(MxK) @ B(KxN), all row-major, dims divisible by tile ----
// EPI: 0 = store, 1 = gelu(acc), 2 = C += acc, 3 = C += gate[col]*acc
template<int EPI>
__global__ __launch_bounds__(256) void sgemm(const float* __restrict__ A,
                                             const float* __restrict__ Bm,
                                             float* __restrict__ C,
                                             const float* __restrict__ gate,
                                             int M, int N, int K)
{
    __shared__ float As[16][64];
    __shared__ float Bs[16][64];
    const int tid = threadIdx.x;
    const int bx = blockIdx.x, by = blockIdx.y;
    const float* Ab = A  + (size_t)by*64*K;
    const float* Bb = Bm + (size_t)bx*64;
    const int ar = tid >> 2,  ac = (tid & 3)  << 2;   // A load: 64 rows x 16 cols
    const int br = tid >> 4,  bc = (tid & 15) << 2;   // B load: 16 rows x 64 cols
    const int ty = tid >> 4,  tx = tid & 15;

    float acc[4][4];
    #pragma unroll
    for (int i=0;i<4;i++)
        #pragma unroll
        for (int j=0;j<4;j++) acc[i][j]=0.f;

    for (int k0 = 0; k0 < K; k0 += 16) {
        float4 a4 = *reinterpret_cast<const float4*>(Ab + (size_t)ar*K + k0 + ac);
        As[ac+0][ar]=a4.x; As[ac+1][ar]=a4.y; As[ac+2][ar]=a4.z; As[ac+3][ar]=a4.w;
        float4 b4 = *reinterpret_cast<const float4*>(Bb + (size_t)(k0+br)*N + bc);
        *reinterpret_cast<float4*>(&Bs[br][bc]) = b4;
        __syncthreads();
        #pragma unroll
        for (int kk=0;kk<16;kk++){
            float a0[4], b0[4];
            #pragma unroll
            for (int i=0;i<4;i++) a0[i]=As[kk][(ty<<2)+i];
            #pragma unroll
            for (int j=0;j<4;j++) b0[j]=Bs[kk][(tx<<2)+j];
            #pragma unroll
            for (int i=0;i<4;i++)
                #pragma unroll
                for (int j=0;j<4;j++) acc[i][j] += a0[i]*b0[j];
        }
        __syncthreads();
    }

    const int row0 = by*64 + (ty<<2);
    const int col0 = bx*64 + (tx<<2);
    #pragma unroll
    for (int i=0;i<4;i++){
        float* cp = C + (size_t)(row0+i)*N + col0;
        #pragma unroll
        for (int j=0;j<4;j++){
            float vv = acc[i][j];
            if      (EPI==0) cp[j] = vv;
            else if (EPI==1) cp[j] = gelu_f(vv);
            else if (EPI==2) cp[j] += vv;
            else             cp[j] += gate[col0+j]*vv;
        }
    }
}

// ---------------- LayerNorm over D=768, one block per row ----------------
__global__ __launch_bounds__(256) void layernorm_k(const float* __restrict__ X,
                                                   float* __restrict__ Y,
                                                   const float* __restrict__ g,
                                                   const float* __restrict__ bb)
{
    __shared__ float red[256];
    const int row = blockIdx.x, tid = threadIdx.x;
    const float* x = X + (size_t)row*D_;
    float v0=x[tid], v1=x[tid+256], v2=x[tid+512];
    red[tid]=v0+v1+v2; __syncthreads();
    for (int o=128;o>0;o>>=1){ if(tid<o) red[tid]+=red[tid+o]; __syncthreads(); }
    float mean = red[0]*(1.f/768.f);
    __syncthreads();
    float d0=v0-mean, d1=v1-mean, d2=v2-mean;
    red[tid]=d0*d0+d1*d1+d2*d2; __syncthreads();
    for (int o=128;o>0;o>>=1){ if(tid<o) red[tid]+=red[tid+o]; __syncthreads(); }
    float inv = rsqrtf(red[0]*(1.f/768.f)+1e-6f);
    float* y = Y + (size_t)row*D_;
    y[tid]     = d0*inv*g[tid]     + bb[tid];
    y[tid+256] = d1*inv*g[tid+256] + bb[tid+256];
    y[tid+512] = d2*inv*g[tid+512] + bb[tid+512];
}

// ---------------- RoPE tables ----------------
__global__ void rope_local_pre(const float* __restrict__ centers, const float* __restrict__ scales){
    int t = blockIdx.x, b = blockIdx.y, j = threadIdx.x;   // grid (49, B), block 32
    int iy = t/7, ix = t%7;
    float gy = (iy+0.5f)*(2.f/7.f)-1.f;
    float gx = (ix+0.5f)*(2.f/7.f)-1.f;
    float sc = scales[b];
    float pos = (j<16) ? (centers[2*b]+sc*gy) : (centers[2*b+1]+sc*gx);
    float f = expf(-4.605170185988091f * (float)(j&15) * (1.f/16.f));  // 100^(-(j%16)/16)
    float a = pos*f;
    int idx = (b*NTL_+t)*32 + j;
    g_lsin[idx]=sinf(a); g_lcos[idx]=cosf(a);
}
__global__ void rope_scene_pre(){
    int t = blockIdx.x, j = threadIdx.x;                   // grid 256, block 32
    int iy = t/16, ix = t%16;
    float gy = (iy+0.5f)*(2.f/16.f)-1.f;
    float gx = (ix+0.5f)*(2.f/16.f)-1.f;
    float pos = (j<16)? gy : gx;
    float f = expf(-4.605170185988091f * (float)(j&15) * (1.f/16.f));
    float a = pos*f;
    g_ssin[t*32+j]=sinf(a); g_scos[t*32+j]=cosf(a);
}

// In-place rope on head-layout buffer. grid (N-prefix, B), block (32, NH)
__global__ void rope_apply(float* __restrict__ X, const float* __restrict__ S,
                           const float* __restrict__ C, int N, int prefix, int rs, int bi)
{
    int t = blockIdx.x, b = blockIdx.y;
    int j = threadIdx.x, h = threadIdx.y;
    int nt = gridDim.x;
    size_t so = bi ? ((size_t)t*32+j) : (((size_t)b*nt+t)*32+j);
    float s = S[so], c = C[so];
    float* xp = X + ((size_t)(b*N+prefix+t)*rs + h*64);
    float x1 = xp[j], x2 = xp[j+32];
    xp[j]    = x1*c - x2*s;
    xp[j+32] = x2*c + x1*s;
}

// ---------------- fused attention: block = (b, h, 64-query tile) ----------------
// smem: qt[64*65] | kv[64*65] | sc[64*Nk(max 256)]
__global__ __launch_bounds__(256) void attn_fused(const float* __restrict__ Q,
                                                  const float* __restrict__ K,
                                                  const float* __restrict__ V,
                                                  float* __restrict__ O,
                                                  int Nq, int Nk, int qs, int ks)
{
    extern __shared__ float sm[];
    float* qt = sm;
    float* kv = sm + 64*65;
    float* sc = sm + 2*64*65;
    const int q0 = blockIdx.x*64;
    const int h = blockIdx.y, b = blockIdx.z, tid = threadIdx.x;
    const int nq = min(64, Nq - q0);

    for (int u = tid; u < nq*16; u += 256) {
        int r = u >> 4, c4 = (u & 15) << 2;
        float4 v4 = *reinterpret_cast<const float4*>(Q + ((size_t)(b*Nq + q0 + r)*qs + h*64 + c4));
        qt[r*65+c4]=v4.x; qt[r*65+c4+1]=v4.y; qt[r*65+c4+2]=v4.z; qt[r*65+c4+3]=v4.w;
    }
    const int tq  = tid >> 2;      // query in tile
    const int tk0 = tid & 3;

    // QK^T * scale
    for (int c0 = 0; c0 < Nk; c0 += 64) {
        int nc = min(64, Nk - c0);
        __syncthreads();
        for (int u = tid; u < nc*16; u += 256) {
            int r = u >> 4, c4 = (u & 15) << 2;
            float4 v4 = *reinterpret_cast<const float4*>(K + ((size_t)(b*Nk + c0 + r)*ks + h*64 + c4));
            kv[r*65+c4]=v4.x; kv[r*65+c4+1]=v4.y; kv[r*65+c4+2]=v4.z; kv[r*65+c4+3]=v4.w;
        }
        __syncthreads();
        if (tq < nq) {
            #pragma unroll 4
            for (int m = 0; m < 16; m++) {
                int k = tk0 + (m<<2);
                if (k < nc) {
                    float d = 0.f;
                    #pragma unroll
                    for (int i = 0; i < 64; i++) d += qt[tq*65+i]*kv[k*65+i];
                    sc[tq*Nk + c0 + k] = d * 0.125f;
                }
            }
        }
    }
    __syncthreads();

    // softmax per row
    if (tid < nq) {
        float m = -1e30f;
        for (int k=0;k<Nk;k++) m = fmaxf(m, sc[tid*Nk+k]);
        float ssum = 0.f;
        for (int k=0;k<Nk;k++){ float e=expf(sc[tid*Nk+k]-m); sc[tid*Nk+k]=e; ssum+=e; }
        float inv = 1.f/ssum;
        for (int k=0;k<Nk;k++) sc[tid*Nk+k]*=inv;
    }
    __syncthreads();

    // P @ V
    const int dg = (tid & 3) << 4;
    float acc[16];
    #pragma unroll
    for (int j=0;j<16;j++) acc[j]=0.f;
    for (int c0 = 0; c0 < Nk; c0 += 64) {
        int nc = min(64, Nk - c0);
        __syncthreads();
        for (int u = tid; u < nc*16; u += 256) {
            int r = u >> 4, c4 = (u & 15) << 2;
            float4 v4 = *reinterpret_cast<const float4*>(V + ((size_t)(b*Nk + c0 + r)*ks + h*64 + c4));
            kv[r*65+c4]=v4.x; kv[r*65+c4+1]=v4.y; kv[r*65+c4+2]=v4.z; kv[r*65+c4+3]=v4.w;
        }
        __syncthreads();
        if (tq < nq) {
            for (int k=0;k<nc;k++){
                float p = sc[tq*Nk + c0 + k];
                #pragma unroll
                for (int j=0;j<16;j++) acc[j] += p*kv[k*65 + dg + j];
            }
        }
    }
    if (tq < nq) {
        float* op = O + ((size_t)(b*Nq + q0 + tq)*D_ + h*64 + dg);
        #pragma unroll
        for (int j=0;j<16;j++) op[j]=acc[j];
    }
}

// ---------------- init: broadcast scene tokens ----------------
__global__ void bcast_scene(const float* __restrict__ st){
    int off = blockIdx.x*256 + threadIdx.x;                // grid (NS_*D_/256, B_)
    g_scene[(size_t)blockIdx.y*(NS_*D_) + off] = st[off];
}

// ---------------- host ----------------
extern "C" void kernel_launch(void* const* d_in, const int* in_sizes, int n_in,
                              void* d_out, int out_size)
{
    (void)in_sizes; (void)n_in; (void)out_size;
    const float* in_local   = (const float*)d_in[0];
    const float* in_centers = (const float*)d_in[1];
    const float* in_scales  = (const float*)d_in[2];
    const float* in_scene   = (const float*)d_in[3];
    const float* rgate = (const float*)d_in[4];
    const float* wgate = (const float*)d_in[5];
    const float* rWq = (const float*)d_in[6];
    const float* rWk = (const float*)d_in[7];
    const float* rWv = (const float*)d_in[8];
    const float* rWo = (const float*)d_in[9];
    const float* wWq = (const float*)d_in[10];
    const float* wWk = (const float*)d_in[11];
    const float* wWv = (const float*)d_in[12];
    const float* wWo = (const float*)d_in[13];
    const float* ln1g = (const float*)d_in[14];
    const float* ln1b = (const float*)d_in[15];
    const float* qkvW = (const float*)d_in[16];
    const float* aWo  = (const float*)d_in[17];
    const float* ln2g = (const float*)d_in[18];
    const float* ln2b = (const float*)d_in[19];
    const float* mW1  = (const float*)d_in[20];
    const float* mW2  = (const float*)d_in[21];

    float *local,*scene,*q,*k,*v,*ao,*hb,*qkv,*mlp,*lsin,*lcos,*ssin,*scos;
    cudaGetSymbolAddress((void**)&local, g_local);
    cudaGetSymbolAddress((void**)&scene, g_scene);
    cudaGetSymbolAddress((void**)&q,   g_q);
    cudaGetSymbolAddress((void**)&k,   g_k);
    cudaGetSymbolAddress((void**)&v,   g_v);
    cudaGetSymbolAddress((void**)&ao,  g_ao);
    cudaGetSymbolAddress((void**)&hb,  g_h);
    cudaGetSymbolAddress((void**)&qkv, g_qkv);
    cudaGetSymbolAddress((void**)&mlp, g_mlp);
    cudaGetSymbolAddress((void**)&lsin, g_lsin);
    cudaGetSymbolAddress((void**)&lcos, g_lcos);
    cudaGetSymbolAddress((void**)&ssin, g_ssin);
    cudaGetSymbolAddress((void**)&scos, g_scos);

    const size_t smem_attn = (size_t)(2*64*65 + 64*256)*sizeof(float);   // ~98.8 KB
    cudaFuncSetAttribute(attn_fused, cudaFuncAttributeMaxDynamicSharedMemorySize, (int)smem_attn);

    cudaMemcpyAsync(local, in_local, sizeof(float)*(size_t)ML_*D_, cudaMemcpyDeviceToDevice);
    bcast_scene<<<dim3(NS_*D_/256, B_),256>>>(in_scene);
    rope_local_pre<<<dim3(NTL_,B_),32>>>(in_centers, in_scales);
    rope_scene_pre<<<NS_,32>>>();

    for (int i=0;i<12;i++){
        size_t wo = (size_t)i*D_*D_;
        // ---- READ cross-attn: q from local, kv from scene ----
        sgemm<0><<<dim3(12,108),256>>>(local, rWq+wo, q, nullptr, ML_, D_, D_);
        rope_apply<<<dim3(NTL_,B_),dim3(32,NH_)>>>(q, lsin, lcos, NL_, P_, D_, 0);
        sgemm<0><<<dim3(12,512),256>>>(scene, rWk+wo, k, nullptr, MS_, D_, D_);
        rope_apply<<<dim3(NS_,B_),dim3(32,NH_)>>>(k, ssin, scos, NS_, 0, D_, 1);
        sgemm<0><<<dim3(12,512),256>>>(scene, rWv+wo, v, nullptr, MS_, D_, D_);
        attn_fused<<<dim3(1,NH_,B_),256,smem_attn>>>(q,k,v,ao, NL_, NS_, D_, D_);
        sgemm<3><<<dim3(12,108),256>>>(ao, rWo+wo, local, rgate+(size_t)i*D_, ML_, D_, D_);

        // ---- ViT block on local ----
        layernorm_k<<<ML_,256>>>(local, hb, ln1g+(size_t)i*D_, ln1b+(size_t)i*D_);
        sgemm<0><<<dim3(36,108),256>>>(hb, qkvW+(size_t)i*D_*3*D_, qkv, nullptr, ML_, 3*D_, D_);
        rope_apply<<<dim3(NTL_,B_),dim3(32,NH_)>>>(qkv,     lsin, lcos, NL_, P_, 3*D_, 0);
        rope_apply<<<dim3(NTL_,B_),dim3(32,NH_)>>>(qkv+D_,  lsin, lcos, NL_, P_, 3*D_, 0);
        attn_fused<<<dim3(1,NH_,B_),256,smem_attn>>>(qkv, qkv+D_, qkv+2*D_, ao, NL_, NL_, 3*D_, 3*D_);
        sgemm<2><<<dim3(12,108),256>>>(ao, aWo+wo, local, nullptr, ML_, D_, D_);
        layernorm_k<<<ML_,256>>>(local, hb, ln2g+(size_t)i*D_, ln2b+(size_t)i*D_);
        sgemm<1><<<dim3(48,108),256>>>(hb, mW1+(size_t)i*D_*4*D_, mlp, nullptr, ML_, 4*D_, D_);
        sgemm<2><<<dim3(12,108),256>>>(mlp, mW2+(size_t)i*4*D_*D_, local, nullptr, ML_, D_, 4*D_);

        // ---- WRITE cross-attn: q from scene, kv from local ----
        sgemm<0><<<dim3(12,512),256>>>(scene, wWq+wo, q, nullptr, MS_, D_, D_);
        rope_apply<<<dim3(NS_,B_),dim3(32,NH_)>>>(q, ssin, scos, NS_, 0, D_, 1);
        sgemm<0><<<dim3(12,108),256>>>(local, wWk+wo, k, nullptr, ML_, D_, D_);
        rope_apply<<<dim3(NTL_,B_),dim3(32,NH_)>>>(k, lsin, lcos, NL_, P_, D_, 0);
        sgemm<0><<<dim3(12,108),256>>>(local, wWv+wo, v, nullptr, ML_, D_, D_);
        attn_fused<<<dim3(4,NH_,B_),256,smem_attn>>>(q,k,v,ao, NS_, NL_, D_, D_);
        sgemm<3><<<dim3(12,512),256>>>(ao, wWo+wo, scene, wgate+(size_t)i*D_, MS_, D_, D_);
    }

    cudaMemcpyAsync(d_out, local, sizeof(float)*(size_t)ML_*D_, cudaMemcpyDeviceToDevice);
    cudaMemcpyAsync((float*)d_out + (size_t)ML_*D_, scene, sizeof(float)*(size_t)MS_*D_,
                    cudaMemcpyDeviceToDevice);
}

// round 3
// speedup vs baseline: 1.0006x; 1.0006x over previous
#include <cuda_runtime.h>

#define D_   768
#define NH_  12
#define P_   5
#define NL_  54
#define NS_  256
#define B_   128
#define NTL_ 49           // NL_ - P_
#define ML_  (B_*NL_)     // 6912
#define MS_  (B_*NS_)     // 32768

// ---------------- scratch (device globals; no allocation in kernel_launch) ----------------
__device__ float g_local[(size_t)ML_*D_];
__device__ float g_scene[(size_t)MS_*D_];
__device__ float g_q    [(size_t)MS_*D_];
__device__ float g_k    [(size_t)MS_*D_];
__device__ float g_v    [(size_t)MS_*D_];
__device__ float g_ao   [(size_t)MS_*D_];
__device__ float g_h    [(size_t)ML_*D_];
__device__ float g_qkv  [(size_t)ML_*3*D_];
__device__ float g_mlp  [(size_t)ML_*4*D_];
__device__ float g_lsin [B_*NTL_*32];
__device__ float g_lcos [B_*NTL_*32];
__device__ float g_ssin [NS_*32];
__device__ float g_scos [NS_*32];

__device__ __forceinline__ float gelu_f(float x){
    float t = tanhf(0.7978845608028654f*(x + 0.044715f*x*x*x));
    return 0.5f*x*(1.0f+t);
}

// ---------------- SGEMM: C(MxN) = A(MxK) @ B(KxN), all row-major, dims divisible by tile ----
// EPI: 0 = store, 1 = gelu(acc), 2 = C += acc, 3 = C += gate[col]*acc
template<int EPI>
__global__ __launch_bounds__(256) void sgemm(const float* __restrict__ A,
                                             const float* __restrict__ Bm,
                                             float* __restrict__ C,
                                             const float* __restrict__ gate,
                                             int M, int N, int K)
{
    __shared__ float As[16][64];
    __shared__ float Bs[16][64];
    const int tid = threadIdx.x;
    const int bx = blockIdx.x, by = blockIdx.y;
    const float* Ab = A  + (size_t)by*64*K;
    const float* Bb = Bm + (size_t)bx*64;
    const int ar = tid >> 2,  ac = (tid & 3)  << 2;   // A load: 64 rows x 16 cols
    const int br = tid >> 4,  bc = (tid & 15) << 2;   // B load: 16 rows x 64 cols
    const int ty = tid >> 4,  tx = tid & 15;

    float acc[4][4];
    #pragma unroll
    for (int i=0;i<4;i++)
        #pragma unroll
        for (int j=0;j<4;j++) acc[i][j]=0.f;

    for (int k0 = 0; k0 < K; k0 += 16) {
        float4 a4 = *reinterpret_cast<const float4*>(Ab + (size_t)ar*K + k0 + ac);
        As[ac+0][ar]=a4.x; As[ac+1][ar]=a4.y; As[ac+2][ar]=a4.z; As[ac+3][ar]=a4.w;
        float4 b4 = *reinterpret_cast<const float4*>(Bb + (size_t)(k0+br)*N + bc);
        *reinterpret_cast<float4*>(&Bs[br][bc]) = b4;
        __syncthreads();
        #pragma unroll
        for (int kk=0;kk<16;kk++){
            float a0[4], b0[4];
            #pragma unroll
            for (int i=0;i<4;i++) a0[i]=As[kk][(ty<<2)+i];
            #pragma unroll
            for (int j=0;j<4;j++) b0[j]=Bs[kk][(tx<<2)+j];
            #pragma unroll
            for (int i=0;i<4;i++)
                #pragma unroll
                for (int j=0;j<4;j++) acc[i][j] += a0[i]*b0[j];
        }
        __syncthreads();
    }

    const int row0 = by*64 + (ty<<2);
    const int col0 = bx*64 + (tx<<2);
    #pragma unroll
    for (int i=0;i<4;i++){
        float* cp = C + (size_t)(row0+i)*N + col0;
        #pragma unroll
        for (int j=0;j<4;j++){
            float vv = acc[i][j];
            if      (EPI==0) cp[j] = vv;
            else if (EPI==1) cp[j] = gelu_f(vv);
            else if (EPI==2) cp[j] += vv;
            else             cp[j] += gate[col0+j]*vv;
        }
    }
}

// ---------------- LayerNorm over D=768, one block per row ----------------
__global__ __launch_bounds__(256) void layernorm_k(const float* __restrict__ X,
                                                   float* __restrict__ Y,
                                                   const float* __restrict__ g,
                                                   const float* __restrict__ bb)
{
    __shared__ float red[256];
    const int row = blockIdx.x, tid = threadIdx.x;
    const float* x = X + (size_t)row*D_;
    float v0=x[tid], v1=x[tid+256], v2=x[tid+512];
    red[tid]=v0+v1+v2; __syncthreads();
    for (int o=128;o>0;o>>=1){ if(tid<o) red[tid]+=red[tid+o]; __syncthreads(); }
    float mean = red[0]*(1.f/768.f);
    __syncthreads();
    float d0=v0-mean, d1=v1-mean, d2=v2-mean;
    red[tid]=d0*d0+d1*d1+d2*d2; __syncthreads();
    for (int o=128;o>0;o>>=1){ if(tid<o) red[tid]+=red[tid+o]; __syncthreads(); }
    float inv = rsqrtf(red[0]*(1.f/768.f)+1e-6f);
    float* y = Y + (size_t)row*D_;
    y[tid]     = d0*inv*g[tid]     + bb[tid];
    y[tid+256] = d1*inv*g[tid+256] + bb[tid+256];
    y[tid+512] = d2*inv*g[tid+512] + bb[tid+512];
}

// ---------------- RoPE tables ----------------
__global__ void rope_local_pre(const float* __restrict__ centers, const float* __restrict__ scales){
    int t = blockIdx.x, b = blockIdx.y, j = threadIdx.x;   // grid (49, B), block 32
    int iy = t/7, ix = t%7;
    float gy = (iy+0.5f)*(2.f/7.f)-1.f;
    float gx = (ix+0.5f)*(2.f/7.f)-1.f;
    float sc = scales[b];
    float pos = (j<16) ? (centers[2*b]+sc*gy) : (centers[2*b+1]+sc*gx);
    float f = expf(-4.605170185988091f * (float)(j&15) * (1.f/16.f));  // 100^(-(j%16)/16)
    float a = pos*f;
    int idx = (b*NTL_+t)*32 + j;
    g_lsin[idx]=sinf(a); g_lcos[idx]=cosf(a);
}
__global__ void rope_scene_pre(){
    int t = blockIdx.x, j = threadIdx.x;                   // grid 256, block 32
    int iy = t/16, ix = t%16;
    float gy = (iy+0.5f)*(2.f/16.f)-1.f;
    float gx = (ix+0.5f)*(2.f/16.f)-1.f;
    float pos = (j<16)? gy : gx;
    float f = expf(-4.605170185988091f * (float)(j&15) * (1.f/16.f));
    float a = pos*f;
    g_ssin[t*32+j]=sinf(a); g_scos[t*32+j]=cosf(a);
}

// In-place rope on head-layout buffer. grid (N-prefix, B), block (32, NH)
__global__ void rope_apply(float* __restrict__ X, const float* __restrict__ S,
                           const float* __restrict__ C, int N, int prefix, int rs, int bi)
{
    int t = blockIdx.x, b = blockIdx.y;
    int j = threadIdx.x, h = threadIdx.y;
    int nt = gridDim.x;
    size_t so = bi ? ((size_t)t*32+j) : (((size_t)b*nt+t)*32+j);
    float s = S[so], c = C[so];
    float* xp = X + ((size_t)(b*N+prefix+t)*rs + h*64);
    float x1 = xp[j], x2 = xp[j+32];
    xp[j]    = x1*c - x2*s;
    xp[j+32] = x2*c + x1*s;
}

// ---------------- fused attention: block = (b, h, 64-query tile) ----------------
// smem: qt[64*65] | kv[64*65] | sc[64*Nk(max 256)]
__global__ __launch_bounds__(256) void attn_fused(const float* __restrict__ Q,
                                                  const float* __restrict__ K,
                                                  const float* __restrict__ V,
                                                  float* __restrict__ O,
                                                  int Nq, int Nk, int qs, int ks)
{
    extern __shared__ float sm[];
    float* qt = sm;
    float* kv = sm + 64*65;
    float* sc = sm + 2*64*65;
    const int q0 = blockIdx.x*64;
    const int h = blockIdx.y, b = blockIdx.z, tid = threadIdx.x;
    const int nq = min(64, Nq - q0);

    for (int u = tid; u < nq*16; u += 256) {
        int r = u >> 4, c4 = (u & 15) << 2;
        float4 v4 = *reinterpret_cast<const float4*>(Q + ((size_t)(b*Nq + q0 + r)*qs + h*64 + c4));
        qt[r*65+c4]=v4.x; qt[r*65+c4+1]=v4.y; qt[r*65+c4+2]=v4.z; qt[r*65+c4+3]=v4.w;
    }
    const int tq  = tid >> 2;      // query in tile
    const int tk0 = tid & 3;

    // QK^T * scale
    for (int c0 = 0; c0 < Nk; c0 += 64) {
        int nc = min(64, Nk - c0);
        __syncthreads();
        for (int u = tid; u < nc*16; u += 256) {
            int r = u >> 4, c4 = (u & 15) << 2;
            float4 v4 = *reinterpret_cast<const float4*>(K + ((size_t)(b*Nk + c0 + r)*ks + h*64 + c4));
            kv[r*65+c4]=v4.x; kv[r*65+c4+1]=v4.y; kv[r*65+c4+2]=v4.z; kv[r*65+c4+3]=v4.w;
        }
        __syncthreads();
        if (tq < nq) {
            #pragma unroll 4
            for (int m = 0; m < 16; m++) {
                int k = tk0 + (m<<2);
                if (k < nc) {
                    float d = 0.f;
                    #pragma unroll
                    for (int i = 0; i < 64; i++) d += qt[tq*65+i]*kv[k*65+i];
                    sc[tq*Nk + c0 + k] = d * 0.125f;
                }
            }
        }
    }
    __syncthreads();

    // softmax per row
    if (tid < nq) {
        float m = -1e30f;
        for (int k=0;k<Nk;k++) m = fmaxf(m, sc[tid*Nk+k]);
        float ssum = 0.f;
        for (int k=0;k<Nk;k++){ float e=expf(sc[tid*Nk+k]-m); sc[tid*Nk+k]=e; ssum+=e; }
        float inv = 1.f/ssum;
        for (int k=0;k<Nk;k++) sc[tid*Nk+k]*=inv;
    }
    __syncthreads();

    // P @ V
    const int dg = (tid & 3) << 4;
    float acc[16];
    #pragma unroll
    for (int j=0;j<16;j++) acc[j]=0.f;
    for (int c0 = 0; c0 < Nk; c0 += 64) {
        int nc = min(64, Nk - c0);
        __syncthreads();
        for (int u = tid; u < nc*16; u += 256) {
            int r = u >> 4, c4 = (u & 15) << 2;
            float4 v4 = *reinterpret_cast<const float4*>(V + ((size_t)(b*Nk + c0 + r)*ks + h*64 + c4));
            kv[r*65+c4]=v4.x; kv[r*65+c4+1]=v4.y; kv[r*65+c4+2]=v4.z; kv[r*65+c4+3]=v4.w;
        }
        __syncthreads();
        if (tq < nq) {
            for (int k=0;k<nc;k++){
                float p = sc[tq*Nk + c0 + k];
                #pragma unroll
                for (int j=0;j<16;j++) acc[j] += p*kv[k*65 + dg + j];
            }
        }
    }
    if (tq < nq) {
        float* op = O + ((size_t)(b*Nq + q0 + tq)*D_ + h*64 + dg);
        #pragma unroll
        for (int j=0;j<16;j++) op[j]=acc[j];
    }
}

// ---------------- init: broadcast scene tokens ----------------
__global__ void bcast_scene(const float* __restrict__ st){
    int off = blockIdx.x*256 + threadIdx.x;                // grid (NS_*D_/256, B_)
    g_scene[(size_t)blockIdx.y*(NS_*D_) + off] = st[off];
}

// ---------------- host ----------------
extern "C" void kernel_launch(void* const* d_in, const int* in_sizes, int n_in,
                              void* d_out, int out_size)
{
    (void)in_sizes; (void)n_in; (void)out_size;
    const float* in_local   = (const float*)d_in[0];
    const float* in_centers = (const float*)d_in[1];
    const float* in_scales  = (const float*)d_in[2];
    const float* in_scene   = (const float*)d_in[3];
    const float* rgate = (const float*)d_in[4];
    const float* wgate = (const float*)d_in[5];
    const float* rWq = (const float*)d_in[6];
    const float* rWk = (const float*)d_in[7];
    const float* rWv = (const float*)d_in[8];
    const float* rWo = (const float*)d_in[9];
    const float* wWq = (const float*)d_in[10];
    const float* wWk = (const float*)d_in[11];
    const float* wWv = (const float*)d_in[12];
    const float* wWo = (const float*)d_in[13];
    const float* ln1g = (const float*)d_in[14];
    const float* ln1b = (const float*)d_in[15];
    const float* qkvW = (const float*)d_in[16];
    const float* aWo  = (const float*)d_in[17];
    const float* ln2g = (const float*)d_in[18];
    const float* ln2b = (const float*)d_in[19];
    const float* mW1  = (const float*)d_in[20];
    const float* mW2  = (const float*)d_in[21];

    float *local,*scene,*q,*k,*v,*ao,*hb,*qkv,*mlp,*lsin,*lcos,*ssin,*scos;
    cudaGetSymbolAddress((void**)&local, g_local);
    cudaGetSymbolAddress((void**)&scene, g_scene);
    cudaGetSymbolAddress((void**)&q,   g_q);
    cudaGetSymbolAddress((void**)&k,   g_k);
    cudaGetSymbolAddress((void**)&v,   g_v);
    cudaGetSymbolAddress((void**)&ao,  g_ao);
    cudaGetSymbolAddress((void**)&hb,  g_h);
    cudaGetSymbolAddress((void**)&qkv, g_qkv);
    cudaGetSymbolAddress((void**)&mlp, g_mlp);
    cudaGetSymbolAddress((void**)&lsin, g_lsin);
    cudaGetSymbolAddress((void**)&lcos, g_lcos);
    cudaGetSymbolAddress((void**)&ssin, g_ssin);
    cudaGetSymbolAddress((void**)&scos, g_scos);

    const size_t smem_attn = (size_t)(2*64*65 + 64*256)*sizeof(float);   // ~98.8 KB
    cudaFuncSetAttribute(attn_fused, cudaFuncAttributeMaxDynamicSharedMemorySize, (int)smem_attn);

    cudaMemcpyAsync(local, in_local, sizeof(float)*(size_t)ML_*D_, cudaMemcpyDeviceToDevice);
    bcast_scene<<<dim3(NS_*D_/256, B_),256>>>(in_scene);
    rope_local_pre<<<dim3(NTL_,B_),32>>>(in_centers, in_scales);
    rope_scene_pre<<<NS_,32>>>();

    for (int i=0;i<12;i++){
        size_t wo = (size_t)i*D_*D_;
        // ---- READ cross-attn: q from local, kv from scene ----
        sgemm<0><<<dim3(12,108),256>>>(local, rWq+wo, q, nullptr, ML_, D_, D_);
        rope_apply<<<dim3(NTL_,B_),dim3(32,NH_)>>>(q, lsin, lcos, NL_, P_, D_, 0);
        sgemm<0><<<dim3(12,512),256>>>(scene, rWk+wo, k, nullptr, MS_, D_, D_);
        rope_apply<<<dim3(NS_,B_),dim3(32,NH_)>>>(k, ssin, scos, NS_, 0, D_, 1);
        sgemm<0><<<dim3(12,512),256>>>(scene, rWv+wo, v, nullptr, MS_, D_, D_);
        attn_fused<<<dim3(1,NH_,B_),256,smem_attn>>>(q,k,v,ao, NL_, NS_, D_, D_);
        sgemm<3><<<dim3(12,108),256>>>(ao, rWo+wo, local, rgate+(size_t)i*D_, ML_, D_, D_);

        // ---- ViT block on local ----
        layernorm_k<<<ML_,256>>>(local, hb, ln1g+(size_t)i*D_, ln1b+(size_t)i*D_);
        sgemm<0><<<dim3(36,108),256>>>(hb, qkvW+(size_t)i*D_*3*D_, qkv, nullptr, ML_, 3*D_, D_);
        rope_apply<<<dim3(NTL_,B_),dim3(32,NH_)>>>(qkv,     lsin, lcos, NL_, P_, 3*D_, 0);
        rope_apply<<<dim3(NTL_,B_),dim3(32,NH_)>>>(qkv+D_,  lsin, lcos, NL_, P_, 3*D_, 0);
        attn_fused<<<dim3(1,NH_,B_),256,smem_attn>>>(qkv, qkv+D_, qkv+2*D_, ao, NL_, NL_, 3*D_, 3*D_);
        sgemm<2><<<dim3(12,108),256>>>(ao, aWo+wo, local, nullptr, ML_, D_, D_);
        layernorm_k<<<ML_,256>>>(local, hb, ln2g+(size_t)i*D_, ln2b+(size_t)i*D_);
        sgemm<1><<<dim3(48,108),256>>>(hb, mW1+(size_t)i*D_*4*D_, mlp, nullptr, ML_, 4*D_, D_);
        sgemm<2><<<dim3(12,108),256>>>(mlp, mW2+(size_t)i*4*D_*D_, local, nullptr, ML_, D_, 4*D_);

        // ---- WRITE cross-attn: q from scene, kv from local ----
        sgemm<0><<<dim3(12,512),256>>>(scene, wWq+wo, q, nullptr, MS_, D_, D_);
        rope_apply<<<dim3(NS_,B_),dim3(32,NH_)>>>(q, ssin, scos, NS_, 0, D_, 1);
        sgemm<0><<<dim3(12,108),256>>>(local, wWk+wo, k, nullptr, ML_, D_, D_);
        rope_apply<<<dim3(NTL_,B_),dim3(32,NH_)>>>(k, lsin, lcos, NL_, P_, D_, 0);
        sgemm<0><<<dim3(12,108),256>>>(local, wWv+wo, v, nullptr, ML_, D_, D_);
        attn_fused<<<dim3(4,NH_,B_),256,smem_attn>>>(q,k,v,ao, NS_, NL_, D_, D_);
        sgemm<3><<<dim3(12,512),256>>>(ao, wWo+wo, scene, wgate+(size_t)i*D_, MS_, D_, D_);
    }

    cudaMemcpyAsync(d_out, local, sizeof(float)*(size_t)ML_*D_, cudaMemcpyDeviceToDevice);
    cudaMemcpyAsync((float*)d_out + (size_t)ML_*D_, scene, sizeof(float)*(size_t)MS_*D_,
                    cudaMemcpyDeviceToDevice);
}

// round 5
// speedup vs baseline: 2.5495x; 2.5479x over previous
#include <cuda_runtime.h>
#include <cuda_bf16.h>
#include <cstdint>

#define D_   768
#define NH_  12
#define P_   5
#define NL_  54
#define NS_  256
#define B_   128
#define NTL_ 49
#define ML_  (B_*NL_)
#define MS_  (B_*NS_)
#define DD_  ((size_t)768*768)

__device__ float g_local[(size_t)ML_*D_];
__device__ float g_scene[(size_t)MS_*D_];
__device__ float g_q    [(size_t)MS_*D_];
__device__ float g_k    [(size_t)MS_*D_];
__device__ float g_v    [(size_t)MS_*D_];
__device__ float g_ao   [(size_t)MS_*D_];
__device__ float g_h    [(size_t)ML_*D_];
__device__ float g_qkv  [(size_t)ML_*3*D_];
__device__ float g_mlp  [(size_t)ML_*4*D_];
__device__ float g_lsin [B_*NTL_*32];
__device__ float g_lcos [B_*NTL_*32];
__device__ float g_ssin [NS_*32];
__device__ float g_scos [NS_*32];
__device__ __nv_bfloat16 g_wt[(size_t)12*40*DD_];

__device__ __forceinline__ uint32_t smem_to_u32(const void* p){
    uint32_t a;
    asm("{ .reg .u64 t; cvta.to.shared.u64 t, %1; cvt.u32.u64 %0, t; }" : "=r"(a) : "l"(p));
    return a;
}
#define SWZ(o) ((o) ^ (((o)>>3)&0x70))

__device__ __forceinline__ void ldsm4(uint32_t* r, uint32_t addr){
    asm volatile("ldmatrix.sync.aligned.m8n8.x4.shared.b16 {%0,%1,%2,%3},[%4];"
        : "=r"(r[0]),"=r"(r[1]),"=r"(r[2]),"=r"(r[3]) : "r"(addr));
}
__device__ __forceinline__ void mma16816(float* d, const uint32_t* a, const uint32_t* b){
    asm volatile("mma.sync.aligned.m16n8k16.row.col.f32.bf16.bf16.f32 "
        "{%0,%1,%2,%3},{%4,%5,%6,%7},{%8,%9},{%0,%1,%2,%3};"
        : "+f"(d[0]),"+f"(d[1]),"+f"(d[2]),"+f"(d[3])
        : "r"(a[0]),"r"(a[1]),"r"(a[2]),"r"(a[3]),"r"(b[0]),"r"(b[1]));
}
__device__ __forceinline__ float gelu_f(float x){
    float t = tanhf(0.7978845608028654f*(x + 0.044715f*x*x*x));
    return 0.5f*x*(1.0f+t);
}

// ---- W[L][K][N] fp32 -> hi[N][K], lo[N][K] bf16 ----
__global__ void wsplit(const float* __restrict__ W, __nv_bfloat16* __restrict__ out,
                       int K, int N, size_t sOut)
{
    __shared__ float t[32][33];
    const int l = blockIdx.z;
    const int n0 = blockIdx.x<<5, k0 = blockIdx.y<<5;
    const int tx = threadIdx.x, ty = threadIdx.y;
    const float* Wl = W + (size_t)l*K*N;
    #pragma unroll
    for (int j=0;j<4;j++) t[ty+8*j][tx] = Wl[(size_t)(k0+ty+8*j)*N + n0+tx];
    __syncthreads();
    __nv_bfloat16* hi = out + (size_t)l*sOut;
    __nv_bfloat16* lo = hi + (size_t)N*K;
    #pragma unroll
    for (int j=0;j<4;j++){
        float x = t[tx][ty+8*j];
        __nv_bfloat16 h = __float2bfloat16(x);
        size_t o = (size_t)(n0+ty+8*j)*K + k0+tx;
        hi[o]=h; lo[o]=__float2bfloat16(x - __bfloat162float(h));
    }
}

// ---- mma.sync GEMM: C[MxN] = A[MxK]fp32 * Bt(bf16 hi/lo [N][K]) ----
// block 128x128x64, 8 warps (4M x 2N), warp 32x64. 3-pass split bf16.
// EPI: 0 store, 1 gelu, 2 +=, 3 C += gate[col]*acc
#define SMEMG 65536
template<int EPI>
__global__ __launch_bounds__(256,2) void mmagemm(const float* __restrict__ A,
        const __nv_bfloat16* __restrict__ Bt, float* __restrict__ C,
        const float* __restrict__ gate, int M, int N, int K)
{
    extern __shared__ __nv_bfloat16 smb[];
    char* smc = reinterpret_cast<char*>(smb);
    const uint32_t sb = smem_to_u32(smb);
    const int tid = threadIdx.x, wid = tid>>5, lane = tid&31;
    const int bxn = blockIdx.x<<7, bym = blockIdx.y<<7;
    const int mw = wid>>1, nw = wid&1;
    const size_t NK = (size_t)N*K;

    float acc[2][8][4];
    #pragma unroll
    for (int i=0;i<2;i++)
        #pragma unroll
        for (int j=0;j<8;j++)
            #pragma unroll
            for (int q=0;q<4;q++) acc[i][j][q]=0.f;

    const int NC = K>>6;
    for (int c=0;c<NC;c++){
        const int kc = c<<6;
        {   // A: 128x64 fp32 -> bf16 hi/lo, SW128
            const float* Ag = A + (size_t)bym*K + kc;
            #pragma unroll
            for (int it=0; it<8; it++){
                int u = (it<<8) + tid;
                int r = u>>4, c4 = (u&15)<<2;
                float4 a = *reinterpret_cast<const float4*>(Ag + (size_t)r*K + c4);
                __nv_bfloat162 h01 = __floats2bfloat162_rn(a.x,a.y);
                __nv_bfloat162 h23 = __floats2bfloat162_rn(a.z,a.w);
                __nv_bfloat162 l01 = __floats2bfloat162_rn(a.x-__bfloat162float(h01.x), a.y-__bfloat162float(h01.y));
                __nv_bfloat162 l23 = __floats2bfloat162_rn(a.z-__bfloat162float(h23.x), a.w-__bfloat162float(h23.y));
                uint32_t so = SWZ((uint32_t)(r*128 + c4*2));
                *reinterpret_cast<uint2*>(smc + so) =
                    make_uint2(*reinterpret_cast<uint32_t*>(&h01), *reinterpret_cast<uint32_t*>(&h23));
                *reinterpret_cast<uint2*>(smc + 16384 + so) =
                    make_uint2(*reinterpret_cast<uint32_t*>(&l01), *reinterpret_cast<uint32_t*>(&l23));
            }
        }
        {   // B: 128x64 bf16 hi/lo (already [N][K])
            const __nv_bfloat16* Bh = Bt + (size_t)bxn*K + kc;
            const __nv_bfloat16* Bl = Bh + NK;
            #pragma unroll
            for (int it=0; it<4; it++){
                int u = (it<<8) + tid;
                int r = u>>3, c8 = (u&7)<<3;
                uint32_t so = SWZ((uint32_t)(r*128 + c8*2));
                *reinterpret_cast<uint4*>(smc + 32768 + so) =
                    *reinterpret_cast<const uint4*>(Bh + (size_t)r*K + c8);
                *reinterpret_cast<uint4*>(smc + 49152 + so) =
                    *reinterpret_cast<const uint4*>(Bl + (size_t)r*K + c8);
            }
        }
        __syncthreads();
        #pragma unroll
        for (int ks=0; ks<4; ks++){
            uint32_t ah[2][4], al[2][4];
            #pragma unroll
            for (int ma=0; ma<2; ma++){
                int row = (mw<<5) + (ma<<4) + (lane&15);
                int kb  = (ks<<4) + ((lane>>4)<<3);
                uint32_t off = SWZ((uint32_t)(row*128 + kb*2));
                ldsm4(ah[ma], sb + off);
                ldsm4(al[ma], sb + 16384 + off);
            }
            #pragma unroll
            for (int np=0; np<4; np++){
                uint32_t bh[4], bl[4];
                int row = (nw<<6) + (np<<4) + (lane&7) + ((lane>>4)<<3);
                int kb  = (ks<<4) + (((lane>>3)&1)<<3);
                uint32_t off = SWZ((uint32_t)(row*128 + kb*2));
                ldsm4(bh, sb + 32768 + off);
                ldsm4(bl, sb + 49152 + off);
                // interleaved 3-pass: dependency distance 4 on each accumulator
                #pragma unroll
                for (int ma=0; ma<2; ma++) mma16816(acc[ma][2*np],   ah[ma], bh);
                #pragma unroll
                for (int ma=0; ma<2; ma++) mma16816(acc[ma][2*np+1], ah[ma], bh+2);
                #pragma unroll
                for (int ma=0; ma<2; ma++) mma16816(acc[ma][2*np],   al[ma], bh);
                #pragma unroll
                for (int ma=0; ma<2; ma++) mma16816(acc[ma][2*np+1], al[ma], bh+2);
                #pragma unroll
                for (int ma=0; ma<2; ma++) mma16816(acc[ma][2*np],   ah[ma], bl);
                #pragma unroll
                for (int ma=0; ma<2; ma++) mma16816(acc[ma][2*np+1], ah[ma], bl+2);
            }
        }
        __syncthreads();
    }
    // epilogue
    const int g = lane>>2, t = lane&3;
    #pragma unroll
    for (int ma=0; ma<2; ma++){
        int r0 = bym + (mw<<5) + (ma<<4) + g;
        #pragma unroll
        for (int na=0; na<8; na++){
            int col = bxn + (nw<<6) + (na<<3) + (t<<1);
            float* c0p = C + (size_t)r0*N + col;
            float* c1p = c0p + 8*(size_t)N;
            float2 v0 = make_float2(acc[ma][na][0], acc[ma][na][1]);
            float2 v1 = make_float2(acc[ma][na][2], acc[ma][na][3]);
            if (EPI==1){
                v0.x=gelu_f(v0.x); v0.y=gelu_f(v0.y); v1.x=gelu_f(v1.x); v1.y=gelu_f(v1.y);
            } else if (EPI==2){
                float2 o0 = *reinterpret_cast<float2*>(c0p);
                float2 o1 = *reinterpret_cast<float2*>(c1p);
                v0.x+=o0.x; v0.y+=o0.y; v1.x+=o1.x; v1.y+=o1.y;
            } else if (EPI==3){
                float g0 = gate[col], g1 = gate[col+1];
                float2 o0 = *reinterpret_cast<float2*>(c0p);
                float2 o1 = *reinterpret_cast<float2*>(c1p);
                v0.x=o0.x+g0*v0.x; v0.y=o0.y+g1*v0.y;
                v1.x=o1.x+g0*v1.x; v1.y=o1.y+g1*v1.y;
            }
            *reinterpret_cast<float2*>(c0p) = v0;
            *reinterpret_cast<float2*>(c1p) = v1;
        }
    }
}

// ---- LayerNorm ----
__global__ __launch_bounds__(256) void layernorm_k(const float* __restrict__ X,
        float* __restrict__ Y, const float* __restrict__ g, const float* __restrict__ bb)
{
    __shared__ float red[256];
    const int row = blockIdx.x, tid = threadIdx.x;
    const float* x = X + (size_t)row*D_;
    float v0=x[tid], v1=x[tid+256], v2=x[tid+512];
    red[tid]=v0+v1+v2; __syncthreads();
    for (int o=128;o>0;o>>=1){ if(tid<o) red[tid]+=red[tid+o]; __syncthreads(); }
    float mean = red[0]*(1.f/768.f);
    __syncthreads();
    float d0=v0-mean, d1=v1-mean, d2=v2-mean;
    red[tid]=d0*d0+d1*d1+d2*d2; __syncthreads();
    for (int o=128;o>0;o>>=1){ if(tid<o) red[tid]+=red[tid+o]; __syncthreads(); }
    float inv = rsqrtf(red[0]*(1.f/768.f)+1e-6f);
    float* y = Y + (size_t)row*D_;
    y[tid]=d0*inv*g[tid]+bb[tid];
    y[tid+256]=d1*inv*g[tid+256]+bb[tid+256];
    y[tid+512]=d2*inv*g[tid+512]+bb[tid+512];
}

// ---- RoPE ----
__global__ void rope_local_pre(const float* __restrict__ centers, const float* __restrict__ scales){
    int t=blockIdx.x, b=blockIdx.y, j=threadIdx.x;
    float gy=(t/7+0.5f)*(2.f/7.f)-1.f, gx=(t%7+0.5f)*(2.f/7.f)-1.f;
    float sc=scales[b];
    float pos=(j<16)?(centers[2*b]+sc*gy):(centers[2*b+1]+sc*gx);
    float a=pos*expf(-4.605170185988091f*(float)(j&15)*(1.f/16.f));
    int idx=(b*NTL_+t)*32+j;
    g_lsin[idx]=sinf(a); g_lcos[idx]=cosf(a);
}
__global__ void rope_scene_pre(){
    int t=blockIdx.x, j=threadIdx.x;
    float gy=(t/16+0.5f)*(2.f/16.f)-1.f, gx=(t%16+0.5f)*(2.f/16.f)-1.f;
    float pos=(j<16)?gy:gx;
    float a=pos*expf(-4.605170185988091f*(float)(j&15)*(1.f/16.f));
    g_ssin[t*32+j]=sinf(a); g_scos[t*32+j]=cosf(a);
}
__global__ void rope_apply(float* __restrict__ X, const float* __restrict__ S,
                           const float* __restrict__ C, int N, int prefix, int rs, int bi)
{
    int t=blockIdx.x, b=blockIdx.y, j=threadIdx.x, h=threadIdx.y;
    size_t so = bi ? ((size_t)t*32+j) : (((size_t)b*gridDim.x+t)*32+j);
    float s=S[so], c=C[so];
    float* xp = X + ((size_t)(b*N+prefix+t)*rs + h*64);
    float x1=xp[j], x2=xp[j+32];
    xp[j]=x1*c-x2*s; xp[j+32]=x2*c+x1*s;
}

// ---- attention: 4x4 register micro-tiles, transposed smem tiles ----
#define SMA ((2*64*68 + 256*68)*4)
__global__ __launch_bounds__(256) void attn2(const float* __restrict__ Q,
     const float* __restrict__ K, const float* __restrict__ V, float* __restrict__ O,
     int Nq, int Nk, int qs, int ks)
{
    extern __shared__ float smf[];
    float* qtT = smf;
    float* kvT = smf + 64*68;
    float* scT = smf + 2*64*68;
    const int q0 = blockIdx.x<<6, h = blockIdx.y, b = blockIdx.z;
    const int tid = threadIdx.x;
    const int nq = min(64, Nq - q0);
    const int ty = tid>>4, tx = tid&15;

    for (int u=tid; u<nq*16; u+=256){
        int r=u>>4, c4=(u&15)<<2;
        float4 v = *reinterpret_cast<const float4*>(Q + ((size_t)(b*Nq+q0+r)*qs + h*64 + c4));
        qtT[(c4+0)*68+r]=v.x; qtT[(c4+1)*68+r]=v.y; qtT[(c4+2)*68+r]=v.z; qtT[(c4+3)*68+r]=v.w;
    }
    for (int c0=0; c0<Nk; c0+=64){
        int nc = min(64, Nk-c0);
        __syncthreads();
        for (int u=tid; u<nc*16; u+=256){
            int r=u>>4, c4=(u&15)<<2;
            float4 v = *reinterpret_cast<const float4*>(K + ((size_t)(b*Nk+c0+r)*ks + h*64 + c4));
            kvT[(c4+0)*68+r]=v.x; kvT[(c4+1)*68+r]=v.y; kvT[(c4+2)*68+r]=v.z; kvT[(c4+3)*68+r]=v.w;
        }
        __syncthreads();
        float acc[4][4] = {};
        #pragma unroll 8
        for (int kk=0; kk<64; kk++){
            float4 qv = *reinterpret_cast<float4*>(qtT + kk*68 + (ty<<2));
            float4 kv = *reinterpret_cast<float4*>(kvT + kk*68 + (tx<<2));
            float qa[4]={qv.x,qv.y,qv.z,qv.w}, ka[4]={kv.x,kv.y,kv.z,kv.w};
            #pragma unroll
            for (int i=0;i<4;i++)
                #pragma unroll
                for (int j=0;j<4;j++) acc[i][j]+=qa[i]*ka[j];
        }
        #pragma unroll
        for (int j=0;j<4;j++){
            int kc=(tx<<2)+j;
            if (kc<nc)
                #pragma unroll
                for (int i=0;i<4;i++) scT[(c0+kc)*68+(ty<<2)+i]=acc[i][j]*0.125f;
        }
    }
    __syncthreads();
    if (tid < nq){
        float m=-1e30f;
        for (int k2=0;k2<Nk;k2++) m=fmaxf(m, scT[k2*68+tid]);
        float sum=0.f;
        for (int k2=0;k2<Nk;k2++){ float e=expf(scT[k2*68+tid]-m); scT[k2*68+tid]=e; sum+=e; }
        qtT[tid]=1.f/sum;
    }
    __syncthreads();
    float acc[4][4] = {};
    for (int c0=0; c0<Nk; c0+=64){
        int nc = min(64, Nk-c0);
        for (int u=tid; u<nc*16; u+=256){
            int r=u>>4, c4=(u&15)<<2;
            *reinterpret_cast<float4*>(kvT + r*68 + c4) =
                *reinterpret_cast<const float4*>(V + ((size_t)(b*Nk+c0+r)*ks + h*64 + c4));
        }
        __syncthreads();
        for (int k2=0;k2<nc;k2++){
            float4 p4 = *reinterpret_cast<float4*>(scT + (c0+k2)*68 + (ty<<2));
            float4 v4 = *reinterpret_cast<float4*>(kvT + k2*68 + (tx<<2));
            float pa[4]={p4.x,p4.y,p4.z,p4.w}, va[4]={v4.x,v4.y,v4.z,v4.w};
            #pragma unroll
            for (int i=0;i<4;i++)
                #pragma unroll
                for (int j=0;j<4;j++) acc[i][j]+=pa[i]*va[j];
        }
        __syncthreads();
    }
    #pragma unroll
    for (int i=0;i<4;i++){
        int qr=(ty<<2)+i;
        if (qr<nq){
            float iv=qtT[qr];
            float4 o = make_float4(acc[i][0]*iv, acc[i][1]*iv, acc[i][2]*iv, acc[i][3]*iv);
            *reinterpret_cast<float4*>(O + ((size_t)(b*Nq+q0+qr)*D_ + h*64 + (tx<<2))) = o;
        }
    }
}

__global__ void bcast_scene(const float* __restrict__ st){
    int off = blockIdx.x*256 + threadIdx.x;
    g_scene[(size_t)blockIdx.y*(NS_*D_) + off] = st[off];
}

extern "C" void kernel_launch(void* const* d_in, const int* in_sizes, int n_in,
                              void* d_out, int out_size)
{
    (void)in_sizes; (void)n_in; (void)out_size;
    const float *in_local=(const float*)d_in[0], *in_centers=(const float*)d_in[1],
        *in_scales=(const float*)d_in[2], *in_scene=(const float*)d_in[3],
        *rgate=(const float*)d_in[4], *wgate=(const float*)d_in[5],
        *rWq=(const float*)d_in[6], *rWk=(const float*)d_in[7], *rWv=(const float*)d_in[8],
        *rWo=(const float*)d_in[9], *wWq=(const float*)d_in[10], *wWk=(const float*)d_in[11],
        *wWv=(const float*)d_in[12], *wWo=(const float*)d_in[13],
        *ln1g=(const float*)d_in[14], *ln1b=(const float*)d_in[15],
        *qkvW=(const float*)d_in[16], *aWo=(const float*)d_in[17],
        *ln2g=(const float*)d_in[18], *ln2b=(const float*)d_in[19],
        *mW1=(const float*)d_in[20], *mW2=(const float*)d_in[21];

    float *local,*scene,*q,*k,*v,*ao,*hb,*qkv,*mlp,*lsin,*lcos,*ssin,*scos;
    __nv_bfloat16* wt;
    cudaGetSymbolAddress((void**)&local,g_local); cudaGetSymbolAddress((void**)&scene,g_scene);
    cudaGetSymbolAddress((void**)&q,g_q); cudaGetSymbolAddress((void**)&k,g_k);
    cudaGetSymbolAddress((void**)&v,g_v); cudaGetSymbolAddress((void**)&ao,g_ao);
    cudaGetSymbolAddress((void**)&hb,g_h); cudaGetSymbolAddress((void**)&qkv,g_qkv);
    cudaGetSymbolAddress((void**)&mlp,g_mlp);
    cudaGetSymbolAddress((void**)&lsin,g_lsin); cudaGetSymbolAddress((void**)&lcos,g_lcos);
    cudaGetSymbolAddress((void**)&ssin,g_ssin); cudaGetSymbolAddress((void**)&scos,g_scos);
    cudaGetSymbolAddress((void**)&wt,g_wt);

    cudaFuncSetAttribute(mmagemm<0>, cudaFuncAttributeMaxDynamicSharedMemorySize, SMEMG);
    cudaFuncSetAttribute(mmagemm<1>, cudaFuncAttributeMaxDynamicSharedMemorySize, SMEMG);
    cudaFuncSetAttribute(mmagemm<2>, cudaFuncAttributeMaxDynamicSharedMemorySize, SMEMG);
    cudaFuncSetAttribute(mmagemm<3>, cudaFuncAttributeMaxDynamicSharedMemorySize, SMEMG);
    cudaFuncSetAttribute(attn2, cudaFuncAttributeMaxDynamicSharedMemorySize, SMA);

    const size_t LS = 40*DD_;
    dim3 tb(32,8);
    wsplit<<<dim3(24,24,12),tb>>>(rWq,  wt+0*DD_,  768, 768,  LS);
    wsplit<<<dim3(24,24,12),tb>>>(rWk,  wt+2*DD_,  768, 768,  LS);
    wsplit<<<dim3(24,24,12),tb>>>(rWv,  wt+4*DD_,  768, 768,  LS);
    wsplit<<<dim3(24,24,12),tb>>>(rWo,  wt+6*DD_,  768, 768,  LS);
    wsplit<<<dim3(24,24,12),tb>>>(wWq,  wt+8*DD_,  768, 768,  LS);
    wsplit<<<dim3(24,24,12),tb>>>(wWk,  wt+10*DD_, 768, 768,  LS);
    wsplit<<<dim3(24,24,12),tb>>>(wWv,  wt+12*DD_, 768, 768,  LS);
    wsplit<<<dim3(24,24,12),tb>>>(wWo,  wt+14*DD_, 768, 768,  LS);
    wsplit<<<dim3(72,24,12),tb>>>(qkvW, wt+16*DD_, 768, 2304, LS);
    wsplit<<<dim3(24,24,12),tb>>>(aWo,  wt+22*DD_, 768, 768,  LS);
    wsplit<<<dim3(96,24,12),tb>>>(mW1,  wt+24*DD_, 768, 3072, LS);
    wsplit<<<dim3(24,96,12),tb>>>(mW2,  wt+32*DD_, 3072, 768, LS);

    cudaMemcpyAsync(local, in_local, sizeof(float)*(size_t)ML_*D_, cudaMemcpyDeviceToDevice);
    bcast_scene<<<dim3(NS_*D_/256, B_),256>>>(in_scene);
    rope_local_pre<<<dim3(NTL_,B_),32>>>(in_centers, in_scales);
    rope_scene_pre<<<NS_,32>>>();

    for (int i=0;i<12;i++){
        const __nv_bfloat16* wb = wt + (size_t)i*LS;
        mmagemm<0><<<dim3(6,54),   256, SMEMG>>>(local, wb+0*DD_, q, nullptr, ML_, 768, 768);
        rope_apply<<<dim3(NTL_,B_),dim3(32,NH_)>>>(q, lsin, lcos, NL_, P_, D_, 0);
        mmagemm<0><<<dim3(6,256),  256, SMEMG>>>(scene, wb+2*DD_, k, nullptr, MS_, 768, 768);
        rope_apply<<<dim3(NS_,B_),dim3(32,NH_)>>>(k, ssin, scos, NS_, 0, D_, 1);
        mmagemm<0><<<dim3(6,256),  256, SMEMG>>>(scene, wb+4*DD_, v, nullptr, MS_, 768, 768);
        attn2<<<dim3(1,NH_,B_),256,SMA>>>(q,k,v,ao, NL_, NS_, D_, D_);
        mmagemm<3><<<dim3(6,54),   256, SMEMG>>>(ao, wb+6*DD_, local, rgate+(size_t)i*D_, ML_, 768, 768);

        layernorm_k<<<ML_,256>>>(local, hb, ln1g+(size_t)i*D_, ln1b+(size_t)i*D_);
        mmagemm<0><<<dim3(18,54),  256, SMEMG>>>(hb, wb+16*DD_, qkv, nullptr, ML_, 2304, 768);
        rope_apply<<<dim3(NTL_,B_),dim3(32,NH_)>>>(qkv,    lsin, lcos, NL_, P_, 3*D_, 0);
        rope_apply<<<dim3(NTL_,B_),dim3(32,NH_)>>>(qkv+D_, lsin, lcos, NL_, P_, 3*D_, 0);
        attn2<<<dim3(1,NH_,B_),256,SMA>>>(qkv, qkv+D_, qkv+2*D_, ao, NL_, NL_, 3*D_, 3*D_);
        mmagemm<2><<<dim3(6,54),   256, SMEMG>>>(ao, wb+22*DD_, local, nullptr, ML_, 768, 768);
        layernorm_k<<<ML_,256>>>(local, hb, ln2g+(size_t)i*D_, ln2b+(size_t)i*D_);
        mmagemm<1><<<dim3(24,54),  256, SMEMG>>>(hb, wb+24*DD_, mlp, nullptr, ML_, 3072, 768);
        mmagemm<2><<<dim3(6,54),   256, SMEMG>>>(mlp, wb+32*DD_, local, nullptr, ML_, 768, 3072);

        mmagemm<0><<<dim3(6,256),  256, SMEMG>>>(scene, wb+8*DD_, q, nullptr, MS_, 768, 768);
        rope_apply<<<dim3(NS_,B_),dim3(32,NH_)>>>(q, ssin, scos, NS_, 0, D_, 1);
        mmagemm<0><<<dim3(6,54),   256, SMEMG>>>(local, wb+10*DD_, k, nullptr, ML_, 768, 768);
        rope_apply<<<dim3(NTL_,B_),dim3(32,NH_)>>>(k, lsin, lcos, NL_, P_, D_, 0);
        mmagemm<0><<<dim3(6,54),   256, SMEMG>>>(local, wb+12*DD_, v, nullptr, ML_, 768, 768);
        attn2<<<dim3(4,NH_,B_),256,SMA>>>(q,k,v,ao, NS_, NL_, D_, D_);
        mmagemm<3><<<dim3(6,256),  256, SMEMG>>>(ao, wb+14*DD_, scene, wgate+(size_t)i*D_, MS_, 768, 768);
    }

    cudaMemcpyAsync(d_out, local, sizeof(float)*(size_t)ML_*D_, cudaMemcpyDeviceToDevice);
    cudaMemcpyAsync((float*)d_out + (size_t)ML_*D_, scene, sizeof(float)*(size_t)MS_*D_,
                    cudaMemcpyDeviceToDevice);
}

// round 6
// speedup vs baseline: 4.0029x; 1.5701x over previous
#include <cuda_runtime.h>
#include <cuda_fp16.h>
#include <cstdint>

#define D_   768
#define NH_  12
#define P_   5
#define NL_  54
#define NS_  256
#define B_   128
#define NTL_ 49
#define ML_  (B_*NL_)
#define MS_  (B_*NS_)
#define DD_  ((size_t)768*768)

__device__ float g_local[(size_t)ML_*D_];
__device__ float g_scene[(size_t)MS_*D_];
__device__ float g_q    [(size_t)MS_*D_];
__device__ float g_k    [(size_t)MS_*D_];
__device__ float g_v    [(size_t)MS_*D_];
__device__ float g_ao   [(size_t)MS_*D_];
__device__ float g_h    [(size_t)ML_*D_];
__device__ float g_qkv  [(size_t)ML_*3*D_];
__device__ float g_mlp  [(size_t)ML_*4*D_];
__device__ float g_lsin [B_*NTL_*32];
__device__ float g_lcos [B_*NTL_*32];
__device__ float g_ssin [NS_*32];
__device__ float g_scos [NS_*32];
__device__ __half g_wt[(size_t)12*20*DD_];
__device__ __half g_ah[(size_t)MS_*D_];
__device__ __half g_al[(size_t)MS_*D_];

__device__ __forceinline__ uint32_t smem_to_u32(const void* p){
    uint32_t a;
    asm("{ .reg .u64 t; cvta.to.shared.u64 t, %1; cvt.u32.u64 %0, t; }" : "=r"(a) : "l"(p));
    return a;
}
#define SWZ(o) ((o) ^ (((o)>>3)&0x70))
#define CPA16(dst,src) asm volatile("cp.async.cg.shared.global [%0],[%1],16;"::"r"(dst),"l"(src))
#define CPA_COMMIT() asm volatile("cp.async.commit_group;")

__device__ __forceinline__ void ldsm4(uint32_t* r, uint32_t addr){
    asm volatile("ldmatrix.sync.aligned.m8n8.x4.shared.b16 {%0,%1,%2,%3},[%4];"
        : "=r"(r[0]),"=r"(r[1]),"=r"(r[2]),"=r"(r[3]) : "r"(addr));
}
__device__ __forceinline__ void mma16816(float* d, const uint32_t* a, const uint32_t* b){
    asm volatile("mma.sync.aligned.m16n8k16.row.col.f32.f16.f16.f32 "
        "{%0,%1,%2,%3},{%4,%5,%6,%7},{%8,%9},{%0,%1,%2,%3};"
        : "+f"(d[0]),"+f"(d[1]),"+f"(d[2]),"+f"(d[3])
        : "r"(a[0]),"r"(a[1]),"r"(a[2]),"r"(a[3]),"r"(b[0]),"r"(b[1]));
}
__device__ __forceinline__ float gelu_f(float x){
    float t = tanhf(0.7978845608028654f*(x + 0.044715f*x*x*x));
    return 0.5f*x*(1.0f+t);
}

// ---- W[L][K][N] fp32 -> hi[N][K] fp16 (transpose) ----
__global__ void wsplit(const float* __restrict__ W, __half* __restrict__ out,
                       int K, int N, size_t sOut)
{
    __shared__ float t[32][33];
    const int l = blockIdx.z;
    const int n0 = blockIdx.x<<5, k0 = blockIdx.y<<5;
    const int tx = threadIdx.x, ty = threadIdx.y;
    const float* Wl = W + (size_t)l*K*N;
    #pragma unroll
    for (int j=0;j<4;j++) t[ty+8*j][tx] = Wl[(size_t)(k0+ty+8*j)*N + n0+tx];
    __syncthreads();
    __half* hi = out + (size_t)l*sOut;
    #pragma unroll
    for (int j=0;j<4;j++)
        hi[(size_t)(n0+ty+8*j)*K + k0+tx] = __float2half_rn(t[tx][ty+8*j]);
}

// ---- activation split: X fp32 -> H, L fp16 ----
__global__ __launch_bounds__(256) void asplit(const float* __restrict__ X,
        __half* __restrict__ H, __half* __restrict__ L)
{
    int i = blockIdx.x*256 + threadIdx.x;
    float4 a = reinterpret_cast<const float4*>(X)[i];
    __half hx = __float2half_rn(a.x), hy = __float2half_rn(a.y);
    __half hz = __float2half_rn(a.z), hw = __float2half_rn(a.w);
    __half lx = __float2half_rn(a.x-__half2float(hx));
    __half ly = __float2half_rn(a.y-__half2float(hy));
    __half lz = __float2half_rn(a.z-__half2float(hz));
    __half lw = __float2half_rn(a.w-__half2float(hw));
    __half2 h01 = __halves2half2(hx,hy), h23 = __halves2half2(hz,hw);
    __half2 l01 = __halves2half2(lx,ly), l23 = __halves2half2(lz,lw);
    reinterpret_cast<uint2*>(H)[i] = make_uint2(*reinterpret_cast<uint32_t*>(&h01),
                                                *reinterpret_cast<uint32_t*>(&h23));
    reinterpret_cast<uint2*>(L)[i] = make_uint2(*reinterpret_cast<uint32_t*>(&l01),
                                                *reinterpret_cast<uint32_t*>(&l23));
}

// ---- mma.sync GEMM: C[MxN] = (Ah+Al)[MxK] * Bh[N][K]^T ; 2-pass fp16 split ----
// block 128x128x64, 8 warps (4M x 2N), cp.async double-buffered
// EPI: 0 store, 1 gelu, 2 +=, 3 C += gate[col]*acc
#define STAGE_ 49152
#define SMEMG (2*STAGE_)
template<int EPI>
__global__ __launch_bounds__(256,2) void mmagemm(const __half* __restrict__ Ah,
        const __half* __restrict__ Al, const __half* __restrict__ Bh,
        float* __restrict__ C, const float* __restrict__ gate, int M, int N, int K)
{
    extern __shared__ char smc[];
    const uint32_t sb = smem_to_u32(smc);
    const int tid = threadIdx.x, wid = tid>>5, lane = tid&31;
    const int n0 = blockIdx.x<<7, m0 = blockIdx.y<<7;
    const int mw = wid>>1, nw = wid&1;

    float acc[2][8][4];
    #pragma unroll
    for (int i=0;i<2;i++)
        #pragma unroll
        for (int j=0;j<8;j++)
            #pragma unroll
            for (int q=0;q<4;q++) acc[i][j][q]=0.f;

    const int NC = K>>6;
    auto issue = [&](int c){
        const int s = c&1, kc = c<<6;
        const uint32_t sbase = sb + s*STAGE_;
        #pragma unroll
        for (int it=0; it<4; it++){
            int u = (it<<8) + tid;
            int r = u>>3, c16 = u&7;
            uint32_t dst = sbase + SWZ((uint32_t)(r*128 + c16*16));
            CPA16(dst,         Ah + (size_t)(m0+r)*K + kc + (c16<<3));
            CPA16(dst + 16384, Al + (size_t)(m0+r)*K + kc + (c16<<3));
            CPA16(dst + 32768, Bh + (size_t)(n0+r)*K + kc + (c16<<3));
        }
        CPA_COMMIT();
    };
    issue(0);
    for (int c=0; c<NC; c++){
        if (c+1 < NC){ issue(c+1); asm volatile("cp.async.wait_group 1;"); }
        else         {             asm volatile("cp.async.wait_group 0;"); }
        __syncthreads();
        const uint32_t sbase = sb + (c&1)*STAGE_;
        #pragma unroll
        for (int ks=0; ks<4; ks++){
            uint32_t ah[2][4], al[2][4];
            #pragma unroll
            for (int ma=0; ma<2; ma++){
                int row = (mw<<5) + (ma<<4) + (lane&15);
                int kb  = (ks<<4) + ((lane>>4)<<3);
                uint32_t off = SWZ((uint32_t)(row*128 + kb*2));
                ldsm4(ah[ma], sbase + off);
                ldsm4(al[ma], sbase + 16384 + off);
            }
            #pragma unroll
            for (int np=0; np<4; np++){
                uint32_t bh[4];
                int row = (nw<<6) + (np<<4) + (lane&7) + ((lane>>4)<<3);
                int kb  = (ks<<4) + (((lane>>3)&1)<<3);
                ldsm4(bh, sbase + 32768 + SWZ((uint32_t)(row*128 + kb*2)));
                #pragma unroll
                for (int ma=0; ma<2; ma++) mma16816(acc[ma][2*np],   ah[ma], bh);
                #pragma unroll
                for (int ma=0; ma<2; ma++) mma16816(acc[ma][2*np+1], ah[ma], bh+2);
                #pragma unroll
                for (int ma=0; ma<2; ma++) mma16816(acc[ma][2*np],   al[ma], bh);
                #pragma unroll
                for (int ma=0; ma<2; ma++) mma16816(acc[ma][2*np+1], al[ma], bh+2);
            }
        }
        __syncthreads();
    }
    const int g = lane>>2, t = lane&3;
    #pragma unroll
    for (int ma=0; ma<2; ma++){
        int r0 = m0 + (mw<<5) + (ma<<4) + g;
        #pragma unroll
        for (int na=0; na<8; na++){
            int col = n0 + (nw<<6) + (na<<3) + (t<<1);
            float* c0p = C + (size_t)r0*N + col;
            float* c1p = c0p + 8*(size_t)N;
            float2 v0 = make_float2(acc[ma][na][0], acc[ma][na][1]);
            float2 v1 = make_float2(acc[ma][na][2], acc[ma][na][3]);
            if (EPI==1){
                v0.x=gelu_f(v0.x); v0.y=gelu_f(v0.y); v1.x=gelu_f(v1.x); v1.y=gelu_f(v1.y);
            } else if (EPI==2){
                float2 o0 = *reinterpret_cast<float2*>(c0p);
                float2 o1 = *reinterpret_cast<float2*>(c1p);
                v0.x+=o0.x; v0.y+=o0.y; v1.x+=o1.x; v1.y+=o1.y;
            } else if (EPI==3){
                float g0 = gate[col], g1 = gate[col+1];
                float2 o0 = *reinterpret_cast<float2*>(c0p);
                float2 o1 = *reinterpret_cast<float2*>(c1p);
                v0.x=o0.x+g0*v0.x; v0.y=o0.y+g1*v0.y;
                v1.x=o1.x+g0*v1.x; v1.y=o1.y+g1*v1.y;
            }
            *reinterpret_cast<float2*>(c0p) = v0;
            *reinterpret_cast<float2*>(c1p) = v1;
        }
    }
}

// ---- LayerNorm ----
__global__ __launch_bounds__(256) void layernorm_k(const float* __restrict__ X,
        float* __restrict__ Y, const float* __restrict__ g, const float* __restrict__ bb)
{
    __shared__ float red[256];
    const int row = blockIdx.x, tid = threadIdx.x;
    const float* x = X + (size_t)row*D_;
    float v0=x[tid], v1=x[tid+256], v2=x[tid+512];
    red[tid]=v0+v1+v2; __syncthreads();
    for (int o=128;o>0;o>>=1){ if(tid<o) red[tid]+=red[tid+o]; __syncthreads(); }
    float mean = red[0]*(1.f/768.f);
    __syncthreads();
    float d0=v0-mean, d1=v1-mean, d2=v2-mean;
    red[tid]=d0*d0+d1*d1+d2*d2; __syncthreads();
    for (int o=128;o>0;o>>=1){ if(tid<o) red[tid]+=red[tid+o]; __syncthreads(); }
    float inv = rsqrtf(red[0]*(1.f/768.f)+1e-6f);
    float* y = Y + (size_t)row*D_;
    y[tid]=d0*inv*g[tid]+bb[tid];
    y[tid+256]=d1*inv*g[tid+256]+bb[tid+256];
    y[tid+512]=d2*inv*g[tid+512]+bb[tid+512];
}

// ---- RoPE ----
__global__ void rope_local_pre(const float* __restrict__ centers, const float* __restrict__ scales){
    int t=blockIdx.x, b=blockIdx.y, j=threadIdx.x;
    float gy=(t/7+0.5f)*(2.f/7.f)-1.f, gx=(t%7+0.5f)*(2.f/7.f)-1.f;
    float sc=scales[b];
    float pos=(j<16)?(centers[2*b]+sc*gy):(centers[2*b+1]+sc*gx);
    float a=pos*expf(-4.605170185988091f*(float)(j&15)*(1.f/16.f));
    int idx=(b*NTL_+t)*32+j;
    g_lsin[idx]=sinf(a); g_lcos[idx]=cosf(a);
}
__global__ void rope_scene_pre(){
    int t=blockIdx.x, j=threadIdx.x;
    float gy=(t/16+0.5f)*(2.f/16.f)-1.f, gx=(t%16+0.5f)*(2.f/16.f)-1.f;
    float pos=(j<16)?gy:gx;
    float a=pos*expf(-4.605170185988091f*(float)(j&15)*(1.f/16.f));
    g_ssin[t*32+j]=sinf(a); g_scos[t*32+j]=cosf(a);
}
__global__ void rope_apply(float* __restrict__ X, const float* __restrict__ S,
                           const float* __restrict__ C, int N, int prefix, int rs, int bi)
{
    int t=blockIdx.x, b=blockIdx.y, j=threadIdx.x, h=threadIdx.y;
    size_t so = bi ? ((size_t)t*32+j) : (((size_t)b*gridDim.x+t)*32+j);
    float s=S[so], c=C[so];
    float* xp = X + ((size_t)(b*N+prefix+t)*rs + h*64);
    float x1=xp[j], x2=xp[j+32];
    xp[j]=x1*c-x2*s; xp[j+32]=x2*c+x1*s;
}

// ---- attention: 4x4 register micro-tiles, transposed smem tiles ----
#define SMA ((2*64*68 + 256*68)*4)
__global__ __launch_bounds__(256) void attn2(const float* __restrict__ Q,
     const float* __restrict__ K, const float* __restrict__ V, float* __restrict__ O,
     int Nq, int Nk, int qs, int ks)
{
    extern __shared__ float smf[];
    float* qtT = smf;
    float* kvT = smf + 64*68;
    float* scT = smf + 2*64*68;
    const int q0 = blockIdx.x<<6, h = blockIdx.y, b = blockIdx.z;
    const int tid = threadIdx.x;
    const int nq = min(64, Nq - q0);
    const int ty = tid>>4, tx = tid&15;

    for (int u=tid; u<nq*16; u+=256){
        int r=u>>4, c4=(u&15)<<2;
        float4 v = *reinterpret_cast<const float4*>(Q + ((size_t)(b*Nq+q0+r)*qs + h*64 + c4));
        qtT[(c4+0)*68+r]=v.x; qtT[(c4+1)*68+r]=v.y; qtT[(c4+2)*68+r]=v.z; qtT[(c4+3)*68+r]=v.w;
    }
    for (int c0=0; c0<Nk; c0+=64){
        int nc = min(64, Nk-c0);
        __syncthreads();
        for (int u=tid; u<nc*16; u+=256){
            int r=u>>4, c4=(u&15)<<2;
            float4 v = *reinterpret_cast<const float4*>(K + ((size_t)(b*Nk+c0+r)*ks + h*64 + c4));
            kvT[(c4+0)*68+r]=v.x; kvT[(c4+1)*68+r]=v.y; kvT[(c4+2)*68+r]=v.z; kvT[(c4+3)*68+r]=v.w;
        }
        __syncthreads();
        float acc[4][4] = {};
        #pragma unroll 8
        for (int kk=0; kk<64; kk++){
            float4 qv = *reinterpret_cast<float4*>(qtT + kk*68 + (ty<<2));
            float4 kv = *reinterpret_cast<float4*>(kvT + kk*68 + (tx<<2));
            float qa[4]={qv.x,qv.y,qv.z,qv.w}, ka[4]={kv.x,kv.y,kv.z,kv.w};
            #pragma unroll
            for (int i=0;i<4;i++)
                #pragma unroll
                for (int j=0;j<4;j++) acc[i][j]+=qa[i]*ka[j];
        }
        #pragma unroll
        for (int j=0;j<4;j++){
            int kc=(tx<<2)+j;
            if (kc<nc)
                #pragma unroll
                for (int i=0;i<4;i++) scT[(c0+kc)*68+(ty<<2)+i]=acc[i][j]*0.125f;
        }
    }
    __syncthreads();
    if (tid < nq){
        float m=-1e30f;
        for (int k2=0;k2<Nk;k2++) m=fmaxf(m, scT[k2*68+tid]);
        float sum=0.f;
        for (int k2=0;k2<Nk;k2++){ float e=expf(scT[k2*68+tid]-m); scT[k2*68+tid]=e; sum+=e; }
        qtT[tid]=1.f/sum;
    }
    __syncthreads();
    float acc[4][4] = {};
    for (int c0=0; c0<Nk; c0+=64){
        int nc = min(64, Nk-c0);
        for (int u=tid; u<nc*16; u+=256){
            int r=u>>4, c4=(u&15)<<2;
            *reinterpret_cast<float4*>(kvT + r*68 + c4) =
                *reinterpret_cast<const float4*>(V + ((size_t)(b*Nk+c0+r)*ks + h*64 + c4));
        }
        __syncthreads();
        for (int k2=0;k2<nc;k2++){
            float4 p4 = *reinterpret_cast<float4*>(scT + (c0+k2)*68 + (ty<<2));
            float4 v4 = *reinterpret_cast<float4*>(kvT + k2*68 + (tx<<2));
            float pa[4]={p4.x,p4.y,p4.z,p4.w}, va[4]={v4.x,v4.y,v4.z,v4.w};
            #pragma unroll
            for (int i=0;i<4;i++)
                #pragma unroll
                for (int j=0;j<4;j++) acc[i][j]+=pa[i]*va[j];
        }
        __syncthreads();
    }
    #pragma unroll
    for (int i=0;i<4;i++){
        int qr=(ty<<2)+i;
        if (qr<nq){
            float iv=qtT[qr];
            float4 o = make_float4(acc[i][0]*iv, acc[i][1]*iv, acc[i][2]*iv, acc[i][3]*iv);
            *reinterpret_cast<float4*>(O + ((size_t)(b*Nq+q0+qr)*D_ + h*64 + (tx<<2))) = o;
        }
    }
}

__global__ void bcast_scene(const float* __restrict__ st){
    int off = blockIdx.x*256 + threadIdx.x;
    g_scene[(size_t)blockIdx.y*(NS_*D_) + off] = st[off];
}

extern "C" void kernel_launch(void* const* d_in, const int* in_sizes, int n_in,
                              void* d_out, int out_size)
{
    (void)in_sizes; (void)n_in; (void)out_size;
    const float *in_local=(const float*)d_in[0], *in_centers=(const float*)d_in[1],
        *in_scales=(const float*)d_in[2], *in_scene=(const float*)d_in[3],
        *rgate=(const float*)d_in[4], *wgate=(const float*)d_in[5],
        *rWq=(const float*)d_in[6], *rWk=(const float*)d_in[7], *rWv=(const float*)d_in[8],
        *rWo=(const float*)d_in[9], *wWq=(const float*)d_in[10], *wWk=(const float*)d_in[11],
        *wWv=(const float*)d_in[12], *wWo=(const float*)d_in[13],
        *ln1g=(const float*)d_in[14], *ln1b=(const float*)d_in[15],
        *qkvW=(const float*)d_in[16], *aWo=(const float*)d_in[17],
        *ln2g=(const float*)d_in[18], *ln2b=(const float*)d_in[19],
        *mW1=(const float*)d_in[20], *mW2=(const float*)d_in[21];

    float *local,*scene,*q,*k,*v,*ao,*hb,*qkv,*mlp,*lsin,*lcos,*ssin,*scos;
    __half *wt,*ah,*al;
    cudaGetSymbolAddress((void**)&local,g_local); cudaGetSymbolAddress((void**)&scene,g_scene);
    cudaGetSymbolAddress((void**)&q,g_q); cudaGetSymbolAddress((void**)&k,g_k);
    cudaGetSymbolAddress((void**)&v,g_v); cudaGetSymbolAddress((void**)&ao,g_ao);
    cudaGetSymbolAddress((void**)&hb,g_h); cudaGetSymbolAddress((void**)&qkv,g_qkv);
    cudaGetSymbolAddress((void**)&mlp,g_mlp);
    cudaGetSymbolAddress((void**)&lsin,g_lsin); cudaGetSymbolAddress((void**)&lcos,g_lcos);
    cudaGetSymbolAddress((void**)&ssin,g_ssin); cudaGetSymbolAddress((void**)&scos,g_scos);
    cudaGetSymbolAddress((void**)&wt,g_wt);
    cudaGetSymbolAddress((void**)&ah,g_ah); cudaGetSymbolAddress((void**)&al,g_al);

    cudaFuncSetAttribute(mmagemm<0>, cudaFuncAttributeMaxDynamicSharedMemorySize, SMEMG);
    cudaFuncSetAttribute(mmagemm<1>, cudaFuncAttributeMaxDynamicSharedMemorySize, SMEMG);
    cudaFuncSetAttribute(mmagemm<2>, cudaFuncAttributeMaxDynamicSharedMemorySize, SMEMG);
    cudaFuncSetAttribute(mmagemm<3>, cudaFuncAttributeMaxDynamicSharedMemorySize, SMEMG);
    cudaFuncSetAttribute(attn2, cudaFuncAttributeMaxDynamicSharedMemorySize, SMA);

    const size_t LS = 20*DD_;
    dim3 tb(32,8);
    wsplit<<<dim3(24,24,12),tb>>>(rWq,  wt+0*DD_,  768, 768,  LS);
    wsplit<<<dim3(24,24,12),tb>>>(rWk,  wt+1*DD_,  768, 768,  LS);
    wsplit<<<dim3(24,24,12),tb>>>(rWv,  wt+2*DD_,  768, 768,  LS);
    wsplit<<<dim3(24,24,12),tb>>>(rWo,  wt+3*DD_,  768, 768,  LS);
    wsplit<<<dim3(24,24,12),tb>>>(wWq,  wt+4*DD_,  768, 768,  LS);
    wsplit<<<dim3(24,24,12),tb>>>(wWk,  wt+5*DD_,  768, 768,  LS);
    wsplit<<<dim3(24,24,12),tb>>>(wWv,  wt+6*DD_,  768, 768,  LS);
    wsplit<<<dim3(24,24,12),tb>>>(wWo,  wt+7*DD_,  768, 768,  LS);
    wsplit<<<dim3(72,24,12),tb>>>(qkvW, wt+8*DD_,  768, 2304, LS);
    wsplit<<<dim3(24,24,12),tb>>>(aWo,  wt+11*DD_, 768, 768,  LS);
    wsplit<<<dim3(96,24,12),tb>>>(mW1,  wt+12*DD_, 768, 3072, LS);
    wsplit<<<dim3(24,96,12),tb>>>(mW2,  wt+16*DD_, 3072, 768, LS);

    cudaMemcpyAsync(local, in_local, sizeof(float)*(size_t)ML_*D_, cudaMemcpyDeviceToDevice);
    bcast_scene<<<dim3(NS_*D_/256, B_),256>>>(in_scene);
    rope_local_pre<<<dim3(NTL_,B_),32>>>(in_centers, in_scales);
    rope_scene_pre<<<NS_,32>>>();

    const int AML = ML_*D_/1024;    // asplit blocks for ML x 768
    const int AMS = MS_*D_/1024;
    const int AMLP = ML_*4*D_/1024;

    for (int i=0;i<12;i++){
        const __half* wb = wt + (size_t)i*LS;
        // ---- READ cross-attn ----
        asplit<<<AML,256>>>(local, ah, al);
        mmagemm<0><<<dim3(6,54),   256, SMEMG>>>(ah, al, wb+0*DD_, q, nullptr, ML_, 768, 768);
        rope_apply<<<dim3(NTL_,B_),dim3(32,NH_)>>>(q, lsin, lcos, NL_, P_, D_, 0);
        asplit<<<AMS,256>>>(scene, ah, al);
        mmagemm<0><<<dim3(6,256),  256, SMEMG>>>(ah, al, wb+1*DD_, k, nullptr, MS_, 768, 768);
        rope_apply<<<dim3(NS_,B_),dim3(32,NH_)>>>(k, ssin, scos, NS_, 0, D_, 1);
        mmagemm<0><<<dim3(6,256),  256, SMEMG>>>(ah, al, wb+2*DD_, v, nullptr, MS_, 768, 768);
        attn2<<<dim3(1,NH_,B_),256,SMA>>>(q,k,v,ao, NL_, NS_, D_, D_);
        asplit<<<AML,256>>>(ao, ah, al);
        mmagemm<3><<<dim3(6,54),   256, SMEMG>>>(ah, al, wb+3*DD_, local, rgate+(size_t)i*D_, ML_, 768, 768);
        // ---- ViT block ----
        layernorm_k<<<ML_,256>>>(local, hb, ln1g+(size_t)i*D_, ln1b+(size_t)i*D_);
        asplit<<<AML,256>>>(hb, ah, al);
        mmagemm<0><<<dim3(18,54),  256, SMEMG>>>(ah, al, wb+8*DD_, qkv, nullptr, ML_, 2304, 768);
        rope_apply<<<dim3(NTL_,B_),dim3(32,NH_)>>>(qkv,    lsin, lcos, NL_, P_, 3*D_, 0);
        rope_apply<<<dim3(NTL_,B_),dim3(32,NH_)>>>(qkv+D_, lsin, lcos, NL_, P_, 3*D_, 0);
        attn2<<<dim3(1,NH_,B_),256,SMA>>>(qkv, qkv+D_, qkv+2*D_, ao, NL_, NL_, 3*D_, 3*D_);
        asplit<<<AML,256>>>(ao, ah, al);
        mmagemm<2><<<dim3(6,54),   256, SMEMG>>>(ah, al, wb+11*DD_, local, nullptr, ML_, 768, 768);
        layernorm_k<<<ML_,256>>>(local, hb, ln2g+(size_t)i*D_, ln2b+(size_t)i*D_);
        asplit<<<AML,256>>>(hb, ah, al);
        mmagemm<1><<<dim3(24,54),  256, SMEMG>>>(ah, al, wb+12*DD_, mlp, nullptr, ML_, 3072, 768);
        asplit<<<AMLP,256>>>(mlp, ah, al);
        mmagemm<2><<<dim3(6,54),   256, SMEMG>>>(ah, al, wb+16*DD_, local, nullptr, ML_, 768, 3072);
        // ---- WRITE cross-attn ----
        asplit<<<AMS,256>>>(scene, ah, al);
        mmagemm<0><<<dim3(6,256),  256, SMEMG>>>(ah, al, wb+4*DD_, q, nullptr, MS_, 768, 768);
        rope_apply<<<dim3(NS_,B_),dim3(32,NH_)>>>(q, ssin, scos, NS_, 0, D_, 1);
        asplit<<<AML,256>>>(local, ah, al);
        mmagemm<0><<<dim3(6,54),   256, SMEMG>>>(ah, al, wb+5*DD_, k, nullptr, ML_, 768, 768);
        rope_apply<<<dim3(NTL_,B_),dim3(32,NH_)>>>(k, lsin, lcos, NL_, P_, D_, 0);
        mmagemm<0><<<dim3(6,54),   256, SMEMG>>>(ah, al, wb+6*DD_, v, nullptr, ML_, 768, 768);
        attn2<<<dim3(4,NH_,B_),256,SMA>>>(q,k,v,ao, NS_, NL_, D_, D_);
        asplit<<<AMS,256>>>(ao, ah, al);
        mmagemm<3><<<dim3(6,256),  256, SMEMG>>>(ah, al, wb+7*DD_, scene, wgate+(size_t)i*D_, MS_, 768, 768);
    }

    cudaMemcpyAsync(d_out, local, sizeof(float)*(size_t)ML_*D_, cudaMemcpyDeviceToDevice);
    cudaMemcpyAsync((float*)d_out + (size_t)ML_*D_, scene, sizeof(float)*(size_t)MS_*D_,
                    cudaMemcpyDeviceToDevice);
}

// round 7
// speedup vs baseline: 4.1437x; 1.0352x over previous
#include <cuda_runtime.h>
#include <cuda_fp16.h>
#include <cstdint>

#define D_   768
#define NH_  12
#define P_   5
#define NL_  54
#define NS_  256
#define B_   128
#define NTL_ 49
#define ML_  (B_*NL_)
#define MS_  (B_*NS_)
#define DD_  ((size_t)768*768)

__device__ float g_local[(size_t)ML_*D_];
__device__ float g_scene[(size_t)MS_*D_];
__device__ float g_q    [(size_t)MS_*D_];
__device__ float g_k    [(size_t)MS_*D_];
__device__ float g_v    [(size_t)MS_*D_];
__device__ float g_qkv  [(size_t)ML_*3*D_];
__device__ float g_lsin [B_*NTL_*32];
__device__ float g_lcos [B_*NTL_*32];
__device__ float g_ssin [NS_*32];
__device__ float g_scos [NS_*32];
__device__ __half g_wt[(size_t)12*20*DD_];
// fp16 hi/lo split buffers (producer-fused)
__device__ __half g_lh [(size_t)ML_*D_],   g_ll [(size_t)ML_*D_];
__device__ __half g_sh [(size_t)MS_*D_],   g_sl [(size_t)MS_*D_];
__device__ __half g_aoh[(size_t)MS_*D_],   g_aol[(size_t)MS_*D_];
__device__ __half g_hbh[(size_t)ML_*D_],   g_hbl[(size_t)ML_*D_];
__device__ __half g_mh [(size_t)ML_*4*D_], g_ml [(size_t)ML_*4*D_];

__device__ __forceinline__ uint32_t smem_to_u32(const void* p){
    uint32_t a;
    asm("{ .reg .u64 t; cvta.to.shared.u64 t, %1; cvt.u32.u64 %0, t; }" : "=r"(a) : "l"(p));
    return a;
}
#define SWZ(o) ((o) ^ (((o)>>3)&0x70))
#define CPA16(dst,src) asm volatile("cp.async.cg.shared.global [%0],[%1],16;"::"r"(dst),"l"(src))
#define CPA_COMMIT() asm volatile("cp.async.commit_group;")

__device__ __forceinline__ void ldsm4(uint32_t* r, uint32_t addr){
    asm volatile("ldmatrix.sync.aligned.m8n8.x4.shared.b16 {%0,%1,%2,%3},[%4];"
        : "=r"(r[0]),"=r"(r[1]),"=r"(r[2]),"=r"(r[3]) : "r"(addr));
}
__device__ __forceinline__ void mma16816(float* d, const uint32_t* a, const uint32_t* b){
    asm volatile("mma.sync.aligned.m16n8k16.row.col.f32.f16.f16.f32 "
        "{%0,%1,%2,%3},{%4,%5,%6,%7},{%8,%9},{%0,%1,%2,%3};"
        : "+f"(d[0]),"+f"(d[1]),"+f"(d[2]),"+f"(d[3])
        : "r"(a[0]),"r"(a[1]),"r"(a[2]),"r"(a[3]),"r"(b[0]),"r"(b[1]));
}
__device__ __forceinline__ float gelu_f(float x){
    float t = tanhf(0.7978845608028654f*(x + 0.044715f*x*x*x));
    return 0.5f*x*(1.0f+t);
}
__device__ __forceinline__ void split2(float2 v, __half* H, __half* L, size_t idx){
    __half hx = __float2half_rn(v.x), hy = __float2half_rn(v.y);
    __half lx = __float2half_rn(v.x-__half2float(hx));
    __half ly = __float2half_rn(v.y-__half2float(hy));
    *reinterpret_cast<__half2*>(H+idx) = __halves2half2(hx,hy);
    *reinterpret_cast<__half2*>(L+idx) = __halves2half2(lx,ly);
}

// ---- W[L][K][N] fp32 -> [N][K] fp16 (transpose) ----
__global__ void wsplit(const float* __restrict__ W, __half* __restrict__ out,
                       int K, int N, size_t sOut)
{
    __shared__ float t[32][33];
    const int l = blockIdx.z;
    const int n0 = blockIdx.x<<5, k0 = blockIdx.y<<5;
    const int tx = threadIdx.x, ty = threadIdx.y;
    const float* Wl = W + (size_t)l*K*N;
    #pragma unroll
    for (int j=0;j<4;j++) t[ty+8*j][tx] = Wl[(size_t)(k0+ty+8*j)*N + n0+tx];
    __syncthreads();
    __half* hi = out + (size_t)l*sOut;
    #pragma unroll
    for (int j=0;j<4;j++)
        hi[(size_t)(n0+ty+8*j)*K + k0+tx] = __float2half_rn(t[tx][ty+8*j]);
}

// ---- activation split (init only) ----
__global__ __launch_bounds__(256) void asplit(const float* __restrict__ X,
        __half* __restrict__ H, __half* __restrict__ L)
{
    int i = blockIdx.x*256 + threadIdx.x;
    float4 a = reinterpret_cast<const float4*>(X)[i];
    split2(make_float2(a.x,a.y), H, L, (size_t)i*4);
    split2(make_float2(a.z,a.w), H, L, (size_t)i*4+2);
}

// ---- mma.sync GEMM: C = (Ah+Al) * Bh^T ; 2-pass fp16 split; cp.async double-buffered ----
// EPI: 0 store, 1 gelu, 2 +=, 3 C += gate[col]*acc ; SPLIT: also emit hi/lo fp16 (EPI1: only split)
#define STAGE_ 49152
#define SMEMG (2*STAGE_)
template<int EPI, int SPLIT>
__global__ __launch_bounds__(256,2) void mmagemm(const __half* __restrict__ Ah,
        const __half* __restrict__ Al, const __half* __restrict__ Bh,
        float* __restrict__ C, __half* __restrict__ Hs, __half* __restrict__ Ls,
        const float* __restrict__ gate, int M, int N, int K)
{
    extern __shared__ char smc[];
    const uint32_t sb = smem_to_u32(smc);
    const int tid = threadIdx.x, wid = tid>>5, lane = tid&31;
    const int n0 = blockIdx.x<<7, m0 = blockIdx.y<<7;
    const int mw = wid>>1, nw = wid&1;

    float acc[2][8][4];
    #pragma unroll
    for (int i=0;i<2;i++)
        #pragma unroll
        for (int j=0;j<8;j++)
            #pragma unroll
            for (int q=0;q<4;q++) acc[i][j][q]=0.f;

    const int NC = K>>6;
    auto issue = [&](int c){
        const int s = c&1, kc = c<<6;
        const uint32_t sbase = sb + s*STAGE_;
        #pragma unroll
        for (int it=0; it<4; it++){
            int u = (it<<8) + tid;
            int r = u>>3, c16 = u&7;
            uint32_t dst = sbase + SWZ((uint32_t)(r*128 + c16*16));
            CPA16(dst,         Ah + (size_t)(m0+r)*K + kc + (c16<<3));
            CPA16(dst + 16384, Al + (size_t)(m0+r)*K + kc + (c16<<3));
            CPA16(dst + 32768, Bh + (size_t)(n0+r)*K + kc + (c16<<3));
        }
        CPA_COMMIT();
    };
    issue(0);
    for (int c=0; c<NC; c++){
        if (c+1 < NC){ issue(c+1); asm volatile("cp.async.wait_group 1;"); }
        else         {             asm volatile("cp.async.wait_group 0;"); }
        __syncthreads();
        const uint32_t sbase = sb + (c&1)*STAGE_;
        #pragma unroll
        for (int ks=0; ks<4; ks++){
            uint32_t ah[2][4], al[2][4];
            #pragma unroll
            for (int ma=0; ma<2; ma++){
                int row = (mw<<5) + (ma<<4) + (lane&15);
                int kb  = (ks<<4) + ((lane>>4)<<3);
                uint32_t off = SWZ((uint32_t)(row*128 + kb*2));
                ldsm4(ah[ma], sbase + off);
                ldsm4(al[ma], sbase + 16384 + off);
            }
            #pragma unroll
            for (int np=0; np<4; np++){
                uint32_t bh[4];
                int row = (nw<<6) + (np<<4) + (lane&7) + ((lane>>4)<<3);
                int kb  = (ks<<4) + (((lane>>3)&1)<<3);
                ldsm4(bh, sbase + 32768 + SWZ((uint32_t)(row*128 + kb*2)));
                #pragma unroll
                for (int ma=0; ma<2; ma++) mma16816(acc[ma][2*np],   ah[ma], bh);
                #pragma unroll
                for (int ma=0; ma<2; ma++) mma16816(acc[ma][2*np+1], ah[ma], bh+2);
                #pragma unroll
                for (int ma=0; ma<2; ma++) mma16816(acc[ma][2*np],   al[ma], bh);
                #pragma unroll
                for (int ma=0; ma<2; ma++) mma16816(acc[ma][2*np+1], al[ma], bh+2);
            }
        }
        __syncthreads();
    }
    const int g = lane>>2, t = lane&3;
    #pragma unroll
    for (int ma=0; ma<2; ma++){
        int r0 = m0 + (mw<<5) + (ma<<4) + g;
        #pragma unroll
        for (int na=0; na<8; na++){
            int col = n0 + (nw<<6) + (na<<3) + (t<<1);
            size_t i0 = (size_t)r0*N + col;
            size_t i1 = i0 + 8*(size_t)N;
            float2 v0 = make_float2(acc[ma][na][0], acc[ma][na][1]);
            float2 v1 = make_float2(acc[ma][na][2], acc[ma][na][3]);
            if (EPI==1){
                v0.x=gelu_f(v0.x); v0.y=gelu_f(v0.y); v1.x=gelu_f(v1.x); v1.y=gelu_f(v1.y);
            } else if (EPI==2){
                float2 o0 = *reinterpret_cast<float2*>(C+i0);
                float2 o1 = *reinterpret_cast<float2*>(C+i1);
                v0.x+=o0.x; v0.y+=o0.y; v1.x+=o1.x; v1.y+=o1.y;
            } else if (EPI==3){
                float g0 = gate[col], g1 = gate[col+1];
                float2 o0 = *reinterpret_cast<float2*>(C+i0);
                float2 o1 = *reinterpret_cast<float2*>(C+i1);
                v0.x=o0.x+g0*v0.x; v0.y=o0.y+g1*v0.y;
                v1.x=o1.x+g0*v1.x; v1.y=o1.y+g1*v1.y;
            }
            if (!(EPI==1 && SPLIT)){
                *reinterpret_cast<float2*>(C+i0) = v0;
                *reinterpret_cast<float2*>(C+i1) = v1;
            }
            if (SPLIT){
                split2(v0, Hs, Ls, i0);
                split2(v1, Hs, Ls, i1);
            }
        }
    }
}

// ---- LayerNorm: fp32 in -> fp16 hi/lo out ----
__global__ __launch_bounds__(256) void layernorm_k(const float* __restrict__ X,
        __half* __restrict__ H, __half* __restrict__ L,
        const float* __restrict__ g, const float* __restrict__ bb)
{
    __shared__ float red[256];
    const int row = blockIdx.x, tid = threadIdx.x;
    const float* x = X + (size_t)row*D_;
    float v0=x[tid], v1=x[tid+256], v2=x[tid+512];
    red[tid]=v0+v1+v2; __syncthreads();
    for (int o=128;o>0;o>>=1){ if(tid<o) red[tid]+=red[tid+o]; __syncthreads(); }
    float mean = red[0]*(1.f/768.f);
    __syncthreads();
    float d0=v0-mean, d1=v1-mean, d2=v2-mean;
    red[tid]=d0*d0+d1*d1+d2*d2; __syncthreads();
    for (int o=128;o>0;o>>=1){ if(tid<o) red[tid]+=red[tid+o]; __syncthreads(); }
    float inv = rsqrtf(red[0]*(1.f/768.f)+1e-6f);
    size_t base = (size_t)row*D_;
    #pragma unroll
    for (int p=0; p<3; p++){
        float d = (p==0)?d0:(p==1)?d1:d2;
        int o = tid + p*256;
        float y = d*inv*g[o] + bb[o];
        __half h = __float2half_rn(y);
        H[base+o] = h; L[base+o] = __float2half_rn(y-__half2float(h));
    }
}

// ---- RoPE ----
__global__ void rope_local_pre(const float* __restrict__ centers, const float* __restrict__ scales){
    int t=blockIdx.x, b=blockIdx.y, j=threadIdx.x;
    float gy=(t/7+0.5f)*(2.f/7.f)-1.f, gx=(t%7+0.5f)*(2.f/7.f)-1.f;
    float sc=scales[b];
    float pos=(j<16)?(centers[2*b]+sc*gy):(centers[2*b+1]+sc*gx);
    float a=pos*expf(-4.605170185988091f*(float)(j&15)*(1.f/16.f));
    int idx=(b*NTL_+t)*32+j;
    g_lsin[idx]=sinf(a); g_lcos[idx]=cosf(a);
}
__global__ void rope_scene_pre(){
    int t=blockIdx.x, j=threadIdx.x;
    float gy=(t/16+0.5f)*(2.f/16.f)-1.f, gx=(t%16+0.5f)*(2.f/16.f)-1.f;
    float pos=(j<16)?gy:gx;
    float a=pos*expf(-4.605170185988091f*(float)(j&15)*(1.f/16.f));
    g_ssin[t*32+j]=sinf(a); g_scos[t*32+j]=cosf(a);
}
__global__ void rope_apply(float* __restrict__ X, const float* __restrict__ S,
                           const float* __restrict__ C, int N, int prefix, int rs, int bi)
{
    int t=blockIdx.x, b=blockIdx.y, j=threadIdx.x, h=threadIdx.y;
    size_t so = bi ? ((size_t)t*32+j) : (((size_t)b*gridDim.x+t)*32+j);
    float s=S[so], c=C[so];
    float* xp = X + ((size_t)(b*N+prefix+t)*rs + h*64);
    float x1=xp[j], x2=xp[j+32];
    xp[j]=x1*c-x2*s; xp[j+32]=x2*c+x1*s;
}

// ---- attention: fp32 compute, fp16 hi/lo output ----
#define SMA ((2*64*68 + 256*68)*4)
__global__ __launch_bounds__(256) void attn2(const float* __restrict__ Q,
     const float* __restrict__ K, const float* __restrict__ V,
     __half* __restrict__ Oh, __half* __restrict__ Ol,
     int Nq, int Nk, int qs, int ks)
{
    extern __shared__ float smf[];
    float* qtT = smf;
    float* kvT = smf + 64*68;
    float* scT = smf + 2*64*68;
    const int q0 = blockIdx.x<<6, h = blockIdx.y, b = blockIdx.z;
    const int tid = threadIdx.x;
    const int nq = min(64, Nq - q0);
    const int ty = tid>>4, tx = tid&15;

    for (int u=tid; u<nq*16; u+=256){
        int r=u>>4, c4=(u&15)<<2;
        float4 v = *reinterpret_cast<const float4*>(Q + ((size_t)(b*Nq+q0+r)*qs + h*64 + c4));
        qtT[(c4+0)*68+r]=v.x; qtT[(c4+1)*68+r]=v.y; qtT[(c4+2)*68+r]=v.z; qtT[(c4+3)*68+r]=v.w;
    }
    for (int c0=0; c0<Nk; c0+=64){
        int nc = min(64, Nk-c0);
        __syncthreads();
        for (int u=tid; u<nc*16; u+=256){
            int r=u>>4, c4=(u&15)<<2;
            float4 v = *reinterpret_cast<const float4*>(K + ((size_t)(b*Nk+c0+r)*ks + h*64 + c4));
            kvT[(c4+0)*68+r]=v.x; kvT[(c4+1)*68+r]=v.y; kvT[(c4+2)*68+r]=v.z; kvT[(c4+3)*68+r]=v.w;
        }
        __syncthreads();
        float acc[4][4] = {};
        #pragma unroll 8
        for (int kk=0; kk<64; kk++){
            float4 qv = *reinterpret_cast<float4*>(qtT + kk*68 + (ty<<2));
            float4 kv = *reinterpret_cast<float4*>(kvT + kk*68 + (tx<<2));
            float qa[4]={qv.x,qv.y,qv.z,qv.w}, ka[4]={kv.x,kv.y,kv.z,kv.w};
            #pragma unroll
            for (int i=0;i<4;i++)
                #pragma unroll
                for (int j=0;j<4;j++) acc[i][j]+=qa[i]*ka[j];
        }
        #pragma unroll
        for (int j=0;j<4;j++){
            int kc=(tx<<2)+j;
            if (kc<nc)
                #pragma unroll
                for (int i=0;i<4;i++) scT[(c0+kc)*68+(ty<<2)+i]=acc[i][j]*0.125f;
        }
    }
    __syncthreads();
    if (tid < nq){
        float m=-1e30f;
        for (int k2=0;k2<Nk;k2++) m=fmaxf(m, scT[k2*68+tid]);
        float sum=0.f;
        for (int k2=0;k2<Nk;k2++){ float e=expf(scT[k2*68+tid]-m); scT[k2*68+tid]=e; sum+=e; }
        qtT[tid]=1.f/sum;
    }
    __syncthreads();
    float acc[4][4] = {};
    for (int c0=0; c0<Nk; c0+=64){
        int nc = min(64, Nk-c0);
        for (int u=tid; u<nc*16; u+=256){
            int r=u>>4, c4=(u&15)<<2;
            *reinterpret_cast<float4*>(kvT + r*68 + c4) =
                *reinterpret_cast<const float4*>(V + ((size_t)(b*Nk+c0+r)*ks + h*64 + c4));
        }
        __syncthreads();
        for (int k2=0;k2<nc;k2++){
            float4 p4 = *reinterpret_cast<float4*>(scT + (c0+k2)*68 + (ty<<2));
            float4 v4 = *reinterpret_cast<float4*>(kvT + k2*68 + (tx<<2));
            float pa[4]={p4.x,p4.y,p4.z,p4.w}, va[4]={v4.x,v4.y,v4.z,v4.w};
            #pragma unroll
            for (int i=0;i<4;i++)
                #pragma unroll
                for (int j=0;j<4;j++) acc[i][j]+=pa[i]*va[j];
        }
        __syncthreads();
    }
    #pragma unroll
    for (int i=0;i<4;i++){
        int qr=(ty<<2)+i;
        if (qr<nq){
            float iv=qtT[qr];
            size_t idx = (size_t)(b*Nq+q0+qr)*D_ + h*64 + (tx<<2);
            split2(make_float2(acc[i][0]*iv, acc[i][1]*iv), Oh, Ol, idx);
            split2(make_float2(acc[i][2]*iv, acc[i][3]*iv), Oh, Ol, idx+2);
        }
    }
}

// ---- scene broadcast: fp32 + fp16 split ----
__global__ void bcast_scene(const float* __restrict__ st){
    int off = blockIdx.x*256 + threadIdx.x;
    float v = st[off];
    g_scene[(size_t)blockIdx.y*(NS_*D_) + off] = v;
    __half h = __float2half_rn(v);
    size_t i = (size_t)blockIdx.y*(NS_*D_) + off;
    g_sh[i] = h; g_sl[i] = __float2half_rn(v-__half2float(h));
}

extern "C" void kernel_launch(void* const* d_in, const int* in_sizes, int n_in,
                              void* d_out, int out_size)
{
    (void)in_sizes; (void)n_in; (void)out_size;
    const float *in_local=(const float*)d_in[0], *in_centers=(const float*)d_in[1],
        *in_scales=(const float*)d_in[2], *in_scene=(const float*)d_in[3],
        *rgate=(const float*)d_in[4], *wgate=(const float*)d_in[5],
        *rWq=(const float*)d_in[6], *rWk=(const float*)d_in[7], *rWv=(const float*)d_in[8],
        *rWo=(const float*)d_in[9], *wWq=(const float*)d_in[10], *wWk=(const float*)d_in[11],
        *wWv=(const float*)d_in[12], *wWo=(const float*)d_in[13],
        *ln1g=(const float*)d_in[14], *ln1b=(const float*)d_in[15],
        *qkvW=(const float*)d_in[16], *aWo=(const float*)d_in[17],
        *ln2g=(const float*)d_in[18], *ln2b=(const float*)d_in[19],
        *mW1=(const float*)d_in[20], *mW2=(const float*)d_in[21];

    float *local,*scene,*q,*k,*v,*qkv,*lsin,*lcos,*ssin,*scos;
    __half *wt,*lh,*ll,*sh,*sl,*aoh,*aol,*hbh,*hbl,*mh,*ml;
    cudaGetSymbolAddress((void**)&local,g_local); cudaGetSymbolAddress((void**)&scene,g_scene);
    cudaGetSymbolAddress((void**)&q,g_q); cudaGetSymbolAddress((void**)&k,g_k);
    cudaGetSymbolAddress((void**)&v,g_v); cudaGetSymbolAddress((void**)&qkv,g_qkv);
    cudaGetSymbolAddress((void**)&lsin,g_lsin); cudaGetSymbolAddress((void**)&lcos,g_lcos);
    cudaGetSymbolAddress((void**)&ssin,g_ssin); cudaGetSymbolAddress((void**)&scos,g_scos);
    cudaGetSymbolAddress((void**)&wt,g_wt);
    cudaGetSymbolAddress((void**)&lh,g_lh);   cudaGetSymbolAddress((void**)&ll,g_ll);
    cudaGetSymbolAddress((void**)&sh,g_sh);   cudaGetSymbolAddress((void**)&sl,g_sl);
    cudaGetSymbolAddress((void**)&aoh,g_aoh); cudaGetSymbolAddress((void**)&aol,g_aol);
    cudaGetSymbolAddress((void**)&hbh,g_hbh); cudaGetSymbolAddress((void**)&hbl,g_hbl);
    cudaGetSymbolAddress((void**)&mh,g_mh);   cudaGetSymbolAddress((void**)&ml,g_ml);

    cudaFuncSetAttribute(mmagemm<0,0>, cudaFuncAttributeMaxDynamicSharedMemorySize, SMEMG);
    cudaFuncSetAttribute(mmagemm<1,1>, cudaFuncAttributeMaxDynamicSharedMemorySize, SMEMG);
    cudaFuncSetAttribute(mmagemm<2,0>, cudaFuncAttributeMaxDynamicSharedMemorySize, SMEMG);
    cudaFuncSetAttribute(mmagemm<2,1>, cudaFuncAttributeMaxDynamicSharedMemorySize, SMEMG);
    cudaFuncSetAttribute(mmagemm<3,0>, cudaFuncAttributeMaxDynamicSharedMemorySize, SMEMG);
    cudaFuncSetAttribute(mmagemm<3,1>, cudaFuncAttributeMaxDynamicSharedMemorySize, SMEMG);
    cudaFuncSetAttribute(attn2, cudaFuncAttributeMaxDynamicSharedMemorySize, SMA);

    const size_t LS = 20*DD_;
    dim3 tb(32,8);
    wsplit<<<dim3(24,24,12),tb>>>(rWq,  wt+0*DD_,  768, 768,  LS);
    wsplit<<<dim3(24,24,12),tb>>>(rWk,  wt+1*DD_,  768, 768,  LS);
    wsplit<<<dim3(24,24,12),tb>>>(rWv,  wt+2*DD_,  768, 768,  LS);
    wsplit<<<dim3(24,24,12),tb>>>(rWo,  wt+3*DD_,  768, 768,  LS);
    wsplit<<<dim3(24,24,12),tb>>>(wWq,  wt+4*DD_,  768, 768,  LS);
    wsplit<<<dim3(24,24,12),tb>>>(wWk,  wt+5*DD_,  768, 768,  LS);
    wsplit<<<dim3(24,24,12),tb>>>(wWv,  wt+6*DD_,  768, 768,  LS);
    wsplit<<<dim3(24,24,12),tb>>>(wWo,  wt+7*DD_,  768, 768,  LS);
    wsplit<<<dim3(72,24,12),tb>>>(qkvW, wt+8*DD_,  768, 2304, LS);
    wsplit<<<dim3(24,24,12),tb>>>(aWo,  wt+11*DD_, 768, 768,  LS);
    wsplit<<<dim3(96,24,12),tb>>>(mW1,  wt+12*DD_, 768, 3072, LS);
    wsplit<<<dim3(24,96,12),tb>>>(mW2,  wt+16*DD_, 3072, 768, LS);

    cudaMemcpyAsync(local, in_local, sizeof(float)*(size_t)ML_*D_, cudaMemcpyDeviceToDevice);
    bcast_scene<<<dim3(NS_*D_/256, B_),256>>>(in_scene);
    rope_local_pre<<<dim3(NTL_,B_),32>>>(in_centers, in_scales);
    rope_scene_pre<<<NS_,32>>>();
    asplit<<<ML_*D_/1024,256>>>(local, lh, ll);   // initial local split

    for (int i=0;i<12;i++){
        const __half* wb = wt + (size_t)i*LS;
        // ---- READ cross-attn ----
        mmagemm<0,0><<<dim3(6,54),  256, SMEMG>>>(lh, ll, wb+0*DD_, q, nullptr,nullptr, nullptr, ML_, 768, 768);
        rope_apply<<<dim3(NTL_,B_),dim3(32,NH_)>>>(q, lsin, lcos, NL_, P_, D_, 0);
        mmagemm<0,0><<<dim3(6,256), 256, SMEMG>>>(sh, sl, wb+1*DD_, k, nullptr,nullptr, nullptr, MS_, 768, 768);
        rope_apply<<<dim3(NS_,B_),dim3(32,NH_)>>>(k, ssin, scos, NS_, 0, D_, 1);
        mmagemm<0,0><<<dim3(6,256), 256, SMEMG>>>(sh, sl, wb+2*DD_, v, nullptr,nullptr, nullptr, MS_, 768, 768);
        attn2<<<dim3(1,NH_,B_),256,SMA>>>(q,k,v, aoh,aol, NL_, NS_, D_, D_);
        mmagemm<3,0><<<dim3(6,54),  256, SMEMG>>>(aoh, aol, wb+3*DD_, local, nullptr,nullptr, rgate+(size_t)i*D_, ML_, 768, 768);
        // ---- ViT block ----
        layernorm_k<<<ML_,256>>>(local, hbh, hbl, ln1g+(size_t)i*D_, ln1b+(size_t)i*D_);
        mmagemm<0,0><<<dim3(18,54), 256, SMEMG>>>(hbh, hbl, wb+8*DD_, qkv, nullptr,nullptr, nullptr, ML_, 2304, 768);
        rope_apply<<<dim3(NTL_,B_),dim3(32,NH_)>>>(qkv,    lsin, lcos, NL_, P_, 3*D_, 0);
        rope_apply<<<dim3(NTL_,B_),dim3(32,NH_)>>>(qkv+D_, lsin, lcos, NL_, P_, 3*D_, 0);
        attn2<<<dim3(1,NH_,B_),256,SMA>>>(qkv, qkv+D_, qkv+2*D_, aoh,aol, NL_, NL_, 3*D_, 3*D_);
        mmagemm<2,0><<<dim3(6,54),  256, SMEMG>>>(aoh, aol, wb+11*DD_, local, nullptr,nullptr, nullptr, ML_, 768, 768);
        layernorm_k<<<ML_,256>>>(local, hbh, hbl, ln2g+(size_t)i*D_, ln2b+(size_t)i*D_);
        mmagemm<1,1><<<dim3(24,54), 256, SMEMG>>>(hbh, hbl, wb+12*DD_, nullptr, mh, ml, nullptr, ML_, 3072, 768);
        mmagemm<2,1><<<dim3(6,54),  256, SMEMG>>>(mh, ml, wb+16*DD_, local, lh, ll, nullptr, ML_, 768, 3072);
        // ---- WRITE cross-attn ----
        mmagemm<0,0><<<dim3(6,256), 256, SMEMG>>>(sh, sl, wb+4*DD_, q, nullptr,nullptr, nullptr, MS_, 768, 768);
        rope_apply<<<dim3(NS_,B_),dim3(32,NH_)>>>(q, ssin, scos, NS_, 0, D_, 1);
        mmagemm<0,0><<<dim3(6,54),  256, SMEMG>>>(lh, ll, wb+5*DD_, k, nullptr,nullptr, nullptr, ML_, 768, 768);
        rope_apply<<<dim3(NTL_,B_),dim3(32,NH_)>>>(k, lsin, lcos, NL_, P_, D_, 0);
        mmagemm<0,0><<<dim3(6,54),  256, SMEMG>>>(lh, ll, wb+6*DD_, v, nullptr,nullptr, nullptr, ML_, 768, 768);
        attn2<<<dim3(4,NH_,B_),256,SMA>>>(q,k,v, aoh,aol, NS_, NL_, D_, D_);
        mmagemm<3,1><<<dim3(6,256), 256, SMEMG>>>(aoh, aol, wb+7*DD_, scene, sh, sl, wgate+(size_t)i*D_, MS_, 768, 768);
    }

    cudaMemcpyAsync(d_out, local, sizeof(float)*(size_t)ML_*D_, cudaMemcpyDeviceToDevice);
    cudaMemcpyAsync((float*)d_out + (size_t)ML_*D_, scene, sizeof(float)*(size_t)MS_*D_,
                    cudaMemcpyDeviceToDevice);
}

// round 8
// speedup vs baseline: 5.8374x; 1.4087x over previous
#include <cuda_runtime.h>
#include <cuda_fp16.h>
#include <cstdint>

#define D_   768
#define NH_  12
#define P_   5
#define NL_  54
#define NS_  256
#define B_   128
#define NTL_ 49
#define ML_  (B_*NL_)
#define MS_  (B_*NS_)
#define DD_  ((size_t)768*768)

__device__ float g_local[(size_t)ML_*D_];
__device__ float g_scene[(size_t)MS_*D_];
__device__ float g_q    [(size_t)MS_*D_];
__device__ float g_k    [(size_t)MS_*D_];
__device__ float g_v    [(size_t)MS_*D_];
__device__ float g_qkv  [(size_t)ML_*3*D_];
__device__ float g_lsin [B_*NTL_*32];
__device__ float g_lcos [B_*NTL_*32];
__device__ float g_ssin [NS_*32];
__device__ float g_scos [NS_*32];
__device__ __half g_wt[(size_t)12*20*DD_];
__device__ __half g_lh [(size_t)ML_*D_];
__device__ __half g_sh [(size_t)MS_*D_];
__device__ __half g_aoh[(size_t)MS_*D_];
__device__ __half g_hbh[(size_t)ML_*D_];
__device__ __half g_mh [(size_t)ML_*4*D_];

__device__ __forceinline__ uint32_t smem_to_u32(const void* p){
    uint32_t a;
    asm("{ .reg .u64 t; cvta.to.shared.u64 t, %1; cvt.u32.u64 %0, t; }" : "=r"(a) : "l"(p));
    return a;
}
#define SWZ(o) ((o) ^ (((o)>>3)&0x70))
#define CPA16(dst,src) asm volatile("cp.async.cg.shared.global [%0],[%1],16;"::"r"(dst),"l"(src))
#define CPA_COMMIT() asm volatile("cp.async.commit_group;")

__device__ __forceinline__ void ldsm4(uint32_t* r, uint32_t addr){
    asm volatile("ldmatrix.sync.aligned.m8n8.x4.shared.b16 {%0,%1,%2,%3},[%4];"
        : "=r"(r[0]),"=r"(r[1]),"=r"(r[2]),"=r"(r[3]) : "r"(addr));
}
__device__ __forceinline__ void mma16816(float* d, const uint32_t* a, const uint32_t* b){
    asm volatile("mma.sync.aligned.m16n8k16.row.col.f32.f16.f16.f32 "
        "{%0,%1,%2,%3},{%4,%5,%6,%7},{%8,%9},{%0,%1,%2,%3};"
        : "+f"(d[0]),"+f"(d[1]),"+f"(d[2]),"+f"(d[3])
        : "r"(a[0]),"r"(a[1]),"r"(a[2]),"r"(a[3]),"r"(b[0]),"r"(b[1]));
}
__device__ __forceinline__ float gelu_f(float x){
    float t = tanhf(0.7978845608028654f*(x + 0.044715f*x*x*x));
    return 0.5f*x*(1.0f+t);
}
__device__ __forceinline__ void cvt2(float2 v, __half* H, size_t idx){
    *reinterpret_cast<__half2*>(H+idx) =
        __halves2half2(__float2half_rn(v.x), __float2half_rn(v.y));
}

// ---- W[L][K][N] fp32 -> [N][K] fp16 (transpose) ----
__global__ void wsplit(const float* __restrict__ W, __half* __restrict__ out,
                       int K, int N, size_t sOut)
{
    __shared__ float t[32][33];
    const int l = blockIdx.z;
    const int n0 = blockIdx.x<<5, k0 = blockIdx.y<<5;
    const int tx = threadIdx.x, ty = threadIdx.y;
    const float* Wl = W + (size_t)l*K*N;
    #pragma unroll
    for (int j=0;j<4;j++) t[ty+8*j][tx] = Wl[(size_t)(k0+ty+8*j)*N + n0+tx];
    __syncthreads();
    __half* hi = out + (size_t)l*sOut;
    #pragma unroll
    for (int j=0;j<4;j++)
        hi[(size_t)(n0+ty+8*j)*K + k0+tx] = __float2half_rn(t[tx][ty+8*j]);
}

// ---- fp32 -> fp16 convert (init only) ----
__global__ __launch_bounds__(256) void aconv(const float* __restrict__ X, __half* __restrict__ H)
{
    int i = blockIdx.x*256 + threadIdx.x;
    float4 a = reinterpret_cast<const float4*>(X)[i];
    cvt2(make_float2(a.x,a.y), H, (size_t)i*4);
    cvt2(make_float2(a.z,a.w), H, (size_t)i*4+2);
}

// ---- mma.sync GEMM: C[MxN] = Ah[MxK] * Bh[N][K]^T ; single-pass fp16, 3-stage cp.async ----
// EPI: 0 store, 1 gelu, 2 +=, 3 C += gate[col]*acc ; SPLIT: emit fp16 copy (EPI1: only fp16)
#define STAGE_ 32768
#define SMEMG (3*STAGE_)
template<int EPI, int SPLIT>
__global__ __launch_bounds__(256,2) void mmagemm(const __half* __restrict__ Ah,
        const __half* __restrict__ Bh,
        float* __restrict__ C, __half* __restrict__ Hs,
        const float* __restrict__ gate, int M, int N, int K)
{
    extern __shared__ char smc[];
    const uint32_t sb = smem_to_u32(smc);
    const int tid = threadIdx.x, wid = tid>>5, lane = tid&31;
    const int n0 = blockIdx.x<<7, m0 = blockIdx.y<<7;
    const int mw = wid>>1, nw = wid&1;

    float acc[2][8][4];
    #pragma unroll
    for (int i=0;i<2;i++)
        #pragma unroll
        for (int j=0;j<8;j++)
            #pragma unroll
            for (int q=0;q<4;q++) acc[i][j][q]=0.f;

    const int NC = K>>6;
    auto issue = [&](int c){
        const int s = c%3, kc = c<<6;
        const uint32_t sbase = sb + s*STAGE_;
        #pragma unroll
        for (int it=0; it<4; it++){
            int u = (it<<8) + tid;
            int r = u>>3, c16 = u&7;
            uint32_t dst = sbase + SWZ((uint32_t)(r*128 + c16*16));
            CPA16(dst,         Ah + (size_t)(m0+r)*K + kc + (c16<<3));
            CPA16(dst + 16384, Bh + (size_t)(n0+r)*K + kc + (c16<<3));
        }
        CPA_COMMIT();
    };
    issue(0);
    if (NC>1) issue(1);
    for (int c=0; c<NC; c++){
        if (c+1 < NC) asm volatile("cp.async.wait_group 1;");
        else          asm volatile("cp.async.wait_group 0;");
        __syncthreads();
        const uint32_t sbase = sb + (c%3)*STAGE_;
        #pragma unroll
        for (int ks=0; ks<4; ks++){
            uint32_t ah[2][4];
            #pragma unroll
            for (int ma=0; ma<2; ma++){
                int row = (mw<<5) + (ma<<4) + (lane&15);
                int kb  = (ks<<4) + ((lane>>4)<<3);
                ldsm4(ah[ma], sbase + SWZ((uint32_t)(row*128 + kb*2)));
            }
            #pragma unroll
            for (int np=0; np<4; np++){
                uint32_t bh[4];
                int row = (nw<<6) + (np<<4) + (lane&7) + ((lane>>4)<<3);
                int kb  = (ks<<4) + (((lane>>3)&1)<<3);
                ldsm4(bh, sbase + 16384 + SWZ((uint32_t)(row*128 + kb*2)));
                #pragma unroll
                for (int ma=0; ma<2; ma++) mma16816(acc[ma][2*np],   ah[ma], bh);
                #pragma unroll
                for (int ma=0; ma<2; ma++) mma16816(acc[ma][2*np+1], ah[ma], bh+2);
            }
        }
        __syncthreads();
        if (c+2 < NC) issue(c+2);
    }
    const int g = lane>>2, t = lane&3;
    #pragma unroll
    for (int ma=0; ma<2; ma++){
        int r0 = m0 + (mw<<5) + (ma<<4) + g;
        #pragma unroll
        for (int na=0; na<8; na++){
            int col = n0 + (nw<<6) + (na<<3) + (t<<1);
            size_t i0 = (size_t)r0*N + col;
            size_t i1 = i0 + 8*(size_t)N;
            float2 v0 = make_float2(acc[ma][na][0], acc[ma][na][1]);
            float2 v1 = make_float2(acc[ma][na][2], acc[ma][na][3]);
            if (EPI==1){
                v0.x=gelu_f(v0.x); v0.y=gelu_f(v0.y); v1.x=gelu_f(v1.x); v1.y=gelu_f(v1.y);
            } else if (EPI==2){
                float2 o0 = *reinterpret_cast<float2*>(C+i0);
                float2 o1 = *reinterpret_cast<float2*>(C+i1);
                v0.x+=o0.x; v0.y+=o0.y; v1.x+=o1.x; v1.y+=o1.y;
            } else if (EPI==3){
                float g0 = gate[col], g1 = gate[col+1];
                float2 o0 = *reinterpret_cast<float2*>(C+i0);
                float2 o1 = *reinterpret_cast<float2*>(C+i1);
                v0.x=o0.x+g0*v0.x; v0.y=o0.y+g1*v0.y;
                v1.x=o1.x+g0*v1.x; v1.y=o1.y+g1*v1.y;
            }
            if (!(EPI==1 && SPLIT)){
                *reinterpret_cast<float2*>(C+i0) = v0;
                *reinterpret_cast<float2*>(C+i1) = v1;
            }
            if (SPLIT){ cvt2(v0, Hs, i0); cvt2(v1, Hs, i1); }
        }
    }
}

// ---- LayerNorm: fp32 in -> fp16 out ----
__global__ __launch_bounds__(256) void layernorm_k(const float* __restrict__ X,
        __half* __restrict__ H, const float* __restrict__ g, const float* __restrict__ bb)
{
    __shared__ float red[256];
    const int row = blockIdx.x, tid = threadIdx.x;
    const float* x = X + (size_t)row*D_;
    float v0=x[tid], v1=x[tid+256], v2=x[tid+512];
    red[tid]=v0+v1+v2; __syncthreads();
    for (int o=128;o>0;o>>=1){ if(tid<o) red[tid]+=red[tid+o]; __syncthreads(); }
    float mean = red[0]*(1.f/768.f);
    __syncthreads();
    float d0=v0-mean, d1=v1-mean, d2=v2-mean;
    red[tid]=d0*d0+d1*d1+d2*d2; __syncthreads();
    for (int o=128;o>0;o>>=1){ if(tid<o) red[tid]+=red[tid+o]; __syncthreads(); }
    float inv = rsqrtf(red[0]*(1.f/768.f)+1e-6f);
    size_t base = (size_t)row*D_;
    #pragma unroll
    for (int p=0; p<3; p++){
        float d = (p==0)?d0:(p==1)?d1:d2;
        int o = tid + p*256;
        H[base+o] = __float2half_rn(d*inv*g[o] + bb[o]);
    }
}

// ---- RoPE ----
__global__ void rope_local_pre(const float* __restrict__ centers, const float* __restrict__ scales){
    int t=blockIdx.x, b=blockIdx.y, j=threadIdx.x;
    float gy=(t/7+0.5f)*(2.f/7.f)-1.f, gx=(t%7+0.5f)*(2.f/7.f)-1.f;
    float sc=scales[b];
    float pos=(j<16)?(centers[2*b]+sc*gy):(centers[2*b+1]+sc*gx);
    float a=pos*expf(-4.605170185988091f*(float)(j&15)*(1.f/16.f));
    int idx=(b*NTL_+t)*32+j;
    g_lsin[idx]=sinf(a); g_lcos[idx]=cosf(a);
}
__global__ void rope_scene_pre(){
    int t=blockIdx.x, j=threadIdx.x;
    float gy=(t/16+0.5f)*(2.f/16.f)-1.f, gx=(t%16+0.5f)*(2.f/16.f)-1.f;
    float pos=(j<16)?gy:gx;
    float a=pos*expf(-4.605170185988091f*(float)(j&15)*(1.f/16.f));
    g_ssin[t*32+j]=sinf(a); g_scos[t*32+j]=cosf(a);
}
__global__ void rope_apply(float* __restrict__ X, const float* __restrict__ S,
                           const float* __restrict__ C, int N, int prefix, int rs, int bi)
{
    int t=blockIdx.x, b=blockIdx.y, j=threadIdx.x, h=threadIdx.y;
    size_t so = bi ? ((size_t)t*32+j) : (((size_t)b*gridDim.x+t)*32+j);
    float s=S[so], c=C[so];
    float* xp = X + ((size_t)(b*N+prefix+t)*rs + h*64);
    float x1=xp[j], x2=xp[j+32];
    xp[j]=x1*c-x2*s; xp[j+32]=x2*c+x1*s;
}

// ---- attention: fp32 compute, fp16 output ----
#define SMA ((2*64*68 + 256*68)*4)
__global__ __launch_bounds__(256) void attn2(const float* __restrict__ Q,
     const float* __restrict__ K, const float* __restrict__ V,
     __half* __restrict__ Oh, int Nq, int Nk, int qs, int ks)
{
    extern __shared__ float smf[];
    float* qtT = smf;
    float* kvT = smf + 64*68;
    float* scT = smf + 2*64*68;
    const int q0 = blockIdx.x<<6, h = blockIdx.y, b = blockIdx.z;
    const int tid = threadIdx.x;
    const int nq = min(64, Nq - q0);
    const int ty = tid>>4, tx = tid&15;

    for (int u=tid; u<nq*16; u+=256){
        int r=u>>4, c4=(u&15)<<2;
        float4 v = *reinterpret_cast<const float4*>(Q + ((size_t)(b*Nq+q0+r)*qs + h*64 + c4));
        qtT[(c4+0)*68+r]=v.x; qtT[(c4+1)*68+r]=v.y; qtT[(c4+2)*68+r]=v.z; qtT[(c4+3)*68+r]=v.w;
    }
    for (int c0=0; c0<Nk; c0+=64){
        int nc = min(64, Nk-c0);
        __syncthreads();
        for (int u=tid; u<nc*16; u+=256){
            int r=u>>4, c4=(u&15)<<2;
            float4 v = *reinterpret_cast<const float4*>(K + ((size_t)(b*Nk+c0+r)*ks + h*64 + c4));
            kvT[(c4+0)*68+r]=v.x; kvT[(c4+1)*68+r]=v.y; kvT[(c4+2)*68+r]=v.z; kvT[(c4+3)*68+r]=v.w;
        }
        __syncthreads();
        float acc[4][4] = {};
        #pragma unroll 8
        for (int kk=0; kk<64; kk++){
            float4 qv = *reinterpret_cast<float4*>(qtT + kk*68 + (ty<<2));
            float4 kv = *reinterpret_cast<float4*>(kvT + kk*68 + (tx<<2));
            float qa[4]={qv.x,qv.y,qv.z,qv.w}, ka[4]={kv.x,kv.y,kv.z,kv.w};
            #pragma unroll
            for (int i=0;i<4;i++)
                #pragma unroll
                for (int j=0;j<4;j++) acc[i][j]+=qa[i]*ka[j];
        }
        #pragma unroll
        for (int j=0;j<4;j++){
            int kc=(tx<<2)+j;
            if (kc<nc)
                #pragma unroll
                for (int i=0;i<4;i++) scT[(c0+kc)*68+(ty<<2)+i]=acc[i][j]*0.125f;
        }
    }
    __syncthreads();
    if (tid < nq){
        float m=-1e30f;
        for (int k2=0;k2<Nk;k2++) m=fmaxf(m, scT[k2*68+tid]);
        float sum=0.f;
        for (int k2=0;k2<Nk;k2++){ float e=expf(scT[k2*68+tid]-m); scT[k2*68+tid]=e; sum+=e; }
        qtT[tid]=1.f/sum;
    }
    __syncthreads();
    float acc[4][4] = {};
    for (int c0=0; c0<Nk; c0+=64){
        int nc = min(64, Nk-c0);
        for (int u=tid; u<nc*16; u+=256){
            int r=u>>4, c4=(u&15)<<2;
            *reinterpret_cast<float4*>(kvT + r*68 + c4) =
                *reinterpret_cast<const float4*>(V + ((size_t)(b*Nk+c0+r)*ks + h*64 + c4));
        }
        __syncthreads();
        for (int k2=0;k2<nc;k2++){
            float4 p4 = *reinterpret_cast<float4*>(scT + (c0+k2)*68 + (ty<<2));
            float4 v4 = *reinterpret_cast<float4*>(kvT + k2*68 + (tx<<2));
            float pa[4]={p4.x,p4.y,p4.z,p4.w}, va[4]={v4.x,v4.y,v4.z,v4.w};
            #pragma unroll
            for (int i=0;i<4;i++)
                #pragma unroll
                for (int j=0;j<4;j++) acc[i][j]+=pa[i]*va[j];
        }
        __syncthreads();
    }
    #pragma unroll
    for (int i=0;i<4;i++){
        int qr=(ty<<2)+i;
        if (qr<nq){
            float iv=qtT[qr];
            size_t idx = (size_t)(b*Nq+q0+qr)*D_ + h*64 + (tx<<2);
            cvt2(make_float2(acc[i][0]*iv, acc[i][1]*iv), Oh, idx);
            cvt2(make_float2(acc[i][2]*iv, acc[i][3]*iv), Oh, idx+2);
        }
    }
}

// ---- scene broadcast: fp32 + fp16 ----
__global__ void bcast_scene(const float* __restrict__ st){
    int off = blockIdx.x*256 + threadIdx.x;
    float v = st[off];
    size_t i = (size_t)blockIdx.y*(NS_*D_) + off;
    g_scene[i] = v;
    g_sh[i] = __float2half_rn(v);
}

extern "C" void kernel_launch(void* const* d_in, const int* in_sizes, int n_in,
                              void* d_out, int out_size)
{
    (void)in_sizes; (void)n_in; (void)out_size;
    const float *in_local=(const float*)d_in[0], *in_centers=(const float*)d_in[1],
        *in_scales=(const float*)d_in[2], *in_scene=(const float*)d_in[3],
        *rgate=(const float*)d_in[4], *wgate=(const float*)d_in[5],
        *rWq=(const float*)d_in[6], *rWk=(const float*)d_in[7], *rWv=(const float*)d_in[8],
        *rWo=(const float*)d_in[9], *wWq=(const float*)d_in[10], *wWk=(const float*)d_in[11],
        *wWv=(const float*)d_in[12], *wWo=(const float*)d_in[13],
        *ln1g=(const float*)d_in[14], *ln1b=(const float*)d_in[15],
        *qkvW=(const float*)d_in[16], *aWo=(const float*)d_in[17],
        *ln2g=(const float*)d_in[18], *ln2b=(const float*)d_in[19],
        *mW1=(const float*)d_in[20], *mW2=(const float*)d_in[21];

    float *local,*scene,*q,*k,*v,*qkv,*lsin,*lcos,*ssin,*scos;
    __half *wt,*lh,*sh,*aoh,*hbh,*mh;
    cudaGetSymbolAddress((void**)&local,g_local); cudaGetSymbolAddress((void**)&scene,g_scene);
    cudaGetSymbolAddress((void**)&q,g_q); cudaGetSymbolAddress((void**)&k,g_k);
    cudaGetSymbolAddress((void**)&v,g_v); cudaGetSymbolAddress((void**)&qkv,g_qkv);
    cudaGetSymbolAddress((void**)&lsin,g_lsin); cudaGetSymbolAddress((void**)&lcos,g_lcos);
    cudaGetSymbolAddress((void**)&ssin,g_ssin); cudaGetSymbolAddress((void**)&scos,g_scos);
    cudaGetSymbolAddress((void**)&wt,g_wt);
    cudaGetSymbolAddress((void**)&lh,g_lh);   cudaGetSymbolAddress((void**)&sh,g_sh);
    cudaGetSymbolAddress((void**)&aoh,g_aoh); cudaGetSymbolAddress((void**)&hbh,g_hbh);
    cudaGetSymbolAddress((void**)&mh,g_mh);

    cudaFuncSetAttribute(mmagemm<0,0>, cudaFuncAttributeMaxDynamicSharedMemorySize, SMEMG);
    cudaFuncSetAttribute(mmagemm<1,1>, cudaFuncAttributeMaxDynamicSharedMemorySize, SMEMG);
    cudaFuncSetAttribute(mmagemm<2,0>, cudaFuncAttributeMaxDynamicSharedMemorySize, SMEMG);
    cudaFuncSetAttribute(mmagemm<2,1>, cudaFuncAttributeMaxDynamicSharedMemorySize, SMEMG);
    cudaFuncSetAttribute(mmagemm<3,0>, cudaFuncAttributeMaxDynamicSharedMemorySize, SMEMG);
    cudaFuncSetAttribute(mmagemm<3,1>, cudaFuncAttributeMaxDynamicSharedMemorySize, SMEMG);
    cudaFuncSetAttribute(attn2, cudaFuncAttributeMaxDynamicSharedMemorySize, SMA);

    const size_t LS = 20*DD_;
    dim3 tb(32,8);
    wsplit<<<dim3(24,24,12),tb>>>(rWq,  wt+0*DD_,  768, 768,  LS);
    wsplit<<<dim3(24,24,12),tb>>>(rWk,  wt+1*DD_,  768, 768,  LS);
    wsplit<<<dim3(24,24,12),tb>>>(rWv,  wt+2*DD_,  768, 768,  LS);
    wsplit<<<dim3(24,24,12),tb>>>(rWo,  wt+3*DD_,  768, 768,  LS);
    wsplit<<<dim3(24,24,12),tb>>>(wWq,  wt+4*DD_,  768, 768,  LS);
    wsplit<<<dim3(24,24,12),tb>>>(wWk,  wt+5*DD_,  768, 768,  LS);
    wsplit<<<dim3(24,24,12),tb>>>(wWv,  wt+6*DD_,  768, 768,  LS);
    wsplit<<<dim3(24,24,12),tb>>>(wWo,  wt+7*DD_,  768, 768,  LS);
    wsplit<<<dim3(72,24,12),tb>>>(qkvW, wt+8*DD_,  768, 2304, LS);
    wsplit<<<dim3(24,24,12),tb>>>(aWo,  wt+11*DD_, 768, 768,  LS);
    wsplit<<<dim3(96,24,12),tb>>>(mW1,  wt+12*DD_, 768, 3072, LS);
    wsplit<<<dim3(24,96,12),tb>>>(mW2,  wt+16*DD_, 3072, 768, LS);

    cudaMemcpyAsync(local, in_local, sizeof(float)*(size_t)ML_*D_, cudaMemcpyDeviceToDevice);
    bcast_scene<<<dim3(NS_*D_/256, B_),256>>>(in_scene);
    rope_local_pre<<<dim3(NTL_,B_),32>>>(in_centers, in_scales);
    rope_scene_pre<<<NS_,32>>>();
    aconv<<<ML_*D_/1024,256>>>(local, lh);

    for (int i=0;i<12;i++){
        const __half* wb = wt + (size_t)i*LS;
        // ---- READ cross-attn ----
        mmagemm<0,0><<<dim3(6,54),  256, SMEMG>>>(lh, wb+0*DD_, q, nullptr, nullptr, ML_, 768, 768);
        rope_apply<<<dim3(NTL_,B_),dim3(32,NH_)>>>(q, lsin, lcos, NL_, P_, D_, 0);
        mmagemm<0,0><<<dim3(6,256), 256, SMEMG>>>(sh, wb+1*DD_, k, nullptr, nullptr, MS_, 768, 768);
        rope_apply<<<dim3(NS_,B_),dim3(32,NH_)>>>(k, ssin, scos, NS_, 0, D_, 1);
        mmagemm<0,0><<<dim3(6,256), 256, SMEMG>>>(sh, wb+2*DD_, v, nullptr, nullptr, MS_, 768, 768);
        attn2<<<dim3(1,NH_,B_),256,SMA>>>(q,k,v, aoh, NL_, NS_, D_, D_);
        mmagemm<3,0><<<dim3(6,54),  256, SMEMG>>>(aoh, wb+3*DD_, local, nullptr, rgate+(size_t)i*D_, ML_, 768, 768);
        // ---- ViT block ----
        layernorm_k<<<ML_,256>>>(local, hbh, ln1g+(size_t)i*D_, ln1b+(size_t)i*D_);
        mmagemm<0,0><<<dim3(18,54), 256, SMEMG>>>(hbh, wb+8*DD_, qkv, nullptr, nullptr, ML_, 2304, 768);
        rope_apply<<<dim3(NTL_,B_),dim3(32,NH_)>>>(qkv,    lsin, lcos, NL_, P_, 3*D_, 0);
        rope_apply<<<dim3(NTL_,B_),dim3(32,NH_)>>>(qkv+D_, lsin, lcos, NL_, P_, 3*D_, 0);
        attn2<<<dim3(1,NH_,B_),256,SMA>>>(qkv, qkv+D_, qkv+2*D_, aoh, NL_, NL_, 3*D_, 3*D_);
        mmagemm<2,0><<<dim3(6,54),  256, SMEMG>>>(aoh, wb+11*DD_, local, nullptr, nullptr, ML_, 768, 768);
        layernorm_k<<<ML_,256>>>(local, hbh, ln2g+(size_t)i*D_, ln2b+(size_t)i*D_);
        mmagemm<1,1><<<dim3(24,54), 256, SMEMG>>>(hbh, wb+12*DD_, nullptr, mh, nullptr, ML_, 3072, 768);
        mmagemm<2,1><<<dim3(6,54),  256, SMEMG>>>(mh, wb+16*DD_, local, lh, nullptr, ML_, 768, 3072);
        // ---- WRITE cross-attn ----
        mmagemm<0,0><<<dim3(6,256), 256, SMEMG>>>(sh, wb+4*DD_, q, nullptr, nullptr, MS_, 768, 768);
        rope_apply<<<dim3(NS_,B_),dim3(32,NH_)>>>(q, ssin, scos, NS_, 0, D_, 1);
        mmagemm<0,0><<<dim3(6,54),  256, SMEMG>>>(lh, wb+5*DD_, k, nullptr, nullptr, ML_, 768, 768);
        rope_apply<<<dim3(NTL_,B_),dim3(32,NH_)>>>(k, lsin, lcos, NL_, P_, D_, 0);
        mmagemm<0,0><<<dim3(6,54),  256, SMEMG>>>(lh, wb+6*DD_, v, nullptr, nullptr, ML_, 768, 768);
        attn2<<<dim3(4,NH_,B_),256,SMA>>>(q,k,v, aoh, NS_, NL_, D_, D_);
        mmagemm<3,1><<<dim3(6,256), 256, SMEMG>>>(aoh, wb+7*DD_, scene, sh, wgate+(size_t)i*D_, MS_, 768, 768);
    }

    cudaMemcpyAsync(d_out, local, sizeof(float)*(size_t)ML_*D_, cudaMemcpyDeviceToDevice);
    cudaMemcpyAsync((float*)d_out + (size_t)ML_*D_, scene, sizeof(float)*(size_t)MS_*D_,
                    cudaMemcpyDeviceToDevice);
}

// round 9
// speedup vs baseline: 7.1847x; 1.2308x over previous
#include <cuda_runtime.h>
#include <cuda_fp16.h>
#include <cstdint>

#define D_   768
#define NH_  12
#define P_   5
#define NL_  54
#define NS_  256
#define B_   128
#define NTL_ 49
#define ML_  (B_*NL_)
#define MS_  (B_*NS_)
#define DD_  ((size_t)768*768)

__device__ float g_local[(size_t)ML_*D_];
__device__ float g_scene[(size_t)MS_*D_];
__device__ float g_lsin [B_*NTL_*32];
__device__ float g_lcos [B_*NTL_*32];
__device__ float g_ssin [NS_*32];
__device__ float g_scos [NS_*32];
__device__ __half g_wt[(size_t)12*20*DD_];
__device__ __half g_lh  [(size_t)ML_*D_];
__device__ __half g_sh  [(size_t)MS_*D_];
__device__ __half g_aoh [(size_t)MS_*D_];
__device__ __half g_hbh [(size_t)ML_*D_];
__device__ __half g_mh  [(size_t)ML_*4*D_];
__device__ __half g_qh  [(size_t)MS_*D_];
__device__ __half g_kh  [(size_t)MS_*D_];
__device__ __half g_vh  [(size_t)MS_*D_];
__device__ __half g_qkvh[(size_t)ML_*3*D_];

__device__ __forceinline__ uint32_t smem_to_u32(const void* p){
    uint32_t a;
    asm("{ .reg .u64 t; cvta.to.shared.u64 t, %1; cvt.u32.u64 %0, t; }" : "=r"(a) : "l"(p));
    return a;
}
#define SWZ(o) ((o) ^ (((o)>>3)&0x70))
#define CPA16(dst,src) asm volatile("cp.async.cg.shared.global [%0],[%1],16;"::"r"(dst),"l"(src))
#define CPA_COMMIT() asm volatile("cp.async.commit_group;")

__device__ __forceinline__ void ldsm4(uint32_t* r, uint32_t addr){
    asm volatile("ldmatrix.sync.aligned.m8n8.x4.shared.b16 {%0,%1,%2,%3},[%4];"
        : "=r"(r[0]),"=r"(r[1]),"=r"(r[2]),"=r"(r[3]) : "r"(addr));
}
__device__ __forceinline__ void ldsm4t(uint32_t* r, uint32_t addr){
    asm volatile("ldmatrix.sync.aligned.m8n8.x4.trans.shared.b16 {%0,%1,%2,%3},[%4];"
        : "=r"(r[0]),"=r"(r[1]),"=r"(r[2]),"=r"(r[3]) : "r"(addr));
}
__device__ __forceinline__ void mma16816(float* d, const uint32_t* a, const uint32_t* b){
    asm volatile("mma.sync.aligned.m16n8k16.row.col.f32.f16.f16.f32 "
        "{%0,%1,%2,%3},{%4,%5,%6,%7},{%8,%9},{%0,%1,%2,%3};"
        : "+f"(d[0]),"+f"(d[1]),"+f"(d[2]),"+f"(d[3])
        : "r"(a[0]),"r"(a[1]),"r"(a[2]),"r"(a[3]),"r"(b[0]),"r"(b[1]));
}
__device__ __forceinline__ float gelu_f(float x){
    float t = tanhf(0.7978845608028654f*(x + 0.044715f*x*x*x));
    return 0.5f*x*(1.0f+t);
}
__device__ __forceinline__ void cvt2(float2 v, __half* H, size_t idx){
    *reinterpret_cast<__half2*>(H+idx) =
        __halves2half2(__float2half_rn(v.x), __float2half_rn(v.y));
}

// ---- W[L][K][N] fp32 -> [N][K] fp16 (transpose) ----
__global__ void wsplit(const float* __restrict__ W, __half* __restrict__ out,
                       int K, int N, size_t sOut)
{
    __shared__ float t[32][33];
    const int l = blockIdx.z;
    const int n0 = blockIdx.x<<5, k0 = blockIdx.y<<5;
    const int tx = threadIdx.x, ty = threadIdx.y;
    const float* Wl = W + (size_t)l*K*N;
    #pragma unroll
    for (int j=0;j<4;j++) t[ty+8*j][tx] = Wl[(size_t)(k0+ty+8*j)*N + n0+tx];
    __syncthreads();
    __half* hi = out + (size_t)l*sOut;
    #pragma unroll
    for (int j=0;j<4;j++)
        hi[(size_t)(n0+ty+8*j)*K + k0+tx] = __float2half_rn(t[tx][ty+8*j]);
}

// ---- fp32 -> fp16 convert (init only) ----
__global__ __launch_bounds__(256) void aconv(const float* __restrict__ X, __half* __restrict__ H)
{
    int i = blockIdx.x*256 + threadIdx.x;
    float4 a = reinterpret_cast<const float4*>(X)[i];
    cvt2(make_float2(a.x,a.y), H, (size_t)i*4);
    cvt2(make_float2(a.z,a.w), H, (size_t)i*4+2);
}

// ---- mma.sync GEMM ----
// EPI: 0 store, 1 gelu, 2 +=, 3 C += gate[col]*acc
// SPLIT: 0 fp32 only, 1 fp32+fp16, 2 fp16 only
#define STAGE_ 32768
#define SMEMG (3*STAGE_)
template<int EPI, int SPLIT>
__global__ __launch_bounds__(256,2) void mmagemm(const __half* __restrict__ Ah,
        const __half* __restrict__ Bh,
        float* __restrict__ C, __half* __restrict__ Hs,
        const float* __restrict__ gate, int M, int N, int K)
{
    extern __shared__ char smc[];
    const uint32_t sb = smem_to_u32(smc);
    const int tid = threadIdx.x, wid = tid>>5, lane = tid&31;
    const int n0 = blockIdx.x<<7, m0 = blockIdx.y<<7;
    const int mw = wid>>1, nw = wid&1;

    float acc[2][8][4];
    #pragma unroll
    for (int i=0;i<2;i++)
        #pragma unroll
        for (int j=0;j<8;j++)
            #pragma unroll
            for (int q=0;q<4;q++) acc[i][j][q]=0.f;

    const int NC = K>>6;
    auto issue = [&](int c){
        const int s = c%3, kc = c<<6;
        const uint32_t sbase = sb + s*STAGE_;
        #pragma unroll
        for (int it=0; it<4; it++){
            int u = (it<<8) + tid;
            int r = u>>3, c16 = u&7;
            uint32_t dst = sbase + SWZ((uint32_t)(r*128 + c16*16));
            CPA16(dst,         Ah + (size_t)(m0+r)*K + kc + (c16<<3));
            CPA16(dst + 16384, Bh + (size_t)(n0+r)*K + kc + (c16<<3));
        }
        CPA_COMMIT();
    };
    issue(0);
    if (NC>1) issue(1);
    for (int c=0; c<NC; c++){
        if (c+1 < NC) asm volatile("cp.async.wait_group 1;");
        else          asm volatile("cp.async.wait_group 0;");
        __syncthreads();
        const uint32_t sbase = sb + (c%3)*STAGE_;
        #pragma unroll
        for (int ks=0; ks<4; ks++){
            uint32_t ah[2][4];
            #pragma unroll
            for (int ma=0; ma<2; ma++){
                int row = (mw<<5) + (ma<<4) + (lane&15);
                int kb  = (ks<<4) + ((lane>>4)<<3);
                ldsm4(ah[ma], sbase + SWZ((uint32_t)(row*128 + kb*2)));
            }
            #pragma unroll
            for (int np=0; np<4; np++){
                uint32_t bh[4];
                int row = (nw<<6) + (np<<4) + (lane&7) + ((lane>>4)<<3);
                int kb  = (ks<<4) + (((lane>>3)&1)<<3);
                ldsm4(bh, sbase + 16384 + SWZ((uint32_t)(row*128 + kb*2)));
                #pragma unroll
                for (int ma=0; ma<2; ma++) mma16816(acc[ma][2*np],   ah[ma], bh);
                #pragma unroll
                for (int ma=0; ma<2; ma++) mma16816(acc[ma][2*np+1], ah[ma], bh+2);
            }
        }
        __syncthreads();
        if (c+2 < NC) issue(c+2);
    }
    const int g = lane>>2, t = lane&3;
    #pragma unroll
    for (int ma=0; ma<2; ma++){
        int r0 = m0 + (mw<<5) + (ma<<4) + g;
        #pragma unroll
        for (int na=0; na<8; na++){
            int col = n0 + (nw<<6) + (na<<3) + (t<<1);
            size_t i0 = (size_t)r0*N + col;
            size_t i1 = i0 + 8*(size_t)N;
            float2 v0 = make_float2(acc[ma][na][0], acc[ma][na][1]);
            float2 v1 = make_float2(acc[ma][na][2], acc[ma][na][3]);
            if (EPI==1){
                v0.x=gelu_f(v0.x); v0.y=gelu_f(v0.y); v1.x=gelu_f(v1.x); v1.y=gelu_f(v1.y);
            } else if (EPI==2){
                float2 o0 = *reinterpret_cast<float2*>(C+i0);
                float2 o1 = *reinterpret_cast<float2*>(C+i1);
                v0.x+=o0.x; v0.y+=o0.y; v1.x+=o1.x; v1.y+=o1.y;
            } else if (EPI==3){
                float g0 = gate[col], g1 = gate[col+1];
                float2 o0 = *reinterpret_cast<float2*>(C+i0);
                float2 o1 = *reinterpret_cast<float2*>(C+i1);
                v0.x=o0.x+g0*v0.x; v0.y=o0.y+g1*v0.y;
                v1.x=o1.x+g0*v1.x; v1.y=o1.y+g1*v1.y;
            }
            if (SPLIT != 2){
                *reinterpret_cast<float2*>(C+i0) = v0;
                *reinterpret_cast<float2*>(C+i1) = v1;
            }
            if (SPLIT >= 1){ cvt2(v0, Hs, i0); cvt2(v1, Hs, i1); }
        }
    }
}

// ---- LayerNorm: fp32 in -> fp16 out ----
__global__ __launch_bounds__(256) void layernorm_k(const float* __restrict__ X,
        __half* __restrict__ H, const float* __restrict__ g, const float* __restrict__ bb)
{
    __shared__ float red[256];
    const int row = blockIdx.x, tid = threadIdx.x;
    const float* x = X + (size_t)row*D_;
    float v0=x[tid], v1=x[tid+256], v2=x[tid+512];
    red[tid]=v0+v1+v2; __syncthreads();
    for (int o=128;o>0;o>>=1){ if(tid<o) red[tid]+=red[tid+o]; __syncthreads(); }
    float mean = red[0]*(1.f/768.f);
    __syncthreads();
    float d0=v0-mean, d1=v1-mean, d2=v2-mean;
    red[tid]=d0*d0+d1*d1+d2*d2; __syncthreads();
    for (int o=128;o>0;o>>=1){ if(tid<o) red[tid]+=red[tid+o]; __syncthreads(); }
    float inv = rsqrtf(red[0]*(1.f/768.f)+1e-6f);
    size_t base = (size_t)row*D_;
    #pragma unroll
    for (int p=0; p<3; p++){
        float d = (p==0)?d0:(p==1)?d1:d2;
        int o = tid + p*256;
        H[base+o] = __float2half_rn(d*inv*g[o] + bb[o]);
    }
}

// ---- RoPE tables ----
__global__ void rope_local_pre(const float* __restrict__ centers, const float* __restrict__ scales){
    int t=blockIdx.x, b=blockIdx.y, j=threadIdx.x;
    float gy=(t/7+0.5f)*(2.f/7.f)-1.f, gx=(t%7+0.5f)*(2.f/7.f)-1.f;
    float sc=scales[b];
    float pos=(j<16)?(centers[2*b]+sc*gy):(centers[2*b+1]+sc*gx);
    float a=pos*expf(-4.605170185988091f*(float)(j&15)*(1.f/16.f));
    int idx=(b*NTL_+t)*32+j;
    g_lsin[idx]=sinf(a); g_lcos[idx]=cosf(a);
}
__global__ void rope_scene_pre(){
    int t=blockIdx.x, j=threadIdx.x;
    float gy=(t/16+0.5f)*(2.f/16.f)-1.f, gx=(t%16+0.5f)*(2.f/16.f)-1.f;
    float pos=(j<16)?gy:gx;
    float a=pos*expf(-4.605170185988091f*(float)(j&15)*(1.f/16.f));
    g_ssin[t*32+j]=sinf(a); g_scos[t*32+j]=cosf(a);
}

// ---- attention: fp16 mma QK/PV, fp32 softmax, fused rope ----
#define AQ_OFF  0
#define AKV_OFF 8192
#define AS_OFF  16384
#define AP_OFF  81920
#define SMATT   114688
__global__ __launch_bounds__(256,2) void attn3(
    const __half* __restrict__ Q, const __half* __restrict__ K, const __half* __restrict__ V,
    __half* __restrict__ Oh, int Nq, int Nk, int qs, int ks,
    const float* __restrict__ qS, const float* __restrict__ qC, int qpre, int qbi,
    const float* __restrict__ kS, const float* __restrict__ kC, int kpre, int kbi)
{
    extern __shared__ char smc[];
    const uint32_t sb = smem_to_u32(smc);
    float* Sm = reinterpret_cast<float*>(smc + AS_OFF);
    const int q0 = blockIdx.x<<6, h = blockIdx.y, b = blockIdx.z;
    const int tid = threadIdx.x, wid = tid>>5, lane = tid&31;
    const int mw = wid>>1, nw = wid&1;

    // load Q tile (64x64) with rope
    {
        int r = tid>>2, pj = (tid&3)<<3;
        int t = q0 + r;
        uint4 lo = make_uint4(0,0,0,0), hi = make_uint4(0,0,0,0);
        if (t < Nq){
            const __half* qp = Q + (size_t)(b*Nq+t)*qs + h*64;
            lo = *reinterpret_cast<const uint4*>(qp + pj);
            hi = *reinterpret_cast<const uint4*>(qp + pj + 32);
            if (t >= qpre){
                int so = (qbi ? t*32 : (b*NTL_ + (t-qpre))*32) + pj;
                __half2* l2 = reinterpret_cast<__half2*>(&lo);
                __half2* h2 = reinterpret_cast<__half2*>(&hi);
                #pragma unroll
                for (int jj=0;jj<4;jj++){
                    float2 x1 = __half22float2(l2[jj]);
                    float2 x2 = __half22float2(h2[jj]);
                    float s0=qS[so+2*jj], c0=qC[so+2*jj];
                    float s1=qS[so+2*jj+1], c1=qC[so+2*jj+1];
                    l2[jj] = __floats2half2_rn(x1.x*c0-x2.x*s0, x1.y*c1-x2.y*s1);
                    h2[jj] = __floats2half2_rn(x2.x*c0+x1.x*s0, x2.y*c1+x1.y*s1);
                }
            }
        }
        *reinterpret_cast<uint4*>(smc + AQ_OFF + SWZ(r*128 + pj*2)) = lo;
        *reinterpret_cast<uint4*>(smc + AQ_OFF + SWZ(r*128 + pj*2 + 64)) = hi;
    }

    const int NC = (Nk + 63) >> 6;
    // pass 1: S = Q K^T * scale
    for (int c=0;c<NC;c++){
        int c0 = c<<6;
        __syncthreads();
        {   // load K chunk with rope
            int r = tid>>2, pj = (tid&3)<<3;
            int t = c0 + r;
            uint4 lo = make_uint4(0,0,0,0), hi = make_uint4(0,0,0,0);
            if (t < Nk){
                const __half* kp = K + (size_t)(b*Nk+t)*ks + h*64;
                lo = *reinterpret_cast<const uint4*>(kp + pj);
                hi = *reinterpret_cast<const uint4*>(kp + pj + 32);
                if (t >= kpre){
                    int so = (kbi ? t*32 : (b*NTL_ + (t-kpre))*32) + pj;
                    __half2* l2 = reinterpret_cast<__half2*>(&lo);
                    __half2* h2 = reinterpret_cast<__half2*>(&hi);
                    #pragma unroll
                    for (int jj=0;jj<4;jj++){
                        float2 x1 = __half22float2(l2[jj]);
                        float2 x2 = __half22float2(h2[jj]);
                        float s0=kS[so+2*jj], c0f=kC[so+2*jj];
                        float s1=kS[so+2*jj+1], c1f=kC[so+2*jj+1];
                        l2[jj] = __floats2half2_rn(x1.x*c0f-x2.x*s0, x1.y*c1f-x2.y*s1);
                        h2[jj] = __floats2half2_rn(x2.x*c0f+x1.x*s0, x2.y*c1f+x1.y*s1);
                    }
                }
            }
            *reinterpret_cast<uint4*>(smc + AKV_OFF + SWZ(r*128 + pj*2)) = lo;
            *reinterpret_cast<uint4*>(smc + AKV_OFF + SWZ(r*128 + pj*2 + 64)) = hi;
        }
        __syncthreads();
        float acc[4][4] = {};
        #pragma unroll
        for (int ks_=0;ks_<4;ks_++){
            uint32_t af[4];
            ldsm4(af, sb + AQ_OFF + SWZ(((mw<<4)+(lane&15))*128 + ((ks_<<4)+((lane>>4)<<3))*2));
            #pragma unroll
            for (int np=0;np<2;np++){
                uint32_t bf[4];
                int krow = (nw<<5)+(np<<4)+(lane&7)+((lane>>4)<<3);
                ldsm4(bf, sb + AKV_OFF + SWZ(krow*128 + ((ks_<<4)+(((lane>>3)&1)<<3))*2));
                mma16816(acc[2*np],   af, bf);
                mma16816(acc[2*np+1], af, bf+2);
            }
        }
        int g = lane>>2, tq = lane&3;
        #pragma unroll
        for (int j=0;j<4;j++){
            int col = c0 + (nw<<5) + ((j>>1)<<4) + ((j&1)<<3) + (tq<<1);
            int r0 = (mw<<4)+g;
            float* s0 = Sm + r0*256 + col;
            s0[0]=acc[j][0]*0.125f; s0[1]=acc[j][1]*0.125f;
            float* s1 = s0 + 8*256;
            s1[0]=acc[j][2]*0.125f; s1[1]=acc[j][3]*0.125f;
        }
    }
    __syncthreads();

    // softmax rows, write P fp16 (swizzled)
    {
        int Nkp = NC<<6;
        for (int rr=0;rr<8;rr++){
            int row = (wid<<3)+rr;
            float* Srow = Sm + row*256;
            float m = -1e30f;
            for (int i=lane;i<Nk;i+=32) m = fmaxf(m, Srow[i]);
            #pragma unroll
            for (int o=16;o>0;o>>=1) m = fmaxf(m, __shfl_xor_sync(0xffffffffu, m, o));
            float sum = 0.f;
            for (int i=lane;i<Nk;i+=32){ float e = expf(Srow[i]-m); Srow[i]=e; sum+=e; }
            #pragma unroll
            for (int o=16;o>0;o>>=1) sum += __shfl_xor_sync(0xffffffffu, sum, o);
            float inv = 1.f/sum;
            for (int i=lane;i<Nkp;i+=32){
                __half p = (i<Nk) ? __float2half_rn(Srow[i]*inv) : __float2half_rn(0.f);
                *reinterpret_cast<__half*>(smc + AP_OFF + row*512 +
                    ((((i>>3)^(row&7)))<<4) + ((i&7)<<1)) = p;
            }
        }
    }

    // pass 2: O = P V
    float oacc[4][4] = {};
    for (int c=0;c<NC;c++){
        int c0 = c<<6;
        __syncthreads();
        {   // load V chunk
            int r = tid>>2, pj = (tid&3)<<3;
            int t = c0 + r;
            uint4 lo = make_uint4(0,0,0,0), hi = make_uint4(0,0,0,0);
            if (t < Nk){
                const __half* vp = V + (size_t)(b*Nk+t)*ks + h*64;
                lo = *reinterpret_cast<const uint4*>(vp + pj);
                hi = *reinterpret_cast<const uint4*>(vp + pj + 32);
            }
            *reinterpret_cast<uint4*>(smc + AKV_OFF + SWZ(r*128 + pj*2)) = lo;
            *reinterpret_cast<uint4*>(smc + AKV_OFF + SWZ(r*128 + pj*2 + 64)) = hi;
        }
        __syncthreads();
        #pragma unroll
        for (int ks_=0;ks_<4;ks_++){
            uint32_t af[4];
            int prow = (mw<<4)+(lane&15);
            int pcol = c0 + (ks_<<4) + ((lane>>4)<<3);
            ldsm4(af, sb + AP_OFF + prow*512 + (((pcol>>3)^(prow&7))<<4));
            #pragma unroll
            for (int np=0;np<2;np++){
                uint32_t bf[4];
                int vrow = (ks_<<4) + (((lane>>3)&1)<<3) + (lane&7);
                int vcol = (nw<<5) + (np<<4) + ((lane>>4)<<3);
                ldsm4t(bf, sb + AKV_OFF + SWZ(vrow*128 + vcol*2));
                mma16816(oacc[2*np],   af, bf);
                mma16816(oacc[2*np+1], af, bf+2);
            }
        }
    }
    // output
    {
        int g = lane>>2, tq = lane&3;
        #pragma unroll
        for (int j=0;j<4;j++){
            int col = (nw<<5)+((j>>1)<<4)+((j&1)<<3)+(tq<<1);
            int r0 = (mw<<4)+g;
            if (q0+r0 < Nq){
                size_t i0 = (size_t)(b*Nq + q0 + r0)*D_ + h*64 + col;
                *reinterpret_cast<__half2*>(Oh+i0) = __floats2half2_rn(oacc[j][0], oacc[j][1]);
            }
            if (q0+r0+8 < Nq){
                size_t i1 = (size_t)(b*Nq + q0 + r0 + 8)*D_ + h*64 + col;
                *reinterpret_cast<__half2*>(Oh+i1) = __floats2half2_rn(oacc[j][2], oacc[j][3]);
            }
        }
    }
}

// ---- scene broadcast: fp32 + fp16 ----
__global__ void bcast_scene(const float* __restrict__ st){
    int off = blockIdx.x*256 + threadIdx.x;
    float v = st[off];
    size_t i = (size_t)blockIdx.y*(NS_*D_) + off;
    g_scene[i] = v;
    g_sh[i] = __float2half_rn(v);
}

extern "C" void kernel_launch(void* const* d_in, const int* in_sizes, int n_in,
                              void* d_out, int out_size)
{
    (void)in_sizes; (void)n_in; (void)out_size;
    const float *in_local=(const float*)d_in[0], *in_centers=(const float*)d_in[1],
        *in_scales=(const float*)d_in[2], *in_scene=(const float*)d_in[3],
        *rgate=(const float*)d_in[4], *wgate=(const float*)d_in[5],
        *rWq=(const float*)d_in[6], *rWk=(const float*)d_in[7], *rWv=(const float*)d_in[8],
        *rWo=(const float*)d_in[9], *wWq=(const float*)d_in[10], *wWk=(const float*)d_in[11],
        *wWv=(const float*)d_in[12], *wWo=(const float*)d_in[13],
        *ln1g=(const float*)d_in[14], *ln1b=(const float*)d_in[15],
        *qkvW=(const float*)d_in[16], *aWo=(const float*)d_in[17],
        *ln2g=(const float*)d_in[18], *ln2b=(const float*)d_in[19],
        *mW1=(const float*)d_in[20], *mW2=(const float*)d_in[21];

    float *local,*scene,*lsin,*lcos,*ssin,*scos;
    __half *wt,*lh,*sh,*aoh,*hbh,*mh,*qh,*kh,*vh,*qkvh;
    cudaGetSymbolAddress((void**)&local,g_local); cudaGetSymbolAddress((void**)&scene,g_scene);
    cudaGetSymbolAddress((void**)&lsin,g_lsin); cudaGetSymbolAddress((void**)&lcos,g_lcos);
    cudaGetSymbolAddress((void**)&ssin,g_ssin); cudaGetSymbolAddress((void**)&scos,g_scos);
    cudaGetSymbolAddress((void**)&wt,g_wt);
    cudaGetSymbolAddress((void**)&lh,g_lh);   cudaGetSymbolAddress((void**)&sh,g_sh);
    cudaGetSymbolAddress((void**)&aoh,g_aoh); cudaGetSymbolAddress((void**)&hbh,g_hbh);
    cudaGetSymbolAddress((void**)&mh,g_mh);
    cudaGetSymbolAddress((void**)&qh,g_qh);   cudaGetSymbolAddress((void**)&kh,g_kh);
    cudaGetSymbolAddress((void**)&vh,g_vh);   cudaGetSymbolAddress((void**)&qkvh,g_qkvh);

    cudaFuncSetAttribute(mmagemm<0,2>, cudaFuncAttributeMaxDynamicSharedMemorySize, SMEMG);
    cudaFuncSetAttribute(mmagemm<1,2>, cudaFuncAttributeMaxDynamicSharedMemorySize, SMEMG);
    cudaFuncSetAttribute(mmagemm<2,0>, cudaFuncAttributeMaxDynamicSharedMemorySize, SMEMG);
    cudaFuncSetAttribute(mmagemm<2,1>, cudaFuncAttributeMaxDynamicSharedMemorySize, SMEMG);
    cudaFuncSetAttribute(mmagemm<3,0>, cudaFuncAttributeMaxDynamicSharedMemorySize, SMEMG);
    cudaFuncSetAttribute(mmagemm<3,1>, cudaFuncAttributeMaxDynamicSharedMemorySize, SMEMG);
    cudaFuncSetAttribute(attn3, cudaFuncAttributeMaxDynamicSharedMemorySize, SMATT);

    const size_t LS = 20*DD_;
    dim3 tb(32,8);
    wsplit<<<dim3(24,24,12),tb>>>(rWq,  wt+0*DD_,  768, 768,  LS);
    wsplit<<<dim3(24,24,12),tb>>>(rWk,  wt+1*DD_,  768, 768,  LS);
    wsplit<<<dim3(24,24,12),tb>>>(rWv,  wt+2*DD_,  768, 768,  LS);
    wsplit<<<dim3(24,24,12),tb>>>(rWo,  wt+3*DD_,  768, 768,  LS);
    wsplit<<<dim3(24,24,12),tb>>>(wWq,  wt+4*DD_,  768, 768,  LS);
    wsplit<<<dim3(24,24,12),tb>>>(wWk,  wt+5*DD_,  768, 768,  LS);
    wsplit<<<dim3(24,24,12),tb>>>(wWv,  wt+6*DD_,  768, 768,  LS);
    wsplit<<<dim3(24,24,12),tb>>>(wWo,  wt+7*DD_,  768, 768,  LS);
    wsplit<<<dim3(72,24,12),tb>>>(qkvW, wt+8*DD_,  768, 2304, LS);
    wsplit<<<dim3(24,24,12),tb>>>(aWo,  wt+11*DD_, 768, 768,  LS);
    wsplit<<<dim3(96,24,12),tb>>>(mW1,  wt+12*DD_, 768, 3072, LS);
    wsplit<<<dim3(24,96,12),tb>>>(mW2,  wt+16*DD_, 3072, 768, LS);

    cudaMemcpyAsync(local, in_local, sizeof(float)*(size_t)ML_*D_, cudaMemcpyDeviceToDevice);
    bcast_scene<<<dim3(NS_*D_/256, B_),256>>>(in_scene);
    rope_local_pre<<<dim3(NTL_,B_),32>>>(in_centers, in_scales);
    rope_scene_pre<<<NS_,32>>>();
    aconv<<<ML_*D_/1024,256>>>(local, lh);

    for (int i=0;i<12;i++){
        const __half* wb = wt + (size_t)i*LS;
        // ---- READ cross-attn ----
        mmagemm<0,2><<<dim3(6,54),  256, SMEMG>>>(lh, wb+0*DD_, nullptr, qh, nullptr, ML_, 768, 768);
        mmagemm<0,2><<<dim3(6,256), 256, SMEMG>>>(sh, wb+1*DD_, nullptr, kh, nullptr, MS_, 768, 768);
        mmagemm<0,2><<<dim3(6,256), 256, SMEMG>>>(sh, wb+2*DD_, nullptr, vh, nullptr, MS_, 768, 768);
        attn3<<<dim3(1,NH_,B_),256,SMATT>>>(qh,kh,vh, aoh, NL_, NS_, 768, 768,
                                            lsin,lcos,P_,0, ssin,scos,0,1);
        mmagemm<3,0><<<dim3(6,54),  256, SMEMG>>>(aoh, wb+3*DD_, local, nullptr, rgate+(size_t)i*D_, ML_, 768, 768);
        // ---- ViT block ----
        layernorm_k<<<ML_,256>>>(local, hbh, ln1g+(size_t)i*D_, ln1b+(size_t)i*D_);
        mmagemm<0,2><<<dim3(18,54), 256, SMEMG>>>(hbh, wb+8*DD_, nullptr, qkvh, nullptr, ML_, 2304, 768);
        attn3<<<dim3(1,NH_,B_),256,SMATT>>>(qkvh, qkvh+768, qkvh+1536, aoh, NL_, NL_, 2304, 2304,
                                            lsin,lcos,P_,0, lsin,lcos,P_,0);
        mmagemm<2,0><<<dim3(6,54),  256, SMEMG>>>(aoh, wb+11*DD_, local, nullptr, nullptr, ML_, 768, 768);
        layernorm_k<<<ML_,256>>>(local, hbh, ln2g+(size_t)i*D_, ln2b+(size_t)i*D_);
        mmagemm<1,2><<<dim3(24,54), 256, SMEMG>>>(hbh, wb+12*DD_, nullptr, mh, nullptr, ML_, 3072, 768);
        mmagemm<2,1><<<dim3(6,54),  256, SMEMG>>>(mh, wb+16*DD_, local, lh, nullptr, ML_, 768, 3072);
        // ---- WRITE cross-attn ----
        mmagemm<0,2><<<dim3(6,256), 256, SMEMG>>>(sh, wb+4*DD_, nullptr, qh, nullptr, MS_, 768, 768);
        mmagemm<0,2><<<dim3(6,54),  256, SMEMG>>>(lh, wb+5*DD_, nullptr, kh, nullptr, ML_, 768, 768);
        mmagemm<0,2><<<dim3(6,54),  256, SMEMG>>>(lh, wb+6*DD_, nullptr, vh, nullptr, ML_, 768, 768);
        attn3<<<dim3(4,NH_,B_),256,SMATT>>>(qh,kh,vh, aoh, NS_, NL_, 768, 768,
                                            ssin,scos,0,1, lsin,lcos,P_,0);
        mmagemm<3,1><<<dim3(6,256), 256, SMEMG>>>(aoh, wb+7*DD_, scene, sh, wgate+(size_t)i*D_, MS_, 768, 768);
    }

    cudaMemcpyAsync(d_out, local, sizeof(float)*(size_t)ML_*D_, cudaMemcpyDeviceToDevice);
    cudaMemcpyAsync((float*)d_out + (size_t)ML_*D_, scene, sizeof(float)*(size_t)MS_*D_,
                    cudaMemcpyDeviceToDevice);
}

// round 10
// speedup vs baseline: 7.3595x; 1.0243x over previous
#include <cuda_runtime.h>
#include <cuda_fp16.h>
#include <cstdint>

#define D_   768
#define NH_  12
#define P_   5
#define NL_  54
#define NS_  256
#define B_   128
#define NTL_ 49
#define ML_  (B_*NL_)
#define MS_  (B_*NS_)
#define DD_  ((size_t)768*768)

__device__ float g_local[(size_t)ML_*D_];
__device__ float g_scene[(size_t)MS_*D_];
__device__ float g_lsin [B_*NTL_*32];
__device__ float g_lcos [B_*NTL_*32];
__device__ float g_ssin [NS_*32];
__device__ float g_scos [NS_*32];
__device__ __half g_wt[(size_t)12*20*DD_];
__device__ __half g_lh  [(size_t)ML_*D_];
__device__ __half g_sh  [(size_t)MS_*D_];
__device__ __half g_aoh [(size_t)MS_*D_];
__device__ __half g_hbh [(size_t)ML_*D_];
__device__ __half g_mh  [(size_t)ML_*4*D_];
__device__ __half g_qh  [(size_t)MS_*D_];
__device__ __half g_kvh [(size_t)MS_*2*D_];
__device__ __half g_qkvh[(size_t)ML_*3*D_];

__device__ __forceinline__ uint32_t smem_to_u32(const void* p){
    uint32_t a;
    asm("{ .reg .u64 t; cvta.to.shared.u64 t, %1; cvt.u32.u64 %0, t; }" : "=r"(a) : "l"(p));
    return a;
}
#define SWZ(o) ((o) ^ (((o)>>3)&0x70))
#define CPA16(dst,src) asm volatile("cp.async.cg.shared.global [%0],[%1],16;"::"r"(dst),"l"(src))
#define CPA_COMMIT() asm volatile("cp.async.commit_group;")

__device__ __forceinline__ void ldsm4(uint32_t* r, uint32_t addr){
    asm volatile("ldmatrix.sync.aligned.m8n8.x4.shared.b16 {%0,%1,%2,%3},[%4];"
        : "=r"(r[0]),"=r"(r[1]),"=r"(r[2]),"=r"(r[3]) : "r"(addr));
}
__device__ __forceinline__ void ldsm4t(uint32_t* r, uint32_t addr){
    asm volatile("ldmatrix.sync.aligned.m8n8.x4.trans.shared.b16 {%0,%1,%2,%3},[%4];"
        : "=r"(r[0]),"=r"(r[1]),"=r"(r[2]),"=r"(r[3]) : "r"(addr));
}
__device__ __forceinline__ void mma16816(float* d, const uint32_t* a, const uint32_t* b){
    asm volatile("mma.sync.aligned.m16n8k16.row.col.f32.f16.f16.f32 "
        "{%0,%1,%2,%3},{%4,%5,%6,%7},{%8,%9},{%0,%1,%2,%3};"
        : "+f"(d[0]),"+f"(d[1]),"+f"(d[2]),"+f"(d[3])
        : "r"(a[0]),"r"(a[1]),"r"(a[2]),"r"(a[3]),"r"(b[0]),"r"(b[1]));
}
__device__ __forceinline__ float gelu_f(float x){
    float t = tanhf(0.7978845608028654f*(x + 0.044715f*x*x*x));
    return 0.5f*x*(1.0f+t);
}
__device__ __forceinline__ void cvt2(float2 v, __half* H, size_t idx){
    *reinterpret_cast<__half2*>(H+idx) =
        __halves2half2(__float2half_rn(v.x), __float2half_rn(v.y));
}

// ---- W[L][K][N] fp32 -> [N][K] fp16 (transpose) ----
__global__ void wsplit(const float* __restrict__ W, __half* __restrict__ out,
                       int K, int N, size_t sOut)
{
    __shared__ float t[32][33];
    const int l = blockIdx.z;
    const int n0 = blockIdx.x<<5, k0 = blockIdx.y<<5;
    const int tx = threadIdx.x, ty = threadIdx.y;
    const float* Wl = W + (size_t)l*K*N;
    #pragma unroll
    for (int j=0;j<4;j++) t[ty+8*j][tx] = Wl[(size_t)(k0+ty+8*j)*N + n0+tx];
    __syncthreads();
    __half* hi = out + (size_t)l*sOut;
    #pragma unroll
    for (int j=0;j<4;j++)
        hi[(size_t)(n0+ty+8*j)*K + k0+tx] = __float2half_rn(t[tx][ty+8*j]);
}

// ---- fp32 -> fp16 convert (init only) ----
__global__ __launch_bounds__(256) void aconv(const float* __restrict__ X, __half* __restrict__ H)
{
    int i = blockIdx.x*256 + threadIdx.x;
    float4 a = reinterpret_cast<const float4*>(X)[i];
    cvt2(make_float2(a.x,a.y), H, (size_t)i*4);
    cvt2(make_float2(a.z,a.w), H, (size_t)i*4+2);
}

// ---- mma.sync GEMM ----
// EPI: 0 store, 1 gelu, 2 +=, 3 C += gate[col]*acc
// SPLIT: 0 fp32 only, 1 fp32+fp16, 2 fp16 only
#define STAGE_ 32768
#define SMEMG (3*STAGE_)
template<int EPI, int SPLIT>
__global__ __launch_bounds__(256,2) void mmagemm(const __half* __restrict__ Ah,
        const __half* __restrict__ Bh,
        float* __restrict__ C, __half* __restrict__ Hs,
        const float* __restrict__ gate, int M, int N, int K)
{
    extern __shared__ char smc[];
    const uint32_t sb = smem_to_u32(smc);
    const int tid = threadIdx.x, wid = tid>>5, lane = tid&31;
    const int n0 = blockIdx.x<<7, m0 = blockIdx.y<<7;
    const int mw = wid>>1, nw = wid&1;

    float acc[2][8][4];
    #pragma unroll
    for (int i=0;i<2;i++)
        #pragma unroll
        for (int j=0;j<8;j++)
            #pragma unroll
            for (int q=0;q<4;q++) acc[i][j][q]=0.f;

    const int NC = K>>6;
    auto issue = [&](int c){
        const int s = c%3, kc = c<<6;
        const uint32_t sbase = sb + s*STAGE_;
        #pragma unroll
        for (int it=0; it<4; it++){
            int u = (it<<8) + tid;
            int r = u>>3, c16 = u&7;
            uint32_t dst = sbase + SWZ((uint32_t)(r*128 + c16*16));
            CPA16(dst,         Ah + (size_t)(m0+r)*K + kc + (c16<<3));
            CPA16(dst + 16384, Bh + (size_t)(n0+r)*K + kc + (c16<<3));
        }
        CPA_COMMIT();
    };
    issue(0);
    if (NC>1) issue(1);
    for (int c=0; c<NC; c++){
        if (c+1 < NC) asm volatile("cp.async.wait_group 1;");
        else          asm volatile("cp.async.wait_group 0;");
        __syncthreads();
        if (c+2 < NC) issue(c+2);           // overlaps with MMA below; stage safe (read finished pre-sync)
        const uint32_t sbase = sb + (c%3)*STAGE_;
        #pragma unroll
        for (int ks=0; ks<4; ks++){
            uint32_t ah[2][4];
            #pragma unroll
            for (int ma=0; ma<2; ma++){
                int row = (mw<<5) + (ma<<4) + (lane&15);
                int kb  = (ks<<4) + ((lane>>4)<<3);
                ldsm4(ah[ma], sbase + SWZ((uint32_t)(row*128 + kb*2)));
            }
            #pragma unroll
            for (int np=0; np<4; np++){
                uint32_t bh[4];
                int row = (nw<<6) + (np<<4) + (lane&7) + ((lane>>4)<<3);
                int kb  = (ks<<4) + (((lane>>3)&1)<<3);
                ldsm4(bh, sbase + 16384 + SWZ((uint32_t)(row*128 + kb*2)));
                #pragma unroll
                for (int ma=0; ma<2; ma++) mma16816(acc[ma][2*np],   ah[ma], bh);
                #pragma unroll
                for (int ma=0; ma<2; ma++) mma16816(acc[ma][2*np+1], ah[ma], bh+2);
            }
        }
    }
    const int g = lane>>2, t = lane&3;
    #pragma unroll
    for (int ma=0; ma<2; ma++){
        int r0 = m0 + (mw<<5) + (ma<<4) + g;
        #pragma unroll
        for (int na=0; na<8; na++){
            int col = n0 + (nw<<6) + (na<<3) + (t<<1);
            size_t i0 = (size_t)r0*N + col;
            size_t i1 = i0 + 8*(size_t)N;
            float2 v0 = make_float2(acc[ma][na][0], acc[ma][na][1]);
            float2 v1 = make_float2(acc[ma][na][2], acc[ma][na][3]);
            if (EPI==1){
                v0.x=gelu_f(v0.x); v0.y=gelu_f(v0.y); v1.x=gelu_f(v1.x); v1.y=gelu_f(v1.y);
            } else if (EPI==2){
                float2 o0 = *reinterpret_cast<float2*>(C+i0);
                float2 o1 = *reinterpret_cast<float2*>(C+i1);
                v0.x+=o0.x; v0.y+=o0.y; v1.x+=o1.x; v1.y+=o1.y;
            } else if (EPI==3){
                float g0 = gate[col], g1 = gate[col+1];
                float2 o0 = *reinterpret_cast<float2*>(C+i0);
                float2 o1 = *reinterpret_cast<float2*>(C+i1);
                v0.x=o0.x+g0*v0.x; v0.y=o0.y+g1*v0.y;
                v1.x=o1.x+g0*v1.x; v1.y=o1.y+g1*v1.y;
            }
            if (SPLIT != 2){
                *reinterpret_cast<float2*>(C+i0) = v0;
                *reinterpret_cast<float2*>(C+i1) = v1;
            }
            if (SPLIT >= 1){ cvt2(v0, Hs, i0); cvt2(v1, Hs, i1); }
        }
    }
}

// ---- LayerNorm: fp32 in -> fp16 out (shuffle reductions) ----
__global__ __launch_bounds__(256) void layernorm_k(const float* __restrict__ X,
        __half* __restrict__ H, const float* __restrict__ g, const float* __restrict__ bb)
{
    __shared__ float red[8], red2[8];
    const int row = blockIdx.x, tid = threadIdx.x, lane = tid&31, wid = tid>>5;
    const float* x = X + (size_t)row*D_;
    float v0=x[tid], v1=x[tid+256], v2=x[tid+512];
    float s = v0+v1+v2;
    #pragma unroll
    for (int o=16;o;o>>=1) s += __shfl_xor_sync(0xffffffffu, s, o);
    if (lane==0) red[wid]=s;
    __syncthreads();
    float mean = (red[0]+red[1]+red[2]+red[3]+red[4]+red[5]+red[6]+red[7])*(1.f/768.f);
    float d0=v0-mean, d1=v1-mean, d2=v2-mean;
    float q = d0*d0+d1*d1+d2*d2;
    #pragma unroll
    for (int o=16;o;o>>=1) q += __shfl_xor_sync(0xffffffffu, q, o);
    if (lane==0) red2[wid]=q;
    __syncthreads();
    float inv = rsqrtf((red2[0]+red2[1]+red2[2]+red2[3]+red2[4]+red2[5]+red2[6]+red2[7])*(1.f/768.f)+1e-6f);
    size_t base = (size_t)row*D_;
    H[base+tid]     = __float2half_rn(d0*inv*g[tid]     + bb[tid]);
    H[base+tid+256] = __float2half_rn(d1*inv*g[tid+256] + bb[tid+256]);
    H[base+tid+512] = __float2half_rn(d2*inv*g[tid+512] + bb[tid+512]);
}

// ---- RoPE tables ----
__global__ void rope_local_pre(const float* __restrict__ centers, const float* __restrict__ scales){
    int t=blockIdx.x, b=blockIdx.y, j=threadIdx.x;
    float gy=(t/7+0.5f)*(2.f/7.f)-1.f, gx=(t%7+0.5f)*(2.f/7.f)-1.f;
    float sc=scales[b];
    float pos=(j<16)?(centers[2*b]+sc*gy):(centers[2*b+1]+sc*gx);
    float a=pos*expf(-4.605170185988091f*(float)(j&15)*(1.f/16.f));
    int idx=(b*NTL_+t)*32+j;
    g_lsin[idx]=sinf(a); g_lcos[idx]=cosf(a);
}
__global__ void rope_scene_pre(){
    int t=blockIdx.x, j=threadIdx.x;
    float gy=(t/16+0.5f)*(2.f/16.f)-1.f, gx=(t%16+0.5f)*(2.f/16.f)-1.f;
    float pos=(j<16)?gy:gx;
    float a=pos*expf(-4.605170185988091f*(float)(j&15)*(1.f/16.f));
    g_ssin[t*32+j]=sinf(a); g_scos[t*32+j]=cosf(a);
}

// ---- attention: fp16 mma QK/PV, fp32 softmax, fused rope ----
#define AQ_OFF  0
#define AKV_OFF 8192
#define AS_OFF  16384
#define AP_OFF  81920
#define SMATT   114688
__global__ __launch_bounds__(256,2) void attn3(
    const __half* __restrict__ Q, const __half* __restrict__ K, const __half* __restrict__ V,
    __half* __restrict__ Oh, int Nq, int Nk, int qs, int ks,
    const float* __restrict__ qS, const float* __restrict__ qC, int qpre, int qbi,
    const float* __restrict__ kS, const float* __restrict__ kC, int kpre, int kbi)
{
    extern __shared__ char smc[];
    const uint32_t sb = smem_to_u32(smc);
    float* Sm = reinterpret_cast<float*>(smc + AS_OFF);
    const int q0 = blockIdx.x<<6, h = blockIdx.y, b = blockIdx.z;
    const int tid = threadIdx.x, wid = tid>>5, lane = tid&31;
    const int mw = wid>>1, nw = wid&1;

    {
        int r = tid>>2, pj = (tid&3)<<3;
        int t = q0 + r;
        uint4 lo = make_uint4(0,0,0,0), hi = make_uint4(0,0,0,0);
        if (t < Nq){
            const __half* qp = Q + (size_t)(b*Nq+t)*qs + h*64;
            lo = *reinterpret_cast<const uint4*>(qp + pj);
            hi = *reinterpret_cast<const uint4*>(qp + pj + 32);
            if (t >= qpre){
                int so = (qbi ? t*32 : (b*NTL_ + (t-qpre))*32) + pj;
                __half2* l2 = reinterpret_cast<__half2*>(&lo);
                __half2* h2 = reinterpret_cast<__half2*>(&hi);
                #pragma unroll
                for (int jj=0;jj<4;jj++){
                    float2 x1 = __half22float2(l2[jj]);
                    float2 x2 = __half22float2(h2[jj]);
                    float s0=qS[so+2*jj], c0=qC[so+2*jj];
                    float s1=qS[so+2*jj+1], c1=qC[so+2*jj+1];
                    l2[jj] = __floats2half2_rn(x1.x*c0-x2.x*s0, x1.y*c1-x2.y*s1);
                    h2[jj] = __floats2half2_rn(x2.x*c0+x1.x*s0, x2.y*c1+x1.y*s1);
                }
            }
        }
        *reinterpret_cast<uint4*>(smc + AQ_OFF + SWZ(r*128 + pj*2)) = lo;
        *reinterpret_cast<uint4*>(smc + AQ_OFF + SWZ(r*128 + pj*2 + 64)) = hi;
    }

    const int NC = (Nk + 63) >> 6;
    for (int c=0;c<NC;c++){
        int c0 = c<<6;
        __syncthreads();
        {
            int r = tid>>2, pj = (tid&3)<<3;
            int t = c0 + r;
            uint4 lo = make_uint4(0,0,0,0), hi = make_uint4(0,0,0,0);
            if (t < Nk){
                const __half* kp = K + (size_t)(b*Nk+t)*ks + h*64;
                lo = *reinterpret_cast<const uint4*>(kp + pj);
                hi = *reinterpret_cast<const uint4*>(kp + pj + 32);
                if (t >= kpre){
                    int so = (kbi ? t*32 : (b*NTL_ + (t-kpre))*32) + pj;
                    __half2* l2 = reinterpret_cast<__half2*>(&lo);
                    __half2* h2 = reinterpret_cast<__half2*>(&hi);
                    #pragma unroll
                    for (int jj=0;jj<4;jj++){
                        float2 x1 = __half22float2(l2[jj]);
                        float2 x2 = __half22float2(h2[jj]);
                        float s0=kS[so+2*jj], c0f=kC[so+2*jj];
                        float s1=kS[so+2*jj+1], c1f=kC[so+2*jj+1];
                        l2[jj] = __floats2half2_rn(x1.x*c0f-x2.x*s0, x1.y*c1f-x2.y*s1);
                        h2[jj] = __floats2half2_rn(x2.x*c0f+x1.x*s0, x2.y*c1f+x1.y*s1);
                    }
                }
            }
            *reinterpret_cast<uint4*>(smc + AKV_OFF + SWZ(r*128 + pj*2)) = lo;
            *reinterpret_cast<uint4*>(smc + AKV_OFF + SWZ(r*128 + pj*2 + 64)) = hi;
        }
        __syncthreads();
        float acc[4][4] = {};
        #pragma unroll
        for (int ks_=0;ks_<4;ks_++){
            uint32_t af[4];
            ldsm4(af, sb + AQ_OFF + SWZ(((mw<<4)+(lane&15))*128 + ((ks_<<4)+((lane>>4)<<3))*2));
            #pragma unroll
            for (int np=0;np<2;np++){
                uint32_t bf[4];
                int krow = (nw<<5)+(np<<4)+(lane&7)+((lane>>4)<<3);
                ldsm4(bf, sb + AKV_OFF + SWZ(krow*128 + ((ks_<<4)+(((lane>>3)&1)<<3))*2));
                mma16816(acc[2*np],   af, bf);
                mma16816(acc[2*np+1], af, bf+2);
            }
        }
        int g = lane>>2, tq = lane&3;
        #pragma unroll
        for (int j=0;j<4;j++){
            int col = c0 + (nw<<5) + ((j>>1)<<4) + ((j&1)<<3) + (tq<<1);
            int r0 = (mw<<4)+g;
            float* s0 = Sm + r0*256 + col;
            s0[0]=acc[j][0]*0.125f; s0[1]=acc[j][1]*0.125f;
            float* s1 = s0 + 8*256;
            s1[0]=acc[j][2]*0.125f; s1[1]=acc[j][3]*0.125f;
        }
    }
    __syncthreads();

    {
        int Nkp = NC<<6;
        for (int rr=0;rr<8;rr++){
            int row = (wid<<3)+rr;
            float* Srow = Sm + row*256;
            float m = -1e30f;
            for (int i=lane;i<Nk;i+=32) m = fmaxf(m, Srow[i]);
            #pragma unroll
            for (int o=16;o>0;o>>=1) m = fmaxf(m, __shfl_xor_sync(0xffffffffu, m, o));
            float sum = 0.f;
            for (int i=lane;i<Nk;i+=32){ float e = expf(Srow[i]-m); Srow[i]=e; sum+=e; }
            #pragma unroll
            for (int o=16;o>0;o>>=1) sum += __shfl_xor_sync(0xffffffffu, sum, o);
            float inv = 1.f/sum;
            for (int i=lane;i<Nkp;i+=32){
                __half p = (i<Nk) ? __float2half_rn(Srow[i]*inv) : __float2half_rn(0.f);
                *reinterpret_cast<__half*>(smc + AP_OFF + row*512 +
                    ((((i>>3)^(row&7)))<<4) + ((i&7)<<1)) = p;
            }
        }
    }

    float oacc[4][4] = {};
    for (int c=0;c<NC;c++){
        int c0 = c<<6;
        __syncthreads();
        {
            int r = tid>>2, pj = (tid&3)<<3;
            int t = c0 + r;
            uint4 lo = make_uint4(0,0,0,0), hi = make_uint4(0,0,0,0);
            if (t < Nk){
                const __half* vp = V + (size_t)(b*Nk+t)*ks + h*64;
                lo = *reinterpret_cast<const uint4*>(vp + pj);
                hi = *reinterpret_cast<const uint4*>(vp + pj + 32);
            }
            *reinterpret_cast<uint4*>(smc + AKV_OFF + SWZ(r*128 + pj*2)) = lo;
            *reinterpret_cast<uint4*>(smc + AKV_OFF + SWZ(r*128 + pj*2 + 64)) = hi;
        }
        __syncthreads();
        #pragma unroll
        for (int ks_=0;ks_<4;ks_++){
            uint32_t af[4];
            int prow = (mw<<4)+(lane&15);
            int pcol = c0 + (ks_<<4) + ((lane>>4)<<3);
            ldsm4(af, sb + AP_OFF + prow*512 + (((pcol>>3)^(prow&7))<<4));
            #pragma unroll
            for (int np=0;np<2;np++){
                uint32_t bf[4];
                int vrow = (ks_<<4) + (((lane>>3)&1)<<3) + (lane&7);
                int vcol = (nw<<5) + (np<<4) + ((lane>>4)<<3);
                ldsm4t(bf, sb + AKV_OFF + SWZ(vrow*128 + vcol*2));
                mma16816(oacc[2*np],   af, bf);
                mma16816(oacc[2*np+1], af, bf+2);
            }
        }
    }
    {
        int g = lane>>2, tq = lane&3;
        #pragma unroll
        for (int j=0;j<4;j++){
            int col = (nw<<5)+((j>>1)<<4)+((j&1)<<3)+(tq<<1);
            int r0 = (mw<<4)+g;
            if (q0+r0 < Nq){
                size_t i0 = (size_t)(b*Nq + q0 + r0)*D_ + h*64 + col;
                *reinterpret_cast<__half2*>(Oh+i0) = __floats2half2_rn(oacc[j][0], oacc[j][1]);
            }
            if (q0+r0+8 < Nq){
                size_t i1 = (size_t)(b*Nq + q0 + r0 + 8)*D_ + h*64 + col;
                *reinterpret_cast<__half2*>(Oh+i1) = __floats2half2_rn(oacc[j][2], oacc[j][3]);
            }
        }
    }
}

// ---- scene broadcast: fp32 + fp16 ----
__global__ void bcast_scene(const float* __restrict__ st){
    int off = blockIdx.x*256 + threadIdx.x;
    float v = st[off];
    size_t i = (size_t)blockIdx.y*(NS_*D_) + off;
    g_scene[i] = v;
    g_sh[i] = __float2half_rn(v);
}

extern "C" void kernel_launch(void* const* d_in, const int* in_sizes, int n_in,
                              void* d_out, int out_size)
{
    (void)in_sizes; (void)n_in; (void)out_size;
    const float *in_local=(const float*)d_in[0], *in_centers=(const float*)d_in[1],
        *in_scales=(const float*)d_in[2], *in_scene=(const float*)d_in[3],
        *rgate=(const float*)d_in[4], *wgate=(const float*)d_in[5],
        *rWq=(const float*)d_in[6], *rWk=(const float*)d_in[7], *rWv=(const float*)d_in[8],
        *rWo=(const float*)d_in[9], *wWq=(const float*)d_in[10], *wWk=(const float*)d_in[11],
        *wWv=(const float*)d_in[12], *wWo=(const float*)d_in[13],
        *ln1g=(const float*)d_in[14], *ln1b=(const float*)d_in[15],
        *qkvW=(const float*)d_in[16], *aWo=(const float*)d_in[17],
        *ln2g=(const float*)d_in[18], *ln2b=(const float*)d_in[19],
        *mW1=(const float*)d_in[20], *mW2=(const float*)d_in[21];

    float *local,*scene,*lsin,*lcos,*ssin,*scos;
    __half *wt,*lh,*sh,*aoh,*hbh,*mh,*qh,*kvh,*qkvh;
    cudaGetSymbolAddress((void**)&local,g_local); cudaGetSymbolAddress((void**)&scene,g_scene);
    cudaGetSymbolAddress((void**)&lsin,g_lsin); cudaGetSymbolAddress((void**)&lcos,g_lcos);
    cudaGetSymbolAddress((void**)&ssin,g_ssin); cudaGetSymbolAddress((void**)&scos,g_scos);
    cudaGetSymbolAddress((void**)&wt,g_wt);
    cudaGetSymbolAddress((void**)&lh,g_lh);   cudaGetSymbolAddress((void**)&sh,g_sh);
    cudaGetSymbolAddress((void**)&aoh,g_aoh); cudaGetSymbolAddress((void**)&hbh,g_hbh);
    cudaGetSymbolAddress((void**)&mh,g_mh);
    cudaGetSymbolAddress((void**)&qh,g_qh);   cudaGetSymbolAddress((void**)&kvh,g_kvh);
    cudaGetSymbolAddress((void**)&qkvh,g_qkvh);

    cudaFuncSetAttribute(mmagemm<0,2>, cudaFuncAttributeMaxDynamicSharedMemorySize, SMEMG);
    cudaFuncSetAttribute(mmagemm<1,2>, cudaFuncAttributeMaxDynamicSharedMemorySize, SMEMG);
    cudaFuncSetAttribute(mmagemm<2,0>, cudaFuncAttributeMaxDynamicSharedMemorySize, SMEMG);
    cudaFuncSetAttribute(mmagemm<2,1>, cudaFuncAttributeMaxDynamicSharedMemorySize, SMEMG);
    cudaFuncSetAttribute(mmagemm<3,0>, cudaFuncAttributeMaxDynamicSharedMemorySize, SMEMG);
    cudaFuncSetAttribute(mmagemm<3,1>, cudaFuncAttributeMaxDynamicSharedMemorySize, SMEMG);
    cudaFuncSetAttribute(attn3, cudaFuncAttributeMaxDynamicSharedMemorySize, SMATT);

    const size_t LS = 20*DD_;
    dim3 tb(32,8);
    wsplit<<<dim3(24,24,12),tb>>>(rWq,  wt+0*DD_,  768, 768,  LS);
    wsplit<<<dim3(24,24,12),tb>>>(rWk,  wt+1*DD_,  768, 768,  LS);
    wsplit<<<dim3(24,24,12),tb>>>(rWv,  wt+2*DD_,  768, 768,  LS);
    wsplit<<<dim3(24,24,12),tb>>>(rWo,  wt+3*DD_,  768, 768,  LS);
    wsplit<<<dim3(24,24,12),tb>>>(wWq,  wt+4*DD_,  768, 768,  LS);
    wsplit<<<dim3(24,24,12),tb>>>(wWk,  wt+5*DD_,  768, 768,  LS);
    wsplit<<<dim3(24,24,12),tb>>>(wWv,  wt+6*DD_,  768, 768,  LS);
    wsplit<<<dim3(24,24,12),tb>>>(wWo,  wt+7*DD_,  768, 768,  LS);
    wsplit<<<dim3(72,24,12),tb>>>(qkvW, wt+8*DD_,  768, 2304, LS);
    wsplit<<<dim3(24,24,12),tb>>>(aWo,  wt+11*DD_, 768, 768,  LS);
    wsplit<<<dim3(96,24,12),tb>>>(mW1,  wt+12*DD_, 768, 3072, LS);
    wsplit<<<dim3(24,96,12),tb>>>(mW2,  wt+16*DD_, 3072, 768, LS);

    cudaMemcpyAsync(local, in_local, sizeof(float)*(size_t)ML_*D_, cudaMemcpyDeviceToDevice);
    bcast_scene<<<dim3(NS_*D_/256, B_),256>>>(in_scene);
    rope_local_pre<<<dim3(NTL_,B_),32>>>(in_centers, in_scales);
    rope_scene_pre<<<NS_,32>>>();
    aconv<<<ML_*D_/1024,256>>>(local, lh);

    for (int i=0;i<12;i++){
        const __half* wb = wt + (size_t)i*LS;
        // ---- READ cross-attn ----
        mmagemm<0,2><<<dim3(6,54),   256, SMEMG>>>(lh, wb+0*DD_, nullptr, qh, nullptr, ML_, 768, 768);
        mmagemm<0,2><<<dim3(12,256), 256, SMEMG>>>(sh, wb+1*DD_, nullptr, kvh, nullptr, MS_, 1536, 768);
        attn3<<<dim3(1,NH_,B_),256,SMATT>>>(qh, kvh, kvh+768, aoh, NL_, NS_, 768, 1536,
                                            lsin,lcos,P_,0, ssin,scos,0,1);
        mmagemm<3,0><<<dim3(6,54),   256, SMEMG>>>(aoh, wb+3*DD_, local, nullptr, rgate+(size_t)i*D_, ML_, 768, 768);
        // ---- ViT block ----
        layernorm_k<<<ML_,256>>>(local, hbh, ln1g+(size_t)i*D_, ln1b+(size_t)i*D_);
        mmagemm<0,2><<<dim3(18,54),  256, SMEMG>>>(hbh, wb+8*DD_, nullptr, qkvh, nullptr, ML_, 2304, 768);
        attn3<<<dim3(1,NH_,B_),256,SMATT>>>(qkvh, qkvh+768, qkvh+1536, aoh, NL_, NL_, 2304, 2304,
                                            lsin,lcos,P_,0, lsin,lcos,P_,0);
        mmagemm<2,0><<<dim3(6,54),   256, SMEMG>>>(aoh, wb+11*DD_, local, nullptr, nullptr, ML_, 768, 768);
        layernorm_k<<<ML_,256>>>(local, hbh, ln2g+(size_t)i*D_, ln2b+(size_t)i*D_);
        mmagemm<1,2><<<dim3(24,54),  256, SMEMG>>>(hbh, wb+12*DD_, nullptr, mh, nullptr, ML_, 3072, 768);
        mmagemm<2,1><<<dim3(6,54),   256, SMEMG>>>(mh, wb+16*DD_, local, lh, nullptr, ML_, 768, 3072);
        // ---- WRITE cross-attn ----
        mmagemm<0,2><<<dim3(6,256),  256, SMEMG>>>(sh, wb+4*DD_, nullptr, qh, nullptr, MS_, 768, 768);
        mmagemm<0,2><<<dim3(12,54),  256, SMEMG>>>(lh, wb+5*DD_, nullptr, kvh, nullptr, ML_, 1536, 768);
        attn3<<<dim3(4,NH_,B_),256,SMATT>>>(qh, kvh, kvh+768, aoh, NS_, NL_, 768, 1536,
                                            ssin,scos,0,1, lsin,lcos,P_,0);
        mmagemm<3,1><<<dim3(6,256),  256, SMEMG>>>(aoh, wb+7*DD_, scene, sh, wgate+(size_t)i*D_, MS_, 768, 768);
    }

    cudaMemcpyAsync(d_out, local, sizeof(float)*(size_t)ML_*D_, cudaMemcpyDeviceToDevice);
    cudaMemcpyAsync((float*)d_out + (size_t)ML_*D_, scene, sizeof(float)*(size_t)MS_*D_,
                    cudaMemcpyDeviceToDevice);
}

// round 11
// speedup vs baseline: 7.4471x; 1.0119x over previous
#include <cuda_runtime.h>
#include <cuda_fp16.h>
#include <cstdint>

#define D_   768
#define NH_  12
#define P_   5
#define NL_  54
#define NS_  256
#define B_   128
#define NTL_ 49
#define ML_  (B_*NL_)
#define MS_  (B_*NS_)
#define DD_  ((size_t)768*768)

__device__ float g_local[(size_t)ML_*D_];
__device__ float g_scene[(size_t)MS_*D_];
__device__ float g_lsin [B_*NTL_*32];
__device__ float g_lcos [B_*NTL_*32];
__device__ float g_ssin [NS_*32];
__device__ float g_scos [NS_*32];
__device__ __half g_wt[(size_t)12*20*DD_];
__device__ __half g_lh  [(size_t)ML_*D_];
__device__ __half g_sh  [(size_t)MS_*D_];
__device__ __half g_aoh [(size_t)MS_*D_];
__device__ __half g_hbh [(size_t)ML_*D_];
__device__ __half g_mh  [(size_t)ML_*4*D_];
__device__ __half g_qh  [(size_t)MS_*D_];
__device__ __half g_kvh [(size_t)MS_*2*D_];
__device__ __half g_qkvh[(size_t)ML_*3*D_];

__device__ __forceinline__ uint32_t smem_to_u32(const void* p){
    uint32_t a;
    asm("{ .reg .u64 t; cvta.to.shared.u64 t, %1; cvt.u32.u64 %0, t; }" : "=r"(a) : "l"(p));
    return a;
}
#define SWZ(o) ((o) ^ (((o)>>3)&0x70))
#define CPA16(dst,src) asm volatile("cp.async.cg.shared.global [%0],[%1],16;"::"r"(dst),"l"(src))
#define CPA_COMMIT() asm volatile("cp.async.commit_group;")

__device__ __forceinline__ void ldsm4(uint32_t* r, uint32_t addr){
    asm volatile("ldmatrix.sync.aligned.m8n8.x4.shared.b16 {%0,%1,%2,%3},[%4];"
        : "=r"(r[0]),"=r"(r[1]),"=r"(r[2]),"=r"(r[3]) : "r"(addr));
}
__device__ __forceinline__ void ldsm4t(uint32_t* r, uint32_t addr){
    asm volatile("ldmatrix.sync.aligned.m8n8.x4.trans.shared.b16 {%0,%1,%2,%3},[%4];"
        : "=r"(r[0]),"=r"(r[1]),"=r"(r[2]),"=r"(r[3]) : "r"(addr));
}
__device__ __forceinline__ void mma16816(float* d, const uint32_t* a, const uint32_t* b){
    asm volatile("mma.sync.aligned.m16n8k16.row.col.f32.f16.f16.f32 "
        "{%0,%1,%2,%3},{%4,%5,%6,%7},{%8,%9},{%0,%1,%2,%3};"
        : "+f"(d[0]),"+f"(d[1]),"+f"(d[2]),"+f"(d[3])
        : "r"(a[0]),"r"(a[1]),"r"(a[2]),"r"(a[3]),"r"(b[0]),"r"(b[1]));
}
__device__ __forceinline__ float gelu_f(float x){
    float t = tanhf(0.7978845608028654f*(x + 0.044715f*x*x*x));
    return 0.5f*x*(1.0f+t);
}
__device__ __forceinline__ void cvt2(float2 v, __half* H, size_t idx){
    *reinterpret_cast<__half2*>(H+idx) =
        __halves2half2(__float2half_rn(v.x), __float2half_rn(v.y));
}

// ---- ALL weights: fp32 [K][N] -> fp16 [N][K] in one launch ----
// per-layer tile space (32x32 tiles): 8x(24x24)=4608 | qkv 72x24=1728 | aWo 576 | mW1 96x24=2304 | mW2 24x96=2304
__global__ void wsplit_all(const float* p0, const float* p1, const float* p2, const float* p3,
                           const float* p4, const float* p5, const float* p6, const float* p7,
                           const float* qkvW, const float* aWo, const float* mW1, const float* mW2,
                           __half* wt)
{
    const float* Wtab[8] = {p0,p1,p2,p3,p4,p5,p6,p7};
    int t = blockIdx.x, l = blockIdx.y;
    const float* W; size_t off; int K=768, N=768, nx=24;
    if (t < 4608){ int m=t/576; t-=m*576; W=Wtab[m]; off=(size_t)m*DD_; }
    else if (t < 6336){ t-=4608; W=qkvW; off=8*DD_;  N=2304; nx=72; }
    else if (t < 6912){ t-=6336; W=aWo;  off=11*DD_; }
    else if (t < 9216){ t-=6912; W=mW1;  off=12*DD_; N=3072; nx=96; }
    else              { t-=9216; W=mW2;  off=16*DD_; K=3072; }
    int n0=(t%nx)<<5, k0=(t/nx)<<5;
    const int tx = threadIdx.x, ty = threadIdx.y;
    __shared__ float tt[32][33];
    const float* Wl = W + (size_t)l*K*N;
    #pragma unroll
    for (int j=0;j<4;j++) tt[ty+8*j][tx] = Wl[(size_t)(k0+ty+8*j)*N + n0+tx];
    __syncthreads();
    __half* hi = wt + (size_t)l*(20*DD_) + off;
    #pragma unroll
    for (int j=0;j<4;j++)
        hi[(size_t)(n0+ty+8*j)*K + k0+tx] = __float2half_rn(tt[tx][ty+8*j]);
}

// ---- fp32 -> fp16 convert ----
__global__ __launch_bounds__(256) void aconv(const float* __restrict__ X, __half* __restrict__ H)
{
    int i = blockIdx.x*256 + threadIdx.x;
    float4 a = reinterpret_cast<const float4*>(X)[i];
    cvt2(make_float2(a.x,a.y), H, (size_t)i*4);
    cvt2(make_float2(a.z,a.w), H, (size_t)i*4+2);
}
// ---- fp32 copy ----
__global__ __launch_bounds__(256) void copyf(const float* __restrict__ X, float* __restrict__ Y)
{
    int i = blockIdx.x*256 + threadIdx.x;
    reinterpret_cast<float4*>(Y)[i] = reinterpret_cast<const float4*>(X)[i];
}

// ---- GEMM body: C[128x128 tile] = A * B^T, fp16 in, single-pass, 3-stage cp.async ----
#define STAGE_ 32768
#define SMEMG (3*STAGE_)
template<int EPI, int SPLIT>
__device__ __forceinline__ void gemm_body(const __half* __restrict__ Ah,
        const __half* __restrict__ Bh, float* __restrict__ C, __half* __restrict__ Hs,
        const float* __restrict__ gate, int N, int K, int m0, int n0, char* smc)
{
    const uint32_t sb = smem_to_u32(smc);
    const int tid = threadIdx.x, wid = tid>>5, lane = tid&31;
    const int mw = wid>>1, nw = wid&1;

    float acc[2][8][4];
    #pragma unroll
    for (int i=0;i<2;i++)
        #pragma unroll
        for (int j=0;j<8;j++)
            #pragma unroll
            for (int q=0;q<4;q++) acc[i][j][q]=0.f;

    const int NC = K>>6;
    auto issue = [&](int c){
        const int s = c%3, kc = c<<6;
        const uint32_t sbase = sb + s*STAGE_;
        #pragma unroll
        for (int it=0; it<4; it++){
            int u = (it<<8) + tid;
            int r = u>>3, c16 = u&7;
            uint32_t dst = sbase + SWZ((uint32_t)(r*128 + c16*16));
            CPA16(dst,         Ah + (size_t)(m0+r)*K + kc + (c16<<3));
            CPA16(dst + 16384, Bh + (size_t)(n0+r)*K + kc + (c16<<3));
        }
        CPA_COMMIT();
    };
    issue(0);
    if (NC>1) issue(1);
    for (int c=0; c<NC; c++){
        if (c+1 < NC) asm volatile("cp.async.wait_group 1;");
        else          asm volatile("cp.async.wait_group 0;");
        __syncthreads();
        if (c+2 < NC) issue(c+2);
        const uint32_t sbase = sb + (c%3)*STAGE_;
        #pragma unroll
        for (int ks=0; ks<4; ks++){
            uint32_t ah[2][4];
            #pragma unroll
            for (int ma=0; ma<2; ma++){
                int row = (mw<<5) + (ma<<4) + (lane&15);
                int kb  = (ks<<4) + ((lane>>4)<<3);
                ldsm4(ah[ma], sbase + SWZ((uint32_t)(row*128 + kb*2)));
            }
            #pragma unroll
            for (int np=0; np<4; np++){
                uint32_t bh[4];
                int row = (nw<<6) + (np<<4) + (lane&7) + ((lane>>4)<<3);
                int kb  = (ks<<4) + (((lane>>3)&1)<<3);
                ldsm4(bh, sbase + 16384 + SWZ((uint32_t)(row*128 + kb*2)));
                #pragma unroll
                for (int ma=0; ma<2; ma++) mma16816(acc[ma][2*np],   ah[ma], bh);
                #pragma unroll
                for (int ma=0; ma<2; ma++) mma16816(acc[ma][2*np+1], ah[ma], bh+2);
            }
        }
    }
    const int g = lane>>2, t = lane&3;
    #pragma unroll
    for (int ma=0; ma<2; ma++){
        int r0 = m0 + (mw<<5) + (ma<<4) + g;
        #pragma unroll
        for (int na=0; na<8; na++){
            int col = n0 + (nw<<6) + (na<<3) + (t<<1);
            size_t i0 = (size_t)r0*N + col;
            size_t i1 = i0 + 8*(size_t)N;
            float2 v0 = make_float2(acc[ma][na][0], acc[ma][na][1]);
            float2 v1 = make_float2(acc[ma][na][2], acc[ma][na][3]);
            if (EPI==1){
                v0.x=gelu_f(v0.x); v0.y=gelu_f(v0.y); v1.x=gelu_f(v1.x); v1.y=gelu_f(v1.y);
            } else if (EPI==2){
                float2 o0 = *reinterpret_cast<float2*>(C+i0);
                float2 o1 = *reinterpret_cast<float2*>(C+i1);
                v0.x+=o0.x; v0.y+=o0.y; v1.x+=o1.x; v1.y+=o1.y;
            } else if (EPI==3){
                float g0 = gate[col], g1 = gate[col+1];
                float2 o0 = *reinterpret_cast<float2*>(C+i0);
                float2 o1 = *reinterpret_cast<float2*>(C+i1);
                v0.x=o0.x+g0*v0.x; v0.y=o0.y+g1*v0.y;
                v1.x=o1.x+g0*v1.x; v1.y=o1.y+g1*v1.y;
            }
            if (SPLIT != 2){
                *reinterpret_cast<float2*>(C+i0) = v0;
                *reinterpret_cast<float2*>(C+i1) = v1;
            }
            if (SPLIT >= 1){ cvt2(v0, Hs, i0); cvt2(v1, Hs, i1); }
        }
    }
}

template<int EPI, int SPLIT>
__global__ __launch_bounds__(256,2) void mmagemm(const __half* __restrict__ Ah,
        const __half* __restrict__ Bh, float* __restrict__ C, __half* __restrict__ Hs,
        const float* __restrict__ gate, int M, int N, int K)
{
    extern __shared__ char smc[];
    gemm_body<EPI,SPLIT>(Ah, Bh, C, Hs, gate, N, K, blockIdx.y<<7, blockIdx.x<<7, smc);
}

// two independent fp16-out GEMMs in one launch (EPI0/SPLIT2), K=768 both
__global__ __launch_bounds__(256,2) void mmagemm_pair(
        const __half* __restrict__ A0, const __half* __restrict__ B0, __half* __restrict__ H0,
        int N0, int ntx0, int T0,
        const __half* __restrict__ A1, const __half* __restrict__ B1, __half* __restrict__ H1,
        int N1, int ntx1)
{
    extern __shared__ char smc[];
    int t = blockIdx.x;
    if (t < T0)
        gemm_body<0,2>(A0, B0, nullptr, H0, nullptr, N0, 768, (t/ntx0)<<7, (t%ntx0)<<7, smc);
    else {
        t -= T0;
        gemm_body<0,2>(A1, B1, nullptr, H1, nullptr, N1, 768, (t/ntx1)<<7, (t%ntx1)<<7, smc);
    }
}

// ---- LayerNorm: fp32 in -> fp16 out ----
__global__ __launch_bounds__(256) void layernorm_k(const float* __restrict__ X,
        __half* __restrict__ H, const float* __restrict__ g, const float* __restrict__ bb)
{
    __shared__ float red[8], red2[8];
    const int row = blockIdx.x, tid = threadIdx.x, lane = tid&31, wid = tid>>5;
    const float* x = X + (size_t)row*D_;
    float v0=x[tid], v1=x[tid+256], v2=x[tid+512];
    float s = v0+v1+v2;
    #pragma unroll
    for (int o=16;o;o>>=1) s += __shfl_xor_sync(0xffffffffu, s, o);
    if (lane==0) red[wid]=s;
    __syncthreads();
    float mean = (red[0]+red[1]+red[2]+red[3]+red[4]+red[5]+red[6]+red[7])*(1.f/768.f);
    float d0=v0-mean, d1=v1-mean, d2=v2-mean;
    float q = d0*d0+d1*d1+d2*d2;
    #pragma unroll
    for (int o=16;o;o>>=1) q += __shfl_xor_sync(0xffffffffu, q, o);
    if (lane==0) red2[wid]=q;
    __syncthreads();
    float inv = rsqrtf((red2[0]+red2[1]+red2[2]+red2[3]+red2[4]+red2[5]+red2[6]+red2[7])*(1.f/768.f)+1e-6f);
    size_t base = (size_t)row*D_;
    H[base+tid]     = __float2half_rn(d0*inv*g[tid]     + bb[tid]);
    H[base+tid+256] = __float2half_rn(d1*inv*g[tid+256] + bb[tid+256]);
    H[base+tid+512] = __float2half_rn(d2*inv*g[tid+512] + bb[tid+512]);
}

// ---- RoPE tables ----
__global__ void rope_local_pre(const float* __restrict__ centers, const float* __restrict__ scales){
    int t=blockIdx.x, b=blockIdx.y, j=threadIdx.x;
    float gy=(t/7+0.5f)*(2.f/7.f)-1.f, gx=(t%7+0.5f)*(2.f/7.f)-1.f;
    float sc=scales[b];
    float pos=(j<16)?(centers[2*b]+sc*gy):(centers[2*b+1]+sc*gx);
    float a=pos*expf(-4.605170185988091f*(float)(j&15)*(1.f/16.f));
    int idx=(b*NTL_+t)*32+j;
    g_lsin[idx]=sinf(a); g_lcos[idx]=cosf(a);
}
__global__ void rope_scene_pre(){
    int t=blockIdx.x, j=threadIdx.x;
    float gy=(t/16+0.5f)*(2.f/16.f)-1.f, gx=(t%16+0.5f)*(2.f/16.f)-1.f;
    float pos=(j<16)?gy:gx;
    float a=pos*expf(-4.605170185988091f*(float)(j&15)*(1.f/16.f));
    g_ssin[t*32+j]=sinf(a); g_scos[t*32+j]=cosf(a);
}

// ---- attention: fp16 mma QK/PV, fp32 softmax, fused rope ----
#define AQ_OFF  0
#define AKV_OFF 8192
#define AS_OFF  16384
#define AP_OFF  81920
#define SMATT   114688
__global__ __launch_bounds__(256,2) void attn3(
    const __half* __restrict__ Q, const __half* __restrict__ K, const __half* __restrict__ V,
    __half* __restrict__ Oh, int Nq, int Nk, int qs, int ks,
    const float* __restrict__ qS, const float* __restrict__ qC, int qpre, int qbi,
    const float* __restrict__ kS, const float* __restrict__ kC, int kpre, int kbi)
{
    extern __shared__ char smc[];
    const uint32_t sb = smem_to_u32(smc);
    float* Sm = reinterpret_cast<float*>(smc + AS_OFF);
    const int q0 = blockIdx.x<<6, h = blockIdx.y, b = blockIdx.z;
    const int tid = threadIdx.x, wid = tid>>5, lane = tid&31;
    const int mw = wid>>1, nw = wid&1;

    {
        int r = tid>>2, pj = (tid&3)<<3;
        int t = q0 + r;
        uint4 lo = make_uint4(0,0,0,0), hi = make_uint4(0,0,0,0);
        if (t < Nq){
            const __half* qp = Q + (size_t)(b*Nq+t)*qs + h*64;
            lo = *reinterpret_cast<const uint4*>(qp + pj);
            hi = *reinterpret_cast<const uint4*>(qp + pj + 32);
            if (t >= qpre){
                int so = (qbi ? t*32 : (b*NTL_ + (t-qpre))*32) + pj;
                __half2* l2 = reinterpret_cast<__half2*>(&lo);
                __half2* h2 = reinterpret_cast<__half2*>(&hi);
                #pragma unroll
                for (int jj=0;jj<4;jj++){
                    float2 x1 = __half22float2(l2[jj]);
                    float2 x2 = __half22float2(h2[jj]);
                    float s0=qS[so+2*jj], c0=qC[so+2*jj];
                    float s1=qS[so+2*jj+1], c1=qC[so+2*jj+1];
                    l2[jj] = __floats2half2_rn(x1.x*c0-x2.x*s0, x1.y*c1-x2.y*s1);
                    h2[jj] = __floats2half2_rn(x2.x*c0+x1.x*s0, x2.y*c1+x1.y*s1);
                }
            }
        }
        *reinterpret_cast<uint4*>(smc + AQ_OFF + SWZ(r*128 + pj*2)) = lo;
        *reinterpret_cast<uint4*>(smc + AQ_OFF + SWZ(r*128 + pj*2 + 64)) = hi;
    }

    const int NC = (Nk + 63) >> 6;
    for (int c=0;c<NC;c++){
        int c0 = c<<6;
        __syncthreads();
        {
            int r = tid>>2, pj = (tid&3)<<3;
            int t = c0 + r;
            uint4 lo = make_uint4(0,0,0,0), hi = make_uint4(0,0,0,0);
            if (t < Nk){
                const __half* kp = K + (size_t)(b*Nk+t)*ks + h*64;
                lo = *reinterpret_cast<const uint4*>(kp + pj);
                hi = *reinterpret_cast<const uint4*>(kp + pj + 32);
                if (t >= kpre){
                    int so = (kbi ? t*32 : (b*NTL_ + (t-kpre))*32) + pj;
                    __half2* l2 = reinterpret_cast<__half2*>(&lo);
                    __half2* h2 = reinterpret_cast<__half2*>(&hi);
                    #pragma unroll
                    for (int jj=0;jj<4;jj++){
                        float2 x1 = __half22float2(l2[jj]);
                        float2 x2 = __half22float2(h2[jj]);
                        float s0=kS[so+2*jj], c0f=kC[so+2*jj];
                        float s1=kS[so+2*jj+1], c1f=kC[so+2*jj+1];
                        l2[jj] = __floats2half2_rn(x1.x*c0f-x2.x*s0, x1.y*c1f-x2.y*s1);
                        h2[jj] = __floats2half2_rn(x2.x*c0f+x1.x*s0, x2.y*c1f+x1.y*s1);
                    }
                }
            }
            *reinterpret_cast<uint4*>(smc + AKV_OFF + SWZ(r*128 + pj*2)) = lo;
            *reinterpret_cast<uint4*>(smc + AKV_OFF + SWZ(r*128 + pj*2 + 64)) = hi;
        }
        __syncthreads();
        float acc[4][4] = {};
        #pragma unroll
        for (int ks_=0;ks_<4;ks_++){
            uint32_t af[4];
            ldsm4(af, sb + AQ_OFF + SWZ(((mw<<4)+(lane&15))*128 + ((ks_<<4)+((lane>>4)<<3))*2));
            #pragma unroll
            for (int np=0;np<2;np++){
                uint32_t bf[4];
                int krow = (nw<<5)+(np<<4)+(lane&7)+((lane>>4)<<3);
                ldsm4(bf, sb + AKV_OFF + SWZ(krow*128 + ((ks_<<4)+(((lane>>3)&1)<<3))*2));
                mma16816(acc[2*np],   af, bf);
                mma16816(acc[2*np+1], af, bf+2);
            }
        }
        int g = lane>>2, tq = lane&3;
        #pragma unroll
        for (int j=0;j<4;j++){
            int col = c0 + (nw<<5) + ((j>>1)<<4) + ((j&1)<<3) + (tq<<1);
            int r0 = (mw<<4)+g;
            float* s0 = Sm + r0*256 + col;
            s0[0]=acc[j][0]*0.125f; s0[1]=acc[j][1]*0.125f;
            float* s1 = s0 + 8*256;
            s1[0]=acc[j][2]*0.125f; s1[1]=acc[j][3]*0.125f;
        }
    }
    __syncthreads();

    {
        int Nkp = NC<<6;
        for (int rr=0;rr<8;rr++){
            int row = (wid<<3)+rr;
            float* Srow = Sm + row*256;
            float m = -1e30f;
            for (int i=lane;i<Nk;i+=32) m = fmaxf(m, Srow[i]);
            #pragma unroll
            for (int o=16;o>0;o>>=1) m = fmaxf(m, __shfl_xor_sync(0xffffffffu, m, o));
            float sum = 0.f;
            for (int i=lane;i<Nk;i+=32){ float e = expf(Srow[i]-m); Srow[i]=e; sum+=e; }
            #pragma unroll
            for (int o=16;o>0;o>>=1) sum += __shfl_xor_sync(0xffffffffu, sum, o);
            float inv = 1.f/sum;
            for (int i=lane;i<Nkp;i+=32){
                __half p = (i<Nk) ? __float2half_rn(Srow[i]*inv) : __float2half_rn(0.f);
                *reinterpret_cast<__half*>(smc + AP_OFF + row*512 +
                    ((((i>>3)^(row&7)))<<4) + ((i&7)<<1)) = p;
            }
        }
    }

    float oacc[4][4] = {};
    for (int c=0;c<NC;c++){
        int c0 = c<<6;
        __syncthreads();
        {
            int r = tid>>2, pj = (tid&3)<<3;
            int t = c0 + r;
            uint4 lo = make_uint4(0,0,0,0), hi = make_uint4(0,0,0,0);
            if (t < Nk){
                const __half* vp = V + (size_t)(b*Nk+t)*ks + h*64;
                lo = *reinterpret_cast<const uint4*>(vp + pj);
                hi = *reinterpret_cast<const uint4*>(vp + pj + 32);
            }
            *reinterpret_cast<uint4*>(smc + AKV_OFF + SWZ(r*128 + pj*2)) = lo;
            *reinterpret_cast<uint4*>(smc + AKV_OFF + SWZ(r*128 + pj*2 + 64)) = hi;
        }
        __syncthreads();
        #pragma unroll
        for (int ks_=0;ks_<4;ks_++){
            uint32_t af[4];
            int prow = (mw<<4)+(lane&15);
            int pcol = c0 + (ks_<<4) + ((lane>>4)<<3);
            ldsm4(af, sb + AP_OFF + prow*512 + (((pcol>>3)^(prow&7))<<4));
            #pragma unroll
            for (int np=0;np<2;np++){
                uint32_t bf[4];
                int vrow = (ks_<<4) + (((lane>>3)&1)<<3) + (lane&7);
                int vcol = (nw<<5) + (np<<4) + ((lane>>4)<<3);
                ldsm4t(bf, sb + AKV_OFF + SWZ(vrow*128 + vcol*2));
                mma16816(oacc[2*np],   af, bf);
                mma16816(oacc[2*np+1], af, bf+2);
            }
        }
    }
    {
        int g = lane>>2, tq = lane&3;
        #pragma unroll
        for (int j=0;j<4;j++){
            int col = (nw<<5)+((j>>1)<<4)+((j&1)<<3)+(tq<<1);
            int r0 = (mw<<4)+g;
            if (q0+r0 < Nq){
                size_t i0 = (size_t)(b*Nq + q0 + r0)*D_ + h*64 + col;
                *reinterpret_cast<__half2*>(Oh+i0) = __floats2half2_rn(oacc[j][0], oacc[j][1]);
            }
            if (q0+r0+8 < Nq){
                size_t i1 = (size_t)(b*Nq + q0 + r0 + 8)*D_ + h*64 + col;
                *reinterpret_cast<__half2*>(Oh+i1) = __floats2half2_rn(oacc[j][2], oacc[j][3]);
            }
        }
    }
}

// ---- scene broadcast: fp32 + fp16 ----
__global__ void bcast_scene(const float* __restrict__ st){
    int off = blockIdx.x*256 + threadIdx.x;
    float v = st[off];
    size_t i = (size_t)blockIdx.y*(NS_*D_) + off;
    g_scene[i] = v;
    g_sh[i] = __float2half_rn(v);
}

extern "C" void kernel_launch(void* const* d_in, const int* in_sizes, int n_in,
                              void* d_out, int out_size)
{
    (void)in_sizes; (void)n_in; (void)out_size;
    const float *in_local=(const float*)d_in[0], *in_centers=(const float*)d_in[1],
        *in_scales=(const float*)d_in[2], *in_scene=(const float*)d_in[3],
        *rgate=(const float*)d_in[4], *wgate=(const float*)d_in[5],
        *rWq=(const float*)d_in[6], *rWk=(const float*)d_in[7], *rWv=(const float*)d_in[8],
        *rWo=(const float*)d_in[9], *wWq=(const float*)d_in[10], *wWk=(const float*)d_in[11],
        *wWv=(const float*)d_in[12], *wWo=(const float*)d_in[13],
        *ln1g=(const float*)d_in[14], *ln1b=(const float*)d_in[15],
        *qkvW=(const float*)d_in[16], *aWo=(const float*)d_in[17],
        *ln2g=(const float*)d_in[18], *ln2b=(const float*)d_in[19],
        *mW1=(const float*)d_in[20], *mW2=(const float*)d_in[21];

    float *local,*scene,*lsin,*lcos,*ssin,*scos;
    __half *wt,*lh,*sh,*aoh,*hbh,*mh,*qh,*kvh,*qkvh;
    cudaGetSymbolAddress((void**)&local,g_local); cudaGetSymbolAddress((void**)&scene,g_scene);
    cudaGetSymbolAddress((void**)&lsin,g_lsin); cudaGetSymbolAddress((void**)&lcos,g_lcos);
    cudaGetSymbolAddress((void**)&ssin,g_ssin); cudaGetSymbolAddress((void**)&scos,g_scos);
    cudaGetSymbolAddress((void**)&wt,g_wt);
    cudaGetSymbolAddress((void**)&lh,g_lh);   cudaGetSymbolAddress((void**)&sh,g_sh);
    cudaGetSymbolAddress((void**)&aoh,g_aoh); cudaGetSymbolAddress((void**)&hbh,g_hbh);
    cudaGetSymbolAddress((void**)&mh,g_mh);
    cudaGetSymbolAddress((void**)&qh,g_qh);   cudaGetSymbolAddress((void**)&kvh,g_kvh);
    cudaGetSymbolAddress((void**)&qkvh,g_qkvh);

    cudaFuncSetAttribute(mmagemm<0,2>, cudaFuncAttributeMaxDynamicSharedMemorySize, SMEMG);
    cudaFuncSetAttribute(mmagemm<1,2>, cudaFuncAttributeMaxDynamicSharedMemorySize, SMEMG);
    cudaFuncSetAttribute(mmagemm<2,0>, cudaFuncAttributeMaxDynamicSharedMemorySize, SMEMG);
    cudaFuncSetAttribute(mmagemm<2,1>, cudaFuncAttributeMaxDynamicSharedMemorySize, SMEMG);
    cudaFuncSetAttribute(mmagemm<3,0>, cudaFuncAttributeMaxDynamicSharedMemorySize, SMEMG);
    cudaFuncSetAttribute(mmagemm<3,1>, cudaFuncAttributeMaxDynamicSharedMemorySize, SMEMG);
    cudaFuncSetAttribute(mmagemm_pair, cudaFuncAttributeMaxDynamicSharedMemorySize, SMEMG);
    cudaFuncSetAttribute(attn3, cudaFuncAttributeMaxDynamicSharedMemorySize, SMATT);

    const size_t LS = 20*DD_;
    // launch order chosen so the first mmagemm_pair is kernel launch #6 (ncu -s 5 -c 1)
    wsplit_all<<<dim3(11520,12), dim3(32,8)>>>(rWq,rWk,rWv,rWo,wWq,wWk,wWv,wWo,
                                               qkvW,aWo,mW1,mW2, wt);         // 1
    aconv<<<ML_*D_/1024,256>>>(in_local, lh);                                  // 2
    bcast_scene<<<dim3(NS_*D_/256, B_),256>>>(in_scene);                       // 3
    rope_local_pre<<<dim3(NTL_,B_),32>>>(in_centers, in_scales);               // 4
    rope_scene_pre<<<NS_,32>>>();                                              // 5

    for (int i=0;i<12;i++){
        const __half* wb = wt + (size_t)i*LS;
        // ---- READ cross-attn: q(local) || kv(scene) grouped ----
        mmagemm_pair<<<324+3072, 256, SMEMG>>>(lh, wb+0*DD_, qh, 768, 6, 324,
                                               sh, wb+1*DD_, kvh, 1536, 12);   // 6 on i==0
        if (i==0) copyf<<<ML_*D_/1024,256>>>(in_local, local);
        attn3<<<dim3(1,NH_,B_),256,SMATT>>>(qh, kvh, kvh+768, aoh, NL_, NS_, 768, 1536,
                                            lsin,lcos,P_,0, ssin,scos,0,1);
        mmagemm<3,0><<<dim3(6,54),   256, SMEMG>>>(aoh, wb+3*DD_, local, nullptr, rgate+(size_t)i*D_, ML_, 768, 768);
        // ---- ViT block ----
        layernorm_k<<<ML_,256>>>(local, hbh, ln1g+(size_t)i*D_, ln1b+(size_t)i*D_);
        mmagemm<0,2><<<dim3(18,54),  256, SMEMG>>>(hbh, wb+8*DD_, nullptr, qkvh, nullptr, ML_, 2304, 768);
        attn3<<<dim3(1,NH_,B_),256,SMATT>>>(qkvh, qkvh+768, qkvh+1536, aoh, NL_, NL_, 2304, 2304,
                                            lsin,lcos,P_,0, lsin,lcos,P_,0);
        mmagemm<2,0><<<dim3(6,54),   256, SMEMG>>>(aoh, wb+11*DD_, local, nullptr, nullptr, ML_, 768, 768);
        layernorm_k<<<ML_,256>>>(local, hbh, ln2g+(size_t)i*D_, ln2b+(size_t)i*D_);
        mmagemm<1,2><<<dim3(24,54),  256, SMEMG>>>(hbh, wb+12*DD_, nullptr, mh, nullptr, ML_, 3072, 768);
        mmagemm<2,1><<<dim3(6,54),   256, SMEMG>>>(mh, wb+16*DD_, local, lh, nullptr, ML_, 768, 3072);
        // ---- WRITE cross-attn: q(scene) || kv(local) grouped ----
        mmagemm_pair<<<1536+648, 256, SMEMG>>>(sh, wb+4*DD_, qh, 768, 6, 1536,
                                               lh, wb+5*DD_, kvh, 1536, 12);
        attn3<<<dim3(4,NH_,B_),256,SMATT>>>(qh, kvh, kvh+768, aoh, NS_, NL_, 768, 1536,
                                            ssin,scos,0,1, lsin,lcos,P_,0);
        mmagemm<3,1><<<dim3(6,256),  256, SMEMG>>>(aoh, wb+7*DD_, scene, sh, wgate+(size_t)i*D_, MS_, 768, 768);
    }

    cudaMemcpyAsync(d_out, local, sizeof(float)*(size_t)ML_*D_, cudaMemcpyDeviceToDevice);
    cudaMemcpyAsync((float*)d_out + (size_t)ML_*D_, scene, sizeof(float)*(size_t)MS_*D_,
                    cudaMemcpyDeviceToDevice);
}

// round 12
// speedup vs baseline: 7.4645x; 1.0023x over previous
#include <cuda_runtime.h>
#include <cuda_fp16.h>
#include <cstdint>

#define D_   768
#define NH_  12
#define P_   5
#define NL_  54
#define NS_  256
#define B_   128
#define NTL_ 49
#define ML_  (B_*NL_)
#define MS_  (B_*NS_)
#define DD_  ((size_t)768*768)

__device__ float g_local[(size_t)ML_*D_];
__device__ float g_scene[(size_t)MS_*D_];
__device__ float g_lsin [B_*NTL_*32];
__device__ float g_lcos [B_*NTL_*32];
__device__ float g_ssin [NS_*32];
__device__ float g_scos [NS_*32];
__device__ __half g_wt[(size_t)12*20*DD_];
__device__ __half g_lh  [(size_t)ML_*D_];
__device__ __half g_sh  [(size_t)MS_*D_];
__device__ __half g_aoh [(size_t)MS_*D_];
__device__ __half g_hbh [(size_t)ML_*D_];
__device__ __half g_mh  [(size_t)ML_*4*D_];
__device__ __half g_qh  [(size_t)MS_*D_];
__device__ __half g_kvh [(size_t)MS_*2*D_];
__device__ __half g_qkvh[(size_t)ML_*3*D_];

__device__ __forceinline__ uint32_t smem_to_u32(const void* p){
    uint32_t a;
    asm("{ .reg .u64 t; cvta.to.shared.u64 t, %1; cvt.u32.u64 %0, t; }" : "=r"(a) : "l"(p));
    return a;
}
#define SWZ(o) ((o) ^ (((o)>>3)&0x70))
#define CPA16(dst,src) asm volatile("cp.async.cg.shared.global [%0],[%1],16;"::"r"(dst),"l"(src))
#define CPA_COMMIT() asm volatile("cp.async.commit_group;")

__device__ __forceinline__ void ldsm4(uint32_t* r, uint32_t addr){
    asm volatile("ldmatrix.sync.aligned.m8n8.x4.shared.b16 {%0,%1,%2,%3},[%4];"
        : "=r"(r[0]),"=r"(r[1]),"=r"(r[2]),"=r"(r[3]) : "r"(addr));
}
__device__ __forceinline__ void ldsm4t(uint32_t* r, uint32_t addr){
    asm volatile("ldmatrix.sync.aligned.m8n8.x4.trans.shared.b16 {%0,%1,%2,%3},[%4];"
        : "=r"(r[0]),"=r"(r[1]),"=r"(r[2]),"=r"(r[3]) : "r"(addr));
}
__device__ __forceinline__ void mma16816(float* d, const uint32_t* a, const uint32_t* b){
    asm volatile("mma.sync.aligned.m16n8k16.row.col.f32.f16.f16.f32 "
        "{%0,%1,%2,%3},{%4,%5,%6,%7},{%8,%9},{%0,%1,%2,%3};"
        : "+f"(d[0]),"+f"(d[1]),"+f"(d[2]),"+f"(d[3])
        : "r"(a[0]),"r"(a[1]),"r"(a[2]),"r"(a[3]),"r"(b[0]),"r"(b[1]));
}
__device__ __forceinline__ float gelu_f(float x){
    float t = tanhf(0.7978845608028654f*(x + 0.044715f*x*x*x));
    return 0.5f*x*(1.0f+t);
}
__device__ __forceinline__ void cvt2(float2 v, __half* H, size_t idx){
    *reinterpret_cast<__half2*>(H+idx) =
        __halves2half2(__float2half_rn(v.x), __float2half_rn(v.y));
}

// ---- ALL weights: fp32 [K][N] -> fp16 [N][K] in one launch ----
__global__ void wsplit_all(const float* p0, const float* p1, const float* p2, const float* p3,
                           const float* p4, const float* p5, const float* p6, const float* p7,
                           const float* qkvW, const float* aWo, const float* mW1, const float* mW2,
                           __half* wt)
{
    const float* Wtab[8] = {p0,p1,p2,p3,p4,p5,p6,p7};
    int t = blockIdx.x, l = blockIdx.y;
    const float* W; size_t off; int K=768, N=768, nx=24;
    if (t < 4608){ int m=t/576; t-=m*576; W=Wtab[m]; off=(size_t)m*DD_; }
    else if (t < 6336){ t-=4608; W=qkvW; off=8*DD_;  N=2304; nx=72; }
    else if (t < 6912){ t-=6336; W=aWo;  off=11*DD_; }
    else if (t < 9216){ t-=6912; W=mW1;  off=12*DD_; N=3072; nx=96; }
    else              { t-=9216; W=mW2;  off=16*DD_; K=3072; }
    int n0=(t%nx)<<5, k0=(t/nx)<<5;
    const int tx = threadIdx.x, ty = threadIdx.y;
    __shared__ float tt[32][33];
    const float* Wl = W + (size_t)l*K*N;
    #pragma unroll
    for (int j=0;j<4;j++) tt[ty+8*j][tx] = Wl[(size_t)(k0+ty+8*j)*N + n0+tx];
    __syncthreads();
    __half* hi = wt + (size_t)l*(20*DD_) + off;
    #pragma unroll
    for (int j=0;j<4;j++)
        hi[(size_t)(n0+ty+8*j)*K + k0+tx] = __float2half_rn(tt[tx][ty+8*j]);
}

// ---- fp32 -> fp16 convert ----
__global__ __launch_bounds__(256) void aconv(const float* __restrict__ X, __half* __restrict__ H)
{
    int i = blockIdx.x*256 + threadIdx.x;
    float4 a = reinterpret_cast<const float4*>(X)[i];
    cvt2(make_float2(a.x,a.y), H, (size_t)i*4);
    cvt2(make_float2(a.z,a.w), H, (size_t)i*4+2);
}
__global__ __launch_bounds__(256) void copyf(const float* __restrict__ X, float* __restrict__ Y)
{
    int i = blockIdx.x*256 + threadIdx.x;
    reinterpret_cast<float4*>(Y)[i] = reinterpret_cast<const float4*>(X)[i];
}

// ---- GEMM body ----
#define STAGE_ 32768
#define SMEMG (3*STAGE_)
template<int EPI, int SPLIT>
__device__ __forceinline__ void gemm_body(const __half* __restrict__ Ah,
        const __half* __restrict__ Bh, float* __restrict__ C, __half* __restrict__ Hs,
        const float* __restrict__ gate, int N, int K, int m0, int n0, char* smc)
{
    const uint32_t sb = smem_to_u32(smc);
    const int tid = threadIdx.x, wid = tid>>5, lane = tid&31;
    const int mw = wid>>1, nw = wid&1;

    float acc[2][8][4];
    #pragma unroll
    for (int i=0;i<2;i++)
        #pragma unroll
        for (int j=0;j<8;j++)
            #pragma unroll
            for (int q=0;q<4;q++) acc[i][j][q]=0.f;

    const int NC = K>>6;
    auto issue = [&](int c){
        const int s = c%3, kc = c<<6;
        const uint32_t sbase = sb + s*STAGE_;
        #pragma unroll
        for (int it=0; it<4; it++){
            int u = (it<<8) + tid;
            int r = u>>3, c16 = u&7;
            uint32_t dst = sbase + SWZ((uint32_t)(r*128 + c16*16));
            CPA16(dst,         Ah + (size_t)(m0+r)*K + kc + (c16<<3));
            CPA16(dst + 16384, Bh + (size_t)(n0+r)*K + kc + (c16<<3));
        }
        CPA_COMMIT();
    };
    issue(0);
    if (NC>1) issue(1);
    for (int c=0; c<NC; c++){
        if (c+1 < NC) asm volatile("cp.async.wait_group 1;");
        else          asm volatile("cp.async.wait_group 0;");
        __syncthreads();
        if (c+2 < NC) issue(c+2);
        const uint32_t sbase = sb + (c%3)*STAGE_;
        #pragma unroll
        for (int ks=0; ks<4; ks++){
            uint32_t ah[2][4];
            #pragma unroll
            for (int ma=0; ma<2; ma++){
                int row = (mw<<5) + (ma<<4) + (lane&15);
                int kb  = (ks<<4) + ((lane>>4)<<3);
                ldsm4(ah[ma], sbase + SWZ((uint32_t)(row*128 + kb*2)));
            }
            #pragma unroll
            for (int np=0; np<4; np++){
                uint32_t bh[4];
                int row = (nw<<6) + (np<<4) + (lane&7) + ((lane>>4)<<3);
                int kb  = (ks<<4) + (((lane>>3)&1)<<3);
                ldsm4(bh, sbase + 16384 + SWZ((uint32_t)(row*128 + kb*2)));
                #pragma unroll
                for (int ma=0; ma<2; ma++) mma16816(acc[ma][2*np],   ah[ma], bh);
                #pragma unroll
                for (int ma=0; ma<2; ma++) mma16816(acc[ma][2*np+1], ah[ma], bh+2);
            }
        }
    }
    const int g = lane>>2, t = lane&3;
    #pragma unroll
    for (int ma=0; ma<2; ma++){
        int r0 = m0 + (mw<<5) + (ma<<4) + g;
        #pragma unroll
        for (int na=0; na<8; na++){
            int col = n0 + (nw<<6) + (na<<3) + (t<<1);
            size_t i0 = (size_t)r0*N + col;
            size_t i1 = i0 + 8*(size_t)N;
            float2 v0 = make_float2(acc[ma][na][0], acc[ma][na][1]);
            float2 v1 = make_float2(acc[ma][na][2], acc[ma][na][3]);
            if (EPI==1){
                v0.x=gelu_f(v0.x); v0.y=gelu_f(v0.y); v1.x=gelu_f(v1.x); v1.y=gelu_f(v1.y);
            } else if (EPI==2){
                float2 o0 = *reinterpret_cast<float2*>(C+i0);
                float2 o1 = *reinterpret_cast<float2*>(C+i1);
                v0.x+=o0.x; v0.y+=o0.y; v1.x+=o1.x; v1.y+=o1.y;
            } else if (EPI==3){
                float g0 = gate[col], g1 = gate[col+1];
                float2 o0 = *reinterpret_cast<float2*>(C+i0);
                float2 o1 = *reinterpret_cast<float2*>(C+i1);
                v0.x=o0.x+g0*v0.x; v0.y=o0.y+g1*v0.y;
                v1.x=o1.x+g0*v1.x; v1.y=o1.y+g1*v1.y;
            }
            if (SPLIT != 2){
                *reinterpret_cast<float2*>(C+i0) = v0;
                *reinterpret_cast<float2*>(C+i1) = v1;
            }
            if (SPLIT >= 1){ cvt2(v0, Hs, i0); cvt2(v1, Hs, i1); }
        }
    }
}

template<int EPI, int SPLIT>
__global__ __launch_bounds__(256,2) void mmagemm(const __half* __restrict__ Ah,
        const __half* __restrict__ Bh, float* __restrict__ C, __half* __restrict__ Hs,
        const float* __restrict__ gate, int M, int N, int K)
{
    extern __shared__ char smc[];
    gemm_body<EPI,SPLIT>(Ah, Bh, C, Hs, gate, N, K, blockIdx.y<<7, blockIdx.x<<7, smc);
}

__global__ __launch_bounds__(256,2) void mmagemm_pair(
        const __half* __restrict__ A0, const __half* __restrict__ B0, __half* __restrict__ H0,
        int N0, int ntx0, int T0,
        const __half* __restrict__ A1, const __half* __restrict__ B1, __half* __restrict__ H1,
        int N1, int ntx1)
{
    extern __shared__ char smc[];
    int t = blockIdx.x;
    if (t < T0)
        gemm_body<0,2>(A0, B0, nullptr, H0, nullptr, N0, 768, (t/ntx0)<<7, (t%ntx0)<<7, smc);
    else {
        t -= T0;
        gemm_body<0,2>(A1, B1, nullptr, H1, nullptr, N1, 768, (t/ntx1)<<7, (t%ntx1)<<7, smc);
    }
}

// ---- LayerNorm ----
__global__ __launch_bounds__(256) void layernorm_k(const float* __restrict__ X,
        __half* __restrict__ H, const float* __restrict__ g, const float* __restrict__ bb)
{
    __shared__ float red[8], red2[8];
    const int row = blockIdx.x, tid = threadIdx.x, lane = tid&31, wid = tid>>5;
    const float* x = X + (size_t)row*D_;
    float v0=x[tid], v1=x[tid+256], v2=x[tid+512];
    float s = v0+v1+v2;
    #pragma unroll
    for (int o=16;o;o>>=1) s += __shfl_xor_sync(0xffffffffu, s, o);
    if (lane==0) red[wid]=s;
    __syncthreads();
    float mean = (red[0]+red[1]+red[2]+red[3]+red[4]+red[5]+red[6]+red[7])*(1.f/768.f);
    float d0=v0-mean, d1=v1-mean, d2=v2-mean;
    float q = d0*d0+d1*d1+d2*d2;
    #pragma unroll
    for (int o=16;o;o>>=1) q += __shfl_xor_sync(0xffffffffu, q, o);
    if (lane==0) red2[wid]=q;
    __syncthreads();
    float inv = rsqrtf((red2[0]+red2[1]+red2[2]+red2[3]+red2[4]+red2[5]+red2[6]+red2[7])*(1.f/768.f)+1e-6f);
    size_t base = (size_t)row*D_;
    H[base+tid]     = __float2half_rn(d0*inv*g[tid]     + bb[tid]);
    H[base+tid+256] = __float2half_rn(d1*inv*g[tid+256] + bb[tid+256]);
    H[base+tid+512] = __float2half_rn(d2*inv*g[tid+512] + bb[tid+512]);
}

// ---- RoPE tables (merged local+scene) ----
__global__ void rope_pre(const float* __restrict__ centers, const float* __restrict__ scales){
    int t = blockIdx.x, b = blockIdx.y, j = threadIdx.x;
    float f = expf(-4.605170185988091f*(float)(j&15)*(1.f/16.f));
    if (b < B_){
        float gy=(t/7+0.5f)*(2.f/7.f)-1.f, gx=(t%7+0.5f)*(2.f/7.f)-1.f;
        float sc=scales[b];
        float pos=(j<16)?(centers[2*b]+sc*gy):(centers[2*b+1]+sc*gx);
        if (t < NTL_){
            float a=pos*f;
            int idx=(b*NTL_+t)*32+j;
            g_lsin[idx]=sinf(a); g_lcos[idx]=cosf(a);
        }
    } else {
        // scene rows: t in [0,256)
        float gy=(t/16+0.5f)*(2.f/16.f)-1.f, gx=(t%16+0.5f)*(2.f/16.f)-1.f;
        float pos=(j<16)?gy:gx;
        float a=pos*f;
        g_ssin[t*32+j]=sinf(a); g_scos[t*32+j]=cosf(a);
    }
}

// ---- attention ----
#define AQ_OFF  0
#define AKV_OFF 8192
#define AS_OFF  16384
#define AP_OFF  81920
#define SMATT   114688
__global__ __launch_bounds__(256,2) void attn3(
    const __half* __restrict__ Q, const __half* __restrict__ K, const __half* __restrict__ V,
    __half* __restrict__ Oh, int Nq, int Nk, int qs, int ks,
    const float* __restrict__ qS, const float* __restrict__ qC, int qpre, int qbi,
    const float* __restrict__ kS, const float* __restrict__ kC, int kpre, int kbi)
{
    extern __shared__ char smc[];
    const uint32_t sb = smem_to_u32(smc);
    float* Sm = reinterpret_cast<float*>(smc + AS_OFF);
    const int q0 = blockIdx.x<<6, h = blockIdx.y, b = blockIdx.z;
    const int tid = threadIdx.x, wid = tid>>5, lane = tid&31;
    const int mw = wid>>1, nw = wid&1;

    {
        int r = tid>>2, pj = (tid&3)<<3;
        int t = q0 + r;
        uint4 lo = make_uint4(0,0,0,0), hi = make_uint4(0,0,0,0);
        if (t < Nq){
            const __half* qp = Q + (size_t)(b*Nq+t)*qs + h*64;
            lo = *reinterpret_cast<const uint4*>(qp + pj);
            hi = *reinterpret_cast<const uint4*>(qp + pj + 32);
            if (t >= qpre){
                int so = (qbi ? t*32 : (b*NTL_ + (t-qpre))*32) + pj;
                __half2* l2 = reinterpret_cast<__half2*>(&lo);
                __half2* h2 = reinterpret_cast<__half2*>(&hi);
                #pragma unroll
                for (int jj=0;jj<4;jj++){
                    float2 x1 = __half22float2(l2[jj]);
                    float2 x2 = __half22float2(h2[jj]);
                    float s0=qS[so+2*jj], c0=qC[so+2*jj];
                    float s1=qS[so+2*jj+1], c1=qC[so+2*jj+1];
                    l2[jj] = __floats2half2_rn(x1.x*c0-x2.x*s0, x1.y*c1-x2.y*s1);
                    h2[jj] = __floats2half2_rn(x2.x*c0+x1.x*s0, x2.y*c1+x1.y*s1);
                }
            }
        }
        *reinterpret_cast<uint4*>(smc + AQ_OFF + SWZ(r*128 + pj*2)) = lo;
        *reinterpret_cast<uint4*>(smc + AQ_OFF + SWZ(r*128 + pj*2 + 64)) = hi;
    }

    const int NC = (Nk + 63) >> 6;
    for (int c=0;c<NC;c++){
        int c0 = c<<6;
        __syncthreads();
        {
            int r = tid>>2, pj = (tid&3)<<3;
            int t = c0 + r;
            uint4 lo = make_uint4(0,0,0,0), hi = make_uint4(0,0,0,0);
            if (t < Nk){
                const __half* kp = K + (size_t)(b*Nk+t)*ks + h*64;
                lo = *reinterpret_cast<const uint4*>(kp + pj);
                hi = *reinterpret_cast<const uint4*>(kp + pj + 32);
                if (t >= kpre){
                    int so = (kbi ? t*32 : (b*NTL_ + (t-kpre))*32) + pj;
                    __half2* l2 = reinterpret_cast<__half2*>(&lo);
                    __half2* h2 = reinterpret_cast<__half2*>(&hi);
                    #pragma unroll
                    for (int jj=0;jj<4;jj++){
                        float2 x1 = __half22float2(l2[jj]);
                        float2 x2 = __half22float2(h2[jj]);
                        float s0=kS[so+2*jj], c0f=kC[so+2*jj];
                        float s1=kS[so+2*jj+1], c1f=kC[so+2*jj+1];
                        l2[jj] = __floats2half2_rn(x1.x*c0f-x2.x*s0, x1.y*c1f-x2.y*s1);
                        h2[jj] = __floats2half2_rn(x2.x*c0f+x1.x*s0, x2.y*c1f+x1.y*s1);
                    }
                }
            }
            *reinterpret_cast<uint4*>(smc + AKV_OFF + SWZ(r*128 + pj*2)) = lo;
            *reinterpret_cast<uint4*>(smc + AKV_OFF + SWZ(r*128 + pj*2 + 64)) = hi;
        }
        __syncthreads();
        float acc[4][4] = {};
        #pragma unroll
        for (int ks_=0;ks_<4;ks_++){
            uint32_t af[4];
            ldsm4(af, sb + AQ_OFF + SWZ(((mw<<4)+(lane&15))*128 + ((ks_<<4)+((lane>>4)<<3))*2));
            #pragma unroll
            for (int np=0;np<2;np++){
                uint32_t bf[4];
                int krow = (nw<<5)+(np<<4)+(lane&7)+((lane>>4)<<3);
                ldsm4(bf, sb + AKV_OFF + SWZ(krow*128 + ((ks_<<4)+(((lane>>3)&1)<<3))*2));
                mma16816(acc[2*np],   af, bf);
                mma16816(acc[2*np+1], af, bf+2);
            }
        }
        int g = lane>>2, tq = lane&3;
        #pragma unroll
        for (int j=0;j<4;j++){
            int col = c0 + (nw<<5) + ((j>>1)<<4) + ((j&1)<<3) + (tq<<1);
            int r0 = (mw<<4)+g;
            float* s0 = Sm + r0*256 + col;
            s0[0]=acc[j][0]*0.125f; s0[1]=acc[j][1]*0.125f;
            float* s1 = s0 + 8*256;
            s1[0]=acc[j][2]*0.125f; s1[1]=acc[j][3]*0.125f;
        }
    }
    __syncthreads();

    {
        int Nkp = NC<<6;
        for (int rr=0;rr<8;rr++){
            int row = (wid<<3)+rr;
            float* Srow = Sm + row*256;
            float m = -1e30f;
            for (int i=lane;i<Nk;i+=32) m = fmaxf(m, Srow[i]);
            #pragma unroll
            for (int o=16;o>0;o>>=1) m = fmaxf(m, __shfl_xor_sync(0xffffffffu, m, o));
            float sum = 0.f;
            for (int i=lane;i<Nk;i+=32){ float e = expf(Srow[i]-m); Srow[i]=e; sum+=e; }
            #pragma unroll
            for (int o=16;o>0;o>>=1) sum += __shfl_xor_sync(0xffffffffu, sum, o);
            float inv = 1.f/sum;
            for (int i=lane;i<Nkp;i+=32){
                __half p = (i<Nk) ? __float2half_rn(Srow[i]*inv) : __float2half_rn(0.f);
                *reinterpret_cast<__half*>(smc + AP_OFF + row*512 +
                    ((((i>>3)^(row&7)))<<4) + ((i&7)<<1)) = p;
            }
        }
    }

    float oacc[4][4] = {};
    for (int c=0;c<NC;c++){
        int c0 = c<<6;
        __syncthreads();
        {
            int r = tid>>2, pj = (tid&3)<<3;
            int t = c0 + r;
            uint4 lo = make_uint4(0,0,0,0), hi = make_uint4(0,0,0,0);
            if (t < Nk){
                const __half* vp = V + (size_t)(b*Nk+t)*ks + h*64;
                lo = *reinterpret_cast<const uint4*>(vp + pj);
                hi = *reinterpret_cast<const uint4*>(vp + pj + 32);
            }
            *reinterpret_cast<uint4*>(smc + AKV_OFF + SWZ(r*128 + pj*2)) = lo;
            *reinterpret_cast<uint4*>(smc + AKV_OFF + SWZ(r*128 + pj*2 + 64)) = hi;
        }
        __syncthreads();
        #pragma unroll
        for (int ks_=0;ks_<4;ks_++){
            uint32_t af[4];
            int prow = (mw<<4)+(lane&15);
            int pcol = c0 + (ks_<<4) + ((lane>>4)<<3);
            ldsm4(af, sb + AP_OFF + prow*512 + (((pcol>>3)^(prow&7))<<4));
            #pragma unroll
            for (int np=0;np<2;np++){
                uint32_t bf[4];
                int vrow = (ks_<<4) + (((lane>>3)&1)<<3) + (lane&7);
                int vcol = (nw<<5) + (np<<4) + ((lane>>4)<<3);
                ldsm4t(bf, sb + AKV_OFF + SWZ(vrow*128 + vcol*2));
                mma16816(oacc[2*np],   af, bf);
                mma16816(oacc[2*np+1], af, bf+2);
            }
        }
    }
    {
        int g = lane>>2, tq = lane&3;
        #pragma unroll
        for (int j=0;j<4;j++){
            int col = (nw<<5)+((j>>1)<<4)+((j&1)<<3)+(tq<<1);
            int r0 = (mw<<4)+g;
            if (q0+r0 < Nq){
                size_t i0 = (size_t)(b*Nq + q0 + r0)*D_ + h*64 + col;
                *reinterpret_cast<__half2*>(Oh+i0) = __floats2half2_rn(oacc[j][0], oacc[j][1]);
            }
            if (q0+r0+8 < Nq){
                size_t i1 = (size_t)(b*Nq + q0 + r0 + 8)*D_ + h*64 + col;
                *reinterpret_cast<__half2*>(Oh+i1) = __floats2half2_rn(oacc[j][2], oacc[j][3]);
            }
        }
    }
}

// ---- scene broadcast ----
__global__ void bcast_scene(const float* __restrict__ st){
    int off = blockIdx.x*256 + threadIdx.x;
    float v = st[off];
    size_t i = (size_t)blockIdx.y*(NS_*D_) + off;
    g_scene[i] = v;
    g_sh[i] = __float2half_rn(v);
}

extern "C" void kernel_launch(void* const* d_in, const int* in_sizes, int n_in,
                              void* d_out, int out_size)
{
    (void)in_sizes; (void)n_in; (void)out_size;
    const float *in_local=(const float*)d_in[0], *in_centers=(const float*)d_in[1],
        *in_scales=(const float*)d_in[2], *in_scene=(const float*)d_in[3],
        *rgate=(const float*)d_in[4], *wgate=(const float*)d_in[5],
        *rWq=(const float*)d_in[6], *rWk=(const float*)d_in[7], *rWv=(const float*)d_in[8],
        *rWo=(const float*)d_in[9], *wWq=(const float*)d_in[10], *wWk=(const float*)d_in[11],
        *wWv=(const float*)d_in[12], *wWo=(const float*)d_in[13],
        *ln1g=(const float*)d_in[14], *ln1b=(const float*)d_in[15],
        *qkvW=(const float*)d_in[16], *aWo=(const float*)d_in[17],
        *ln2g=(const float*)d_in[18], *ln2b=(const float*)d_in[19],
        *mW1=(const float*)d_in[20], *mW2=(const float*)d_in[21];

    float *local,*scene,*lsin,*lcos,*ssin,*scos;
    __half *wt,*lh,*sh,*aoh,*hbh,*mh,*qh,*kvh,*qkvh;
    cudaGetSymbolAddress((void**)&local,g_local); cudaGetSymbolAddress((void**)&scene,g_scene);
    cudaGetSymbolAddress((void**)&lsin,g_lsin); cudaGetSymbolAddress((void**)&lcos,g_lcos);
    cudaGetSymbolAddress((void**)&ssin,g_ssin); cudaGetSymbolAddress((void**)&scos,g_scos);
    cudaGetSymbolAddress((void**)&wt,g_wt);
    cudaGetSymbolAddress((void**)&lh,g_lh);   cudaGetSymbolAddress((void**)&sh,g_sh);
    cudaGetSymbolAddress((void**)&aoh,g_aoh); cudaGetSymbolAddress((void**)&hbh,g_hbh);
    cudaGetSymbolAddress((void**)&mh,g_mh);
    cudaGetSymbolAddress((void**)&qh,g_qh);   cudaGetSymbolAddress((void**)&kvh,g_kvh);
    cudaGetSymbolAddress((void**)&qkvh,g_qkvh);

    cudaFuncSetAttribute(mmagemm<0,2>, cudaFuncAttributeMaxDynamicSharedMemorySize, SMEMG);
    cudaFuncSetAttribute(mmagemm<1,2>, cudaFuncAttributeMaxDynamicSharedMemorySize, SMEMG);
    cudaFuncSetAttribute(mmagemm<2,0>, cudaFuncAttributeMaxDynamicSharedMemorySize, SMEMG);
    cudaFuncSetAttribute(mmagemm<2,1>, cudaFuncAttributeMaxDynamicSharedMemorySize, SMEMG);
    cudaFuncSetAttribute(mmagemm<3,0>, cudaFuncAttributeMaxDynamicSharedMemorySize, SMEMG);
    cudaFuncSetAttribute(mmagemm<3,1>, cudaFuncAttributeMaxDynamicSharedMemorySize, SMEMG);
    cudaFuncSetAttribute(mmagemm_pair, cudaFuncAttributeMaxDynamicSharedMemorySize, SMEMG);
    cudaFuncSetAttribute(attn3, cudaFuncAttributeMaxDynamicSharedMemorySize, SMATT);

    const size_t LS = 20*DD_;
    // Our launch #4 = first mmagemm_pair (harness injects 2 pre-launches; ncu -s5 -c1 => our #4)
    wsplit_all<<<dim3(11520,12), dim3(32,8)>>>(rWq,rWk,rWv,rWo,wWq,wWk,wWv,wWo,
                                               qkvW,aWo,mW1,mW2, wt);          // our 1
    aconv<<<ML_*D_/1024,256>>>(in_local, lh);                                  // our 2
    bcast_scene<<<dim3(NS_*D_/256, B_),256>>>(in_scene);                       // our 3

    for (int i=0;i<12;i++){
        const __half* wb = wt + (size_t)i*LS;
        // ---- READ cross-attn: q(local) || kv(scene) grouped ----
        mmagemm_pair<<<324+3072, 256, SMEMG>>>(lh, wb+0*DD_, qh, 768, 6, 324,
                                               sh, wb+1*DD_, kvh, 1536, 12);   // our 4 on i==0
        if (i==0){
            rope_pre<<<dim3(NS_,B_+1),32>>>(in_centers, in_scales);
            copyf<<<ML_*D_/1024,256>>>(in_local, local);
        }
        attn3<<<dim3(1,NH_,B_),256,SMATT>>>(qh, kvh, kvh+768, aoh, NL_, NS_, 768, 1536,
                                            lsin,lcos,P_,0, ssin,scos,0,1);
        mmagemm<3,0><<<dim3(6,54),   256, SMEMG>>>(aoh, wb+3*DD_, local, nullptr, rgate+(size_t)i*D_, ML_, 768, 768);
        // ---- ViT block ----
        layernorm_k<<<ML_,256>>>(local, hbh, ln1g+(size_t)i*D_, ln1b+(size_t)i*D_);
        mmagemm<0,2><<<dim3(18,54),  256, SMEMG>>>(hbh, wb+8*DD_, nullptr, qkvh, nullptr, ML_, 2304, 768);
        attn3<<<dim3(1,NH_,B_),256,SMATT>>>(qkvh, qkvh+768, qkvh+1536, aoh, NL_, NL_, 2304, 2304,
                                            lsin,lcos,P_,0, lsin,lcos,P_,0);
        mmagemm<2,0><<<dim3(6,54),   256, SMEMG>>>(aoh, wb+11*DD_, local, nullptr, nullptr, ML_, 768, 768);
        layernorm_k<<<ML_,256>>>(local, hbh, ln2g+(size_t)i*D_, ln2b+(size_t)i*D_);
        mmagemm<1,2><<<dim3(24,54),  256, SMEMG>>>(hbh, wb+12*DD_, nullptr, mh, nullptr, ML_, 3072, 768);
        mmagemm<2,1><<<dim3(6,54),   256, SMEMG>>>(mh, wb+16*DD_, local, lh, nullptr, ML_, 768, 3072);
        // ---- WRITE cross-attn: q(scene) || kv(local) grouped ----
        mmagemm_pair<<<1536+648, 256, SMEMG>>>(sh, wb+4*DD_, qh, 768, 6, 1536,
                                               lh, wb+5*DD_, kvh, 1536, 12);
        attn3<<<dim3(4,NH_,B_),256,SMATT>>>(qh, kvh, kvh+768, aoh, NS_, NL_, 768, 1536,
                                            ssin,scos,0,1, lsin,lcos,P_,0);
        mmagemm<3,1><<<dim3(6,256),  256, SMEMG>>>(aoh, wb+7*DD_, scene, sh, wgate+(size_t)i*D_, MS_, 768, 768);
    }

    cudaMemcpyAsync(d_out, local, sizeof(float)*(size_t)ML_*D_, cudaMemcpyDeviceToDevice);
    cudaMemcpyAsync((float*)d_out + (size_t)ML_*D_, scene, sizeof(float)*(size_t)MS_*D_,
                    cudaMemcpyDeviceToDevice);
}

// round 13
// speedup vs baseline: 7.4917x; 1.0036x over previous
#include <cuda_runtime.h>
#include <cuda_fp16.h>
#include <cstdint>

#define D_   768
#define NH_  12
#define P_   5
#define NL_  54
#define NS_  256
#define B_   128
#define NTL_ 49
#define ML_  (B_*NL_)
#define MS_  (B_*NS_)
#define DD_  ((size_t)768*768)

__device__ float g_local[(size_t)ML_*D_];
__device__ float g_scene[(size_t)MS_*D_];
__device__ float g_lsin [B_*NTL_*32];
__device__ float g_lcos [B_*NTL_*32];
__device__ float g_ssin [NS_*32];
__device__ float g_scos [NS_*32];
__device__ __half g_wt[(size_t)12*20*DD_];
__device__ __half g_lh  [(size_t)ML_*D_];
__device__ __half g_sh  [(size_t)MS_*D_];
__device__ __half g_aoh [(size_t)MS_*D_];
__device__ __half g_hbh [(size_t)ML_*D_];
__device__ __half g_mh  [(size_t)ML_*4*D_];
__device__ __half g_qh  [(size_t)MS_*D_];
__device__ __half g_kvh [(size_t)MS_*2*D_];
__device__ __half g_qkvh[(size_t)ML_*3*D_];

__device__ __forceinline__ uint32_t smem_to_u32(const void* p){
    uint32_t a;
    asm("{ .reg .u64 t; cvta.to.shared.u64 t, %1; cvt.u32.u64 %0, t; }" : "=r"(a) : "l"(p));
    return a;
}
#define SWZ(o) ((o) ^ (((o)>>3)&0x70))
#define CPA16(dst,src) asm volatile("cp.async.cg.shared.global [%0],[%1],16;"::"r"(dst),"l"(src))
#define CPA_COMMIT() asm volatile("cp.async.commit_group;")

__device__ __forceinline__ void ldsm4(uint32_t* r, uint32_t addr){
    asm volatile("ldmatrix.sync.aligned.m8n8.x4.shared.b16 {%0,%1,%2,%3},[%4];"
        : "=r"(r[0]),"=r"(r[1]),"=r"(r[2]),"=r"(r[3]) : "r"(addr));
}
__device__ __forceinline__ void ldsm4t(uint32_t* r, uint32_t addr){
    asm volatile("ldmatrix.sync.aligned.m8n8.x4.trans.shared.b16 {%0,%1,%2,%3},[%4];"
        : "=r"(r[0]),"=r"(r[1]),"=r"(r[2]),"=r"(r[3]) : "r"(addr));
}
__device__ __forceinline__ void mma16816(float* d, const uint32_t* a, const uint32_t* b){
    asm volatile("mma.sync.aligned.m16n8k16.row.col.f32.f16.f16.f32 "
        "{%0,%1,%2,%3},{%4,%5,%6,%7},{%8,%9},{%0,%1,%2,%3};"
        : "+f"(d[0]),"+f"(d[1]),"+f"(d[2]),"+f"(d[3])
        : "r"(a[0]),"r"(a[1]),"r"(a[2]),"r"(a[3]),"r"(b[0]),"r"(b[1]));
}
__device__ __forceinline__ float gelu_f(float x){
    float t = tanhf(0.7978845608028654f*(x + 0.044715f*x*x*x));
    return 0.5f*x*(1.0f+t);
}
__device__ __forceinline__ void cvt2(float2 v, __half* H, size_t idx){
    *reinterpret_cast<__half2*>(H+idx) =
        __halves2half2(__float2half_rn(v.x), __float2half_rn(v.y));
}

// ---- ALL weights: fp32 [K][N] -> fp16 [N][K] in one launch ----
__global__ void wsplit_all(const float* p0, const float* p1, const float* p2, const float* p3,
                           const float* p4, const float* p5, const float* p6, const float* p7,
                           const float* qkvW, const float* aWo, const float* mW1, const float* mW2,
                           __half* wt)
{
    const float* Wtab[8] = {p0,p1,p2,p3,p4,p5,p6,p7};
    int t = blockIdx.x, l = blockIdx.y;
    const float* W; size_t off; int K=768, N=768, nx=24;
    if (t < 4608){ int m=t/576; t-=m*576; W=Wtab[m]; off=(size_t)m*DD_; }
    else if (t < 6336){ t-=4608; W=qkvW; off=8*DD_;  N=2304; nx=72; }
    else if (t < 6912){ t-=6336; W=aWo;  off=11*DD_; }
    else if (t < 9216){ t-=6912; W=mW1;  off=12*DD_; N=3072; nx=96; }
    else              { t-=9216; W=mW2;  off=16*DD_; K=3072; }
    int n0=(t%nx)<<5, k0=(t/nx)<<5;
    const int tx = threadIdx.x, ty = threadIdx.y;
    __shared__ float tt[32][33];
    const float* Wl = W + (size_t)l*K*N;
    #pragma unroll
    for (int j=0;j<4;j++) tt[ty+8*j][tx] = Wl[(size_t)(k0+ty+8*j)*N + n0+tx];
    __syncthreads();
    __half* hi = wt + (size_t)l*(20*DD_) + off;
    #pragma unroll
    for (int j=0;j<4;j++)
        hi[(size_t)(n0+ty+8*j)*K + k0+tx] = __float2half_rn(tt[tx][ty+8*j]);
}

// ---- fp32 -> fp16 convert ----
__global__ __launch_bounds__(256) void aconv(const float* __restrict__ X, __half* __restrict__ H)
{
    int i = blockIdx.x*256 + threadIdx.x;
    float4 a = reinterpret_cast<const float4*>(X)[i];
    cvt2(make_float2(a.x,a.y), H, (size_t)i*4);
    cvt2(make_float2(a.z,a.w), H, (size_t)i*4+2);
}
__global__ __launch_bounds__(256) void copyf(const float* __restrict__ X, float* __restrict__ Y)
{
    int i = blockIdx.x*256 + threadIdx.x;
    reinterpret_cast<float4*>(Y)[i] = reinterpret_cast<const float4*>(X)[i];
}

// ---- GEMM body: fragment-double-buffered mainloop ----
#define STAGE_ 32768
#define SMEMG (3*STAGE_)
template<int EPI, int SPLIT>
__device__ __forceinline__ void gemm_body(const __half* __restrict__ Ah,
        const __half* __restrict__ Bh, float* __restrict__ C, __half* __restrict__ Hs,
        const float* __restrict__ gate, int N, int K, int m0, int n0, char* smc)
{
    const uint32_t sb = smem_to_u32(smc);
    const int tid = threadIdx.x, wid = tid>>5, lane = tid&31;
    const int mw = wid>>1, nw = wid&1;

    float acc[2][8][4];
    #pragma unroll
    for (int i=0;i<2;i++)
        #pragma unroll
        for (int j=0;j<8;j++)
            #pragma unroll
            for (int q=0;q<4;q++) acc[i][j][q]=0.f;

    // fragment address helpers (per-warp, fixed lane mapping)
    const int arow0 = (mw<<5) + (lane&15);
    const int akb0  = (lane>>4)<<3;
    const int brow0 = (nw<<6) + (lane&7) + ((lane>>4)<<3);
    const int bkb0  = ((lane>>3)&1)<<3;

    const int NC = K>>6;
    auto issue = [&](int c){
        const int s = c%3, kc = c<<6;
        const uint32_t sbase = sb + s*STAGE_;
        #pragma unroll
        for (int it=0; it<4; it++){
            int u = (it<<8) + tid;
            int r = u>>3, c16 = u&7;
            uint32_t dst = sbase + SWZ((uint32_t)(r*128 + c16*16));
            CPA16(dst,         Ah + (size_t)(m0+r)*K + kc + (c16<<3));
            CPA16(dst + 16384, Bh + (size_t)(n0+r)*K + kc + (c16<<3));
        }
        CPA_COMMIT();
    };
    issue(0);
    if (NC>1) issue(1);
    for (int c=0; c<NC; c++){
        if (c+1 < NC) asm volatile("cp.async.wait_group 1;");
        else          asm volatile("cp.async.wait_group 0;");
        __syncthreads();
        if (c+2 < NC) issue(c+2);
        const uint32_t sbase = sb + (c%3)*STAGE_;

        uint32_t ah[2][2][4];   // [parity][ma][frag]
        uint32_t bh[2][4];      // [parity][frag]
        // preload ks=0 A (both ma) and (ks=0,np=0) B
        #pragma unroll
        for (int ma=0; ma<2; ma++)
            ldsm4(ah[0][ma], sbase + SWZ((uint32_t)((arow0+(ma<<4))*128 + akb0*2)));
        ldsm4(bh[0], sbase + 16384 + SWZ((uint32_t)(brow0*128 + bkb0*2)));

        #pragma unroll
        for (int ks=0; ks<4; ks++){
            const int ap = ks&1;
            #pragma unroll
            for (int np=0; np<4; np++){
                const int bp = (ks*4+np)&1;
                // prefetch next fragments
                if (np < 3){
                    ldsm4(bh[bp^1], sbase + 16384 +
                        SWZ((uint32_t)((brow0+((np+1)<<4))*128 + ((ks<<4)+bkb0)*2)));
                } else if (ks < 3){
                    #pragma unroll
                    for (int ma=0; ma<2; ma++)
                        ldsm4(ah[ap^1][ma], sbase +
                            SWZ((uint32_t)((arow0+(ma<<4))*128 + (((ks+1)<<4)+akb0)*2)));
                    ldsm4(bh[bp^1], sbase + 16384 +
                        SWZ((uint32_t)(brow0*128 + (((ks+1)<<4)+bkb0)*2)));
                }
                #pragma unroll
                for (int ma=0; ma<2; ma++) mma16816(acc[ma][2*np],   ah[ap][ma], bh[bp]);
                #pragma unroll
                for (int ma=0; ma<2; ma++) mma16816(acc[ma][2*np+1], ah[ap][ma], bh[bp]+2);
            }
        }
    }
    const int g = lane>>2, t = lane&3;
    #pragma unroll
    for (int ma=0; ma<2; ma++){
        int r0 = m0 + (mw<<5) + (ma<<4) + g;
        #pragma unroll
        for (int na=0; na<8; na++){
            int col = n0 + (nw<<6) + (na<<3) + (t<<1);
            size_t i0 = (size_t)r0*N + col;
            size_t i1 = i0 + 8*(size_t)N;
            float2 v0 = make_float2(acc[ma][na][0], acc[ma][na][1]);
            float2 v1 = make_float2(acc[ma][na][2], acc[ma][na][3]);
            if (EPI==1){
                v0.x=gelu_f(v0.x); v0.y=gelu_f(v0.y); v1.x=gelu_f(v1.x); v1.y=gelu_f(v1.y);
            } else if (EPI==2){
                float2 o0 = *reinterpret_cast<float2*>(C+i0);
                float2 o1 = *reinterpret_cast<float2*>(C+i1);
                v0.x+=o0.x; v0.y+=o0.y; v1.x+=o1.x; v1.y+=o1.y;
            } else if (EPI==3){
                float g0 = gate[col], g1 = gate[col+1];
                float2 o0 = *reinterpret_cast<float2*>(C+i0);
                float2 o1 = *reinterpret_cast<float2*>(C+i1);
                v0.x=o0.x+g0*v0.x; v0.y=o0.y+g1*v0.y;
                v1.x=o1.x+g0*v1.x; v1.y=o1.y+g1*v1.y;
            }
            if (SPLIT != 2){
                *reinterpret_cast<float2*>(C+i0) = v0;
                *reinterpret_cast<float2*>(C+i1) = v1;
            }
            if (SPLIT >= 1){ cvt2(v0, Hs, i0); cvt2(v1, Hs, i1); }
        }
    }
}

template<int EPI, int SPLIT>
__global__ __launch_bounds__(256,2) void mmagemm(const __half* __restrict__ Ah,
        const __half* __restrict__ Bh, float* __restrict__ C, __half* __restrict__ Hs,
        const float* __restrict__ gate, int M, int N, int K)
{
    extern __shared__ char smc[];
    gemm_body<EPI,SPLIT>(Ah, Bh, C, Hs, gate, N, K, blockIdx.y<<7, blockIdx.x<<7, smc);
}

__global__ __launch_bounds__(256,2) void mmagemm_pair(
        const __half* __restrict__ A0, const __half* __restrict__ B0, __half* __restrict__ H0,
        int N0, int ntx0, int T0,
        const __half* __restrict__ A1, const __half* __restrict__ B1, __half* __restrict__ H1,
        int N1, int ntx1)
{
    extern __shared__ char smc[];
    int t = blockIdx.x;
    if (t < T0)
        gemm_body<0,2>(A0, B0, nullptr, H0, nullptr, N0, 768, (t/ntx0)<<7, (t%ntx0)<<7, smc);
    else {
        t -= T0;
        gemm_body<0,2>(A1, B1, nullptr, H1, nullptr, N1, 768, (t/ntx1)<<7, (t%ntx1)<<7, smc);
    }
}

// ---- LayerNorm ----
__global__ __launch_bounds__(256) void layernorm_k(const float* __restrict__ X,
        __half* __restrict__ H, const float* __restrict__ g, const float* __restrict__ bb)
{
    __shared__ float red[8], red2[8];
    const int row = blockIdx.x, tid = threadIdx.x, lane = tid&31, wid = tid>>5;
    const float* x = X + (size_t)row*D_;
    float v0=x[tid], v1=x[tid+256], v2=x[tid+512];
    float s = v0+v1+v2;
    #pragma unroll
    for (int o=16;o;o>>=1) s += __shfl_xor_sync(0xffffffffu, s, o);
    if (lane==0) red[wid]=s;
    __syncthreads();
    float mean = (red[0]+red[1]+red[2]+red[3]+red[4]+red[5]+red[6]+red[7])*(1.f/768.f);
    float d0=v0-mean, d1=v1-mean, d2=v2-mean;
    float q = d0*d0+d1*d1+d2*d2;
    #pragma unroll
    for (int o=16;o;o>>=1) q += __shfl_xor_sync(0xffffffffu, q, o);
    if (lane==0) red2[wid]=q;
    __syncthreads();
    float inv = rsqrtf((red2[0]+red2[1]+red2[2]+red2[3]+red2[4]+red2[5]+red2[6]+red2[7])*(1.f/768.f)+1e-6f);
    size_t base = (size_t)row*D_;
    H[base+tid]     = __float2half_rn(d0*inv*g[tid]     + bb[tid]);
    H[base+tid+256] = __float2half_rn(d1*inv*g[tid+256] + bb[tid+256]);
    H[base+tid+512] = __float2half_rn(d2*inv*g[tid+512] + bb[tid+512]);
}

// ---- RoPE tables (merged local+scene) ----
__global__ void rope_pre(const float* __restrict__ centers, const float* __restrict__ scales){
    int t = blockIdx.x, b = blockIdx.y, j = threadIdx.x;
    float f = expf(-4.605170185988091f*(float)(j&15)*(1.f/16.f));
    if (b < B_){
        float gy=(t/7+0.5f)*(2.f/7.f)-1.f, gx=(t%7+0.5f)*(2.f/7.f)-1.f;
        float sc=scales[b];
        float pos=(j<16)?(centers[2*b]+sc*gy):(centers[2*b+1]+sc*gx);
        if (t < NTL_){
            float a=pos*f;
            int idx=(b*NTL_+t)*32+j;
            g_lsin[idx]=sinf(a); g_lcos[idx]=cosf(a);
        }
    } else {
        float gy=(t/16+0.5f)*(2.f/16.f)-1.f, gx=(t%16+0.5f)*(2.f/16.f)-1.f;
        float pos=(j<16)?gy:gx;
        float a=pos*f;
        g_ssin[t*32+j]=sinf(a); g_scos[t*32+j]=cosf(a);
    }
}

// ---- attention ----
#define AQ_OFF  0
#define AKV_OFF 8192
#define AS_OFF  16384
#define AP_OFF  81920
#define SMATT   114688
__global__ __launch_bounds__(256,2) void attn3(
    const __half* __restrict__ Q, const __half* __restrict__ K, const __half* __restrict__ V,
    __half* __restrict__ Oh, int Nq, int Nk, int qs, int ks,
    const float* __restrict__ qS, const float* __restrict__ qC, int qpre, int qbi,
    const float* __restrict__ kS, const float* __restrict__ kC, int kpre, int kbi)
{
    extern __shared__ char smc[];
    const uint32_t sb = smem_to_u32(smc);
    float* Sm = reinterpret_cast<float*>(smc + AS_OFF);
    const int q0 = blockIdx.x<<6, h = blockIdx.y, b = blockIdx.z;
    const int tid = threadIdx.x, wid = tid>>5, lane = tid&31;
    const int mw = wid>>1, nw = wid&1;

    {
        int r = tid>>2, pj = (tid&3)<<3;
        int t = q0 + r;
        uint4 lo = make_uint4(0,0,0,0), hi = make_uint4(0,0,0,0);
        if (t < Nq){
            const __half* qp = Q + (size_t)(b*Nq+t)*qs + h*64;
            lo = *reinterpret_cast<const uint4*>(qp + pj);
            hi = *reinterpret_cast<const uint4*>(qp + pj + 32);
            if (t >= qpre){
                int so = (qbi ? t*32 : (b*NTL_ + (t-qpre))*32) + pj;
                __half2* l2 = reinterpret_cast<__half2*>(&lo);
                __half2* h2 = reinterpret_cast<__half2*>(&hi);
                #pragma unroll
                for (int jj=0;jj<4;jj++){
                    float2 x1 = __half22float2(l2[jj]);
                    float2 x2 = __half22float2(h2[jj]);
                    float s0=qS[so+2*jj], c0=qC[so+2*jj];
                    float s1=qS[so+2*jj+1], c1=qC[so+2*jj+1];
                    l2[jj] = __floats2half2_rn(x1.x*c0-x2.x*s0, x1.y*c1-x2.y*s1);
                    h2[jj] = __floats2half2_rn(x2.x*c0+x1.x*s0, x2.y*c1+x1.y*s1);
                }
            }
        }
        *reinterpret_cast<uint4*>(smc + AQ_OFF + SWZ(r*128 + pj*2)) = lo;
        *reinterpret_cast<uint4*>(smc + AQ_OFF + SWZ(r*128 + pj*2 + 64)) = hi;
    }

    const int NC = (Nk + 63) >> 6;
    for (int c=0;c<NC;c++){
        int c0 = c<<6;
        __syncthreads();
        {
            int r = tid>>2, pj = (tid&3)<<3;
            int t = c0 + r;
            uint4 lo = make_uint4(0,0,0,0), hi = make_uint4(0,0,0,0);
            if (t < Nk){
                const __half* kp = K + (size_t)(b*Nk+t)*ks + h*64;
                lo = *reinterpret_cast<const uint4*>(kp + pj);
                hi = *reinterpret_cast<const uint4*>(kp + pj + 32);
                if (t >= kpre){
                    int so = (kbi ? t*32 : (b*NTL_ + (t-kpre))*32) + pj;
                    __half2* l2 = reinterpret_cast<__half2*>(&lo);
                    __half2* h2 = reinterpret_cast<__half2*>(&hi);
                    #pragma unroll
                    for (int jj=0;jj<4;jj++){
                        float2 x1 = __half22float2(l2[jj]);
                        float2 x2 = __half22float2(h2[jj]);
                        float s0=kS[so+2*jj], c0f=kC[so+2*jj];
                        float s1=kS[so+2*jj+1], c1f=kC[so+2*jj+1];
                        l2[jj] = __floats2half2_rn(x1.x*c0f-x2.x*s0, x1.y*c1f-x2.y*s1);
                        h2[jj] = __floats2half2_rn(x2.x*c0f+x1.x*s0, x2.y*c1f+x1.y*s1);
                    }
                }
            }
            *reinterpret_cast<uint4*>(smc + AKV_OFF + SWZ(r*128 + pj*2)) = lo;
            *reinterpret_cast<uint4*>(smc + AKV_OFF + SWZ(r*128 + pj*2 + 64)) = hi;
        }
        __syncthreads();
        float acc[4][4] = {};
        #pragma unroll
        for (int ks_=0;ks_<4;ks_++){
            uint32_t af[4];
            ldsm4(af, sb + AQ_OFF + SWZ(((mw<<4)+(lane&15))*128 + ((ks_<<4)+((lane>>4)<<3))*2));
            #pragma unroll
            for (int np=0;np<2;np++){
                uint32_t bf[4];
                int krow = (nw<<5)+(np<<4)+(lane&7)+((lane>>4)<<3);
                ldsm4(bf, sb + AKV_OFF + SWZ(krow*128 + ((ks_<<4)+(((lane>>3)&1)<<3))*2));
                mma16816(acc[2*np],   af, bf);
                mma16816(acc[2*np+1], af, bf+2);
            }
        }
        int g = lane>>2, tq = lane&3;
        #pragma unroll
        for (int j=0;j<4;j++){
            int col = c0 + (nw<<5) + ((j>>1)<<4) + ((j&1)<<3) + (tq<<1);
            int r0 = (mw<<4)+g;
            float* s0 = Sm + r0*256 + col;
            s0[0]=acc[j][0]*0.125f; s0[1]=acc[j][1]*0.125f;
            float* s1 = s0 + 8*256;
            s1[0]=acc[j][2]*0.125f; s1[1]=acc[j][3]*0.125f;
        }
    }
    __syncthreads();

    {
        int Nkp = NC<<6;
        for (int rr=0;rr<8;rr++){
            int row = (wid<<3)+rr;
            float* Srow = Sm + row*256;
            float m = -1e30f;
            for (int i=lane;i<Nk;i+=32) m = fmaxf(m, Srow[i]);
            #pragma unroll
            for (int o=16;o>0;o>>=1) m = fmaxf(m, __shfl_xor_sync(0xffffffffu, m, o));
            float sum = 0.f;
            for (int i=lane;i<Nk;i+=32){ float e = expf(Srow[i]-m); Srow[i]=e; sum+=e; }
            #pragma unroll
            for (int o=16;o>0;o>>=1) sum += __shfl_xor_sync(0xffffffffu, sum, o);
            float inv = 1.f/sum;
            for (int i=lane;i<Nkp;i+=32){
                __half p = (i<Nk) ? __float2half_rn(Srow[i]*inv) : __float2half_rn(0.f);
                *reinterpret_cast<__half*>(smc + AP_OFF + row*512 +
                    ((((i>>3)^(row&7)))<<4) + ((i&7)<<1)) = p;
            }
        }
    }

    float oacc[4][4] = {};
    for (int c=0;c<NC;c++){
        int c0 = c<<6;
        __syncthreads();
        {
            int r = tid>>2, pj = (tid&3)<<3;
            int t = c0 + r;
            uint4 lo = make_uint4(0,0,0,0), hi = make_uint4(0,0,0,0);
            if (t < Nk){
                const __half* vp = V + (size_t)(b*Nk+t)*ks + h*64;
                lo = *reinterpret_cast<const uint4*>(vp + pj);
                hi = *reinterpret_cast<const uint4*>(vp + pj + 32);
            }
            *reinterpret_cast<uint4*>(smc + AKV_OFF + SWZ(r*128 + pj*2)) = lo;
            *reinterpret_cast<uint4*>(smc + AKV_OFF + SWZ(r*128 + pj*2 + 64)) = hi;
        }
        __syncthreads();
        #pragma unroll
        for (int ks_=0;ks_<4;ks_++){
            uint32_t af[4];
            int prow = (mw<<4)+(lane&15);
            int pcol = c0 + (ks_<<4) + ((lane>>4)<<3);
            ldsm4(af, sb + AP_OFF + prow*512 + (((pcol>>3)^(prow&7))<<4));
            #pragma unroll
            for (int np=0;np<2;np++){
                uint32_t bf[4];
                int vrow = (ks_<<4) + (((lane>>3)&1)<<3) + (lane&7);
                int vcol = (nw<<5) + (np<<4) + ((lane>>4)<<3);
                ldsm4t(bf, sb + AKV_OFF + SWZ(vrow*128 + vcol*2));
                mma16816(oacc[2*np],   af, bf);
                mma16816(oacc[2*np+1], af, bf+2);
            }
        }
    }
    {
        int g = lane>>2, tq = lane&3;
        #pragma unroll
        for (int j=0;j<4;j++){
            int col = (nw<<5)+((j>>1)<<4)+((j&1)<<3)+(tq<<1);
            int r0 = (mw<<4)+g;
            if (q0+r0 < Nq){
                size_t i0 = (size_t)(b*Nq + q0 + r0)*D_ + h*64 + col;
                *reinterpret_cast<__half2*>(Oh+i0) = __floats2half2_rn(oacc[j][0], oacc[j][1]);
            }
            if (q0+r0+8 < Nq){
                size_t i1 = (size_t)(b*Nq + q0 + r0 + 8)*D_ + h*64 + col;
                *reinterpret_cast<__half2*>(Oh+i1) = __floats2half2_rn(oacc[j][2], oacc[j][3]);
            }
        }
    }
}

// ---- scene broadcast ----
__global__ void bcast_scene(const float* __restrict__ st){
    int off = blockIdx.x*256 + threadIdx.x;
    float v = st[off];
    size_t i = (size_t)blockIdx.y*(NS_*D_) + off;
    g_scene[i] = v;
    g_sh[i] = __float2half_rn(v);
}

extern "C" void kernel_launch(void* const* d_in, const int* in_sizes, int n_in,
                              void* d_out, int out_size)
{
    (void)in_sizes; (void)n_in; (void)out_size;
    const float *in_local=(const float*)d_in[0], *in_centers=(const float*)d_in[1],
        *in_scales=(const float*)d_in[2], *in_scene=(const float*)d_in[3],
        *rgate=(const float*)d_in[4], *wgate=(const float*)d_in[5],
        *rWq=(const float*)d_in[6], *rWk=(const float*)d_in[7], *rWv=(const float*)d_in[8],
        *rWo=(const float*)d_in[9], *wWq=(const float*)d_in[10], *wWk=(const float*)d_in[11],
        *wWv=(const float*)d_in[12], *wWo=(const float*)d_in[13],
        *ln1g=(const float*)d_in[14], *ln1b=(const float*)d_in[15],
        *qkvW=(const float*)d_in[16], *aWo=(const float*)d_in[17],
        *ln2g=(const float*)d_in[18], *ln2b=(const float*)d_in[19],
        *mW1=(const float*)d_in[20], *mW2=(const float*)d_in[21];

    float *local,*scene,*lsin,*lcos,*ssin,*scos;
    __half *wt,*lh,*sh,*aoh,*hbh,*mh,*qh,*kvh,*qkvh;
    cudaGetSymbolAddress((void**)&local,g_local); cudaGetSymbolAddress((void**)&scene,g_scene);
    cudaGetSymbolAddress((void**)&lsin,g_lsin); cudaGetSymbolAddress((void**)&lcos,g_lcos);
    cudaGetSymbolAddress((void**)&ssin,g_ssin); cudaGetSymbolAddress((void**)&scos,g_scos);
    cudaGetSymbolAddress((void**)&wt,g_wt);
    cudaGetSymbolAddress((void**)&lh,g_lh);   cudaGetSymbolAddress((void**)&sh,g_sh);
    cudaGetSymbolAddress((void**)&aoh,g_aoh); cudaGetSymbolAddress((void**)&hbh,g_hbh);
    cudaGetSymbolAddress((void**)&mh,g_mh);
    cudaGetSymbolAddress((void**)&qh,g_qh);   cudaGetSymbolAddress((void**)&kvh,g_kvh);
    cudaGetSymbolAddress((void**)&qkvh,g_qkvh);

    cudaFuncSetAttribute(mmagemm<0,2>, cudaFuncAttributeMaxDynamicSharedMemorySize, SMEMG);
    cudaFuncSetAttribute(mmagemm<1,2>, cudaFuncAttributeMaxDynamicSharedMemorySize, SMEMG);
    cudaFuncSetAttribute(mmagemm<2,0>, cudaFuncAttributeMaxDynamicSharedMemorySize, SMEMG);
    cudaFuncSetAttribute(mmagemm<2,1>, cudaFuncAttributeMaxDynamicSharedMemorySize, SMEMG);
    cudaFuncSetAttribute(mmagemm<3,0>, cudaFuncAttributeMaxDynamicSharedMemorySize, SMEMG);
    cudaFuncSetAttribute(mmagemm<3,1>, cudaFuncAttributeMaxDynamicSharedMemorySize, SMEMG);
    cudaFuncSetAttribute(mmagemm_pair, cudaFuncAttributeMaxDynamicSharedMemorySize, SMEMG);
    cudaFuncSetAttribute(attn3, cudaFuncAttributeMaxDynamicSharedMemorySize, SMATT);

    const size_t LS = 20*DD_;
    wsplit_all<<<dim3(11520,12), dim3(32,8)>>>(rWq,rWk,rWv,rWo,wWq,wWk,wWv,wWo,
                                               qkvW,aWo,mW1,mW2, wt);          // our 1
    aconv<<<ML_*D_/1024,256>>>(in_local, lh);                                  // our 2
    bcast_scene<<<dim3(NS_*D_/256, B_),256>>>(in_scene);                       // our 3

    for (int i=0;i<12;i++){
        const __half* wb = wt + (size_t)i*LS;
        // ---- READ cross-attn: q(local) || kv(scene) grouped ----
        mmagemm_pair<<<324+3072, 256, SMEMG>>>(lh, wb+0*DD_, qh, 768, 6, 324,
                                               sh, wb+1*DD_, kvh, 1536, 12);   // our 4 on i==0
        if (i==0){
            rope_pre<<<dim3(NS_,B_+1),32>>>(in_centers, in_scales);
            copyf<<<ML_*D_/1024,256>>>(in_local, local);
        }
        attn3<<<dim3(1,NH_,B_),256,SMATT>>>(qh, kvh, kvh+768, aoh, NL_, NS_, 768, 1536,
                                            lsin,lcos,P_,0, ssin,scos,0,1);
        mmagemm<3,0><<<dim3(6,54),   256, SMEMG>>>(aoh, wb+3*DD_, local, nullptr, rgate+(size_t)i*D_, ML_, 768, 768);
        // ---- ViT block ----
        layernorm_k<<<ML_,256>>>(local, hbh, ln1g+(size_t)i*D_, ln1b+(size_t)i*D_);
        mmagemm<0,2><<<dim3(18,54),  256, SMEMG>>>(hbh, wb+8*DD_, nullptr, qkvh, nullptr, ML_, 2304, 768);
        attn3<<<dim3(1,NH_,B_),256,SMATT>>>(qkvh, qkvh+768, qkvh+1536, aoh, NL_, NL_, 2304, 2304,
                                            lsin,lcos,P_,0, lsin,lcos,P_,0);
        mmagemm<2,0><<<dim3(6,54),   256, SMEMG>>>(aoh, wb+11*DD_, local, nullptr, nullptr, ML_, 768, 768);
        layernorm_k<<<ML_,256>>>(local, hbh, ln2g+(size_t)i*D_, ln2b+(size_t)i*D_);
        mmagemm<1,2><<<dim3(24,54),  256, SMEMG>>>(hbh, wb+12*DD_, nullptr, mh, nullptr, ML_, 3072, 768);
        mmagemm<2,1><<<dim3(6,54),   256, SMEMG>>>(mh, wb+16*DD_, local, lh, nullptr, ML_, 768, 3072);
        // ---- WRITE cross-attn: q(scene) || kv(local) grouped ----
        mmagemm_pair<<<1536+648, 256, SMEMG>>>(sh, wb+4*DD_, qh, 768, 6, 1536,
                                               lh, wb+5*DD_, kvh, 1536, 12);
        attn3<<<dim3(4,NH_,B_),256,SMATT>>>(qh, kvh, kvh+768, aoh, NS_, NL_, 768, 1536,
                                            ssin,scos,0,1, lsin,lcos,P_,0);
        mmagemm<3,1><<<dim3(6,256),  256, SMEMG>>>(aoh, wb+7*DD_, scene, sh, wgate+(size_t)i*D_, MS_, 768, 768);
    }

    cudaMemcpyAsync(d_out, local, sizeof(float)*(size_t)ML_*D_, cudaMemcpyDeviceToDevice);
    cudaMemcpyAsync((float*)d_out + (size_t)ML_*D_, scene, sizeof(float)*(size_t)MS_*D_,
                    cudaMemcpyDeviceToDevice);
}